// round 10
// baseline (speedup 1.0000x reference)
#include <cuda_runtime.h>
#include <cuda_bf16.h>
#include <cstdint>
#include <cstddef>

// Problem constants
#define BB   4
#define CC   256      // D_MODEL = D_INNER
#define SS   64
#define DD   16
#define HH   64
#define WW   64
#define NN   65536    // D*H*W
#define O3S  192      // 3*S
#define KSPLIT_H 64   // split-K factor for h-GEMM

static const size_t YSIZE = (size_t)BB * CC * NN;   // 67108864

// ---- static scratch (no runtime allocation allowed) ----
__device__ float g_bcdt[(size_t)BB * O3S * NN];   // GEMM1 output (pre-conv)
__device__ float g_ab[(size_t)BB * SS * NN];      // AB_unnorm = exp(conv dt)*conv B_
__device__ float g_c [(size_t)BB * SS * NN];      // conv C_ channels
__device__ float g_hpart[(size_t)KSPLIT_H * BB * CC * SS];
__device__ float g_psum[BB * SS * 2];             // per-h-half exp-sums
__device__ float g_h [BB * CC * SS];
__device__ float g_h3[BB * CC * SS];
__device__ float g_h4[BB * CC * SS];

// ============================================================================
// helpers
// ============================================================================
__device__ __forceinline__ uint32_t smem_u32(const void* p) {
    uint32_t a;
    asm("{ .reg .u64 t; cvta.to.shared.u64 t, %1; cvt.u32.u64 %0, t; }" : "=r"(a) : "l"(p));
    return a;
}
__device__ __forceinline__ void ldsm_x4(uint32_t* r, uint32_t addr) {
    asm volatile("ldmatrix.sync.aligned.m8n8.x4.shared.b16 {%0,%1,%2,%3}, [%4];"
        : "=r"(r[0]), "=r"(r[1]), "=r"(r[2]), "=r"(r[3]) : "r"(addr));
}
__device__ __forceinline__ void ldsm_x2(uint32_t* r, uint32_t addr) {
    asm volatile("ldmatrix.sync.aligned.m8n8.x2.shared.b16 {%0,%1}, [%2];"
        : "=r"(r[0]), "=r"(r[1]) : "r"(addr));
}
__device__ __forceinline__ void ldsm_x2_t(uint32_t* r, uint32_t addr) {
    asm volatile("ldmatrix.sync.aligned.m8n8.x2.trans.shared.b16 {%0,%1}, [%2];"
        : "=r"(r[0]), "=r"(r[1]) : "r"(addr));
}
__device__ __forceinline__ void mma_bf16(float* c, const uint32_t* a, const uint32_t* b) {
    asm volatile(
        "mma.sync.aligned.m16n8k16.row.col.f32.bf16.bf16.f32 "
        "{%0,%1,%2,%3}, {%4,%5,%6,%7}, {%8,%9}, {%0,%1,%2,%3};"
        : "+f"(c[0]), "+f"(c[1]), "+f"(c[2]), "+f"(c[3])
        : "r"(a[0]), "r"(a[1]), "r"(a[2]), "r"(a[3]), "r"(b[0]), "r"(b[1]));
}
__device__ __forceinline__ void split2(float v0, float v1, uint32_t& hi, uint32_t& lo) {
    __nv_bfloat16 h0 = __float2bfloat16(v0), h1 = __float2bfloat16(v1);
    float r0 = v0 - __bfloat162float(h0), r1 = v1 - __bfloat162float(h1);
    __nv_bfloat162 hh = __halves2bfloat162(h0, h1);
    __nv_bfloat162 ll = __floats2bfloat162_rn(r0, r1);
    hi = *(uint32_t*)&hh; lo = *(uint32_t*)&ll;
}
// FMA-pipe exp (poly 2^f on [-0.5,0.5], ~2e-9 rel err), clamped both sides
__device__ __forceinline__ float fexp(float x) {
    float t = fminf(fmaxf(x * 1.4426950408889634f, -125.0f), 125.0f);
    float n = rintf(t);
    float f = t - n;
    float p = 1.5403530393381609e-4f;
    p = fmaf(p, f, 1.3333558146428443e-3f);
    p = fmaf(p, f, 9.618129107628477e-3f);
    p = fmaf(p, f, 5.550410866482158e-2f);
    p = fmaf(p, f, 2.402265069591999e-1f);
    p = fmaf(p, f, 6.931471805599453e-1f);
    p = fmaf(p, f, 1.0f);
    return __int_as_float(((int)n + 127) << 23) * p;
}

#define A_STRIDE 40    // halves per 32-k row (32 + 8 pad)
#define B_STRIDE 136   // halves per 128-n row (128 + 8 pad)
#define HB_STRIDE 40

// ============================================================================
// Kernel 1 (HMMA): BCdt = W_bcdt(192x256) @ x(b,256,N) + b_bcdt
// BM=64, BN=128, BK=32. x tile register-prefetched. Per-batch launch.
// ============================================================================
__global__ void __launch_bounds__(256) gemm1_mma_kernel(
    const float* __restrict__ x, const float* __restrict__ W,
    const float* __restrict__ bias, int b)
{
    __shared__ __align__(16) uint16_t As_hi[64 * A_STRIDE];
    __shared__ __align__(16) uint16_t As_lo[64 * A_STRIDE];
    __shared__ __align__(16) uint16_t Bs_hi[32 * B_STRIDE];
    __shared__ __align__(16) uint16_t Bs_lo[32 * B_STRIDE];

    const int m0 = blockIdx.x * 64;     // fastest -> L2 sharing of x tile
    const int n0 = blockIdx.y * 128;
    const int tid  = threadIdx.x;
    const int wid  = tid >> 5;
    const int lane = tid & 31;
    const int wm = wid >> 2;
    const int wn = wid & 3;

    const float* xb = x + (size_t)b * CC * NN;
    const uint32_t as_hi = smem_u32(As_hi), as_lo = smem_u32(As_lo);
    const uint32_t bs_hi = smem_u32(Bs_hi), bs_lo = smem_u32(Bs_lo);

    const int krow0 = tid >> 5;
    const int nloc  = (tid & 31) << 2;

    float acc[2][4][4];
#pragma unroll
    for (int i = 0; i < 2; i++)
#pragma unroll
        for (int j = 0; j < 4; j++)
#pragma unroll
            for (int q = 0; q < 4; q++) acc[i][j][q] = 0.f;

    float4 rbx[4];
#pragma unroll
    for (int r = 0; r < 4; r++)
        rbx[r] = *(const float4*)(xb + (size_t)(krow0 + r * 8) * NN + n0 + nloc);

    for (int k0 = 0; k0 < 256; k0 += 32) {
#pragma unroll
        for (int r = 0; r < 2; r++) {
            int f = tid + r * 256;
            int m = f >> 3, k = (f & 7) << 2;
            float4 v = *(const float4*)(W + (size_t)(m0 + m) * 256 + k0 + k);
            uint32_t h01, l01, h23, l23;
            split2(v.x, v.y, h01, l01);
            split2(v.z, v.w, h23, l23);
            int off = m * A_STRIDE + k;
            *(uint2*)(As_hi + off) = make_uint2(h01, h23);
            *(uint2*)(As_lo + off) = make_uint2(l01, l23);
        }
#pragma unroll
        for (int r = 0; r < 4; r++) {
            float4 v = rbx[r];
            uint32_t h01, l01, h23, l23;
            split2(v.x, v.y, h01, l01);
            split2(v.z, v.w, h23, l23);
            int off = (krow0 + r * 8) * B_STRIDE + nloc;
            *(uint2*)(Bs_hi + off) = make_uint2(h01, h23);
            *(uint2*)(Bs_lo + off) = make_uint2(l01, l23);
        }
        __syncthreads();

        if (k0 + 32 < 256) {
#pragma unroll
            for (int r = 0; r < 4; r++)
                rbx[r] = *(const float4*)(xb + (size_t)(k0 + 32 + krow0 + r * 8) * NN + n0 + nloc);
        }

#pragma unroll
        for (int ks = 0; ks < 2; ks++) {
            uint32_t a_hi[2][4], a_lo[2][4];
            const int arow = lane & 15;
            const int acol = (lane >> 4) << 3;
#pragma unroll
            for (int mi = 0; mi < 2; mi++) {
                uint32_t off = (uint32_t)((wm * 32 + mi * 16 + arow) * A_STRIDE
                                          + ks * 16 + acol) * 2;
                ldsm_x4(a_hi[mi], as_hi + off);
                ldsm_x4(a_lo[mi], as_lo + off);
            }
            uint32_t b_hi[4][2], b_lo[4][2];
            const int brow = lane & 15;
#pragma unroll
            for (int ni = 0; ni < 4; ni++) {
                uint32_t off = (uint32_t)((ks * 16 + brow) * B_STRIDE
                                          + wn * 32 + ni * 8) * 2;
                ldsm_x2_t(b_hi[ni], bs_hi + off);
                ldsm_x2_t(b_lo[ni], bs_lo + off);
            }
#pragma unroll
            for (int mi = 0; mi < 2; mi++)
#pragma unroll
                for (int ni = 0; ni < 4; ni++) {
                    mma_bf16(acc[mi][ni], a_hi[mi], b_hi[ni]);
                    mma_bf16(acc[mi][ni], a_hi[mi], b_lo[ni]);
                    mma_bf16(acc[mi][ni], a_lo[mi], b_hi[ni]);
                }
        }
        __syncthreads();
    }

    const int qrow = lane >> 2;
    const int qcol = (lane & 3) << 1;
#pragma unroll
    for (int mi = 0; mi < 2; mi++) {
        int mA = m0 + wm * 32 + mi * 16 + qrow;
        float bA = bias[mA], bB = bias[mA + 8];
        float* rowA = g_bcdt + ((size_t)(b * O3S + mA)) * NN + n0;
        float* rowB = rowA + (size_t)8 * NN;
#pragma unroll
        for (int ni = 0; ni < 4; ni++) {
            int n = wn * 32 + ni * 8 + qcol;
            *(float2*)(rowA + n) = make_float2(acc[mi][ni][0] + bA, acc[mi][ni][1] + bA);
            *(float2*)(rowB + n) = make_float2(acc[mi][ni][2] + bB, acc[mi][ni][3] + bB);
        }
    }
}

// ============================================================================
// Kernel 2a: FUSED depthwise conv (B_ ch s and dt ch 128+s) + exp + multiply.
// Rolling 3-plane smem buffers over all dz. Per-batch launch.
// ============================================================================
__global__ void __launch_bounds__(256) conv_ab_kernel(
    const float* __restrict__ wdw, const float* __restrict__ bdw, int b)
{
    __shared__ float sB[3][34][66];
    __shared__ float sD[3][34][66];
    __shared__ float wB[27], wD[27];
    __shared__ float red[8];

    const int hhalf = blockIdx.x;
    const int s_ = blockIdx.y;
    const int h0 = hhalf * 32;
    const int tid = threadIdx.x;
    const int chB = s_;
    const int chD = 128 + s_;

    const float* baseB = g_bcdt + ((size_t)(b * O3S + chB)) * NN;
    const float* baseD = g_bcdt + ((size_t)(b * O3S + chD)) * NN;

    if (tid < 27) wB[tid] = wdw[chB * 27 + tid];
    else if (tid >= 32 && tid < 59) wD[tid - 32] = wdw[chD * 27 + (tid - 32)];
    const float biasB = bdw[chB];
    const float biasD = bdw[chD];

    auto loadplane = [&](int z, int slot) {
        for (int idx = tid; idx < 34 * 66; idx += 256) {
            int ih = idx / 66, iw = idx % 66;
            int h = h0 - 1 + ih, w = iw - 1;
            bool ok = ((unsigned)z < (unsigned)DD) && ((unsigned)h < (unsigned)HH)
                      && ((unsigned)w < (unsigned)WW);
            size_t g = (size_t)z * (HH * WW) + (size_t)h * WW + w;
            sB[slot][ih][iw] = ok ? baseB[g] : 0.f;
            sD[slot][ih][iw] = ok ? baseD[g] : 0.f;
        }
    };
    loadplane(-1, 0);
    loadplane(0, 1);
    loadplane(1, 2);
    __syncthreads();

    const int w = tid & 63;
    const int hl0 = tid >> 6;
    float* abp = g_ab + ((size_t)(b * SS + s_)) * NN;
    float lsum = 0.f;

    for (int dz = 0; dz < DD; dz++) {
        const int p0 = dz % 3, p1 = (dz + 1) % 3, p2 = (dz + 2) % 3;
#pragma unroll
        for (int r = 0; r < 8; r++) {
            int hl = hl0 + r * 4;
            float aB = biasB, aD = biasD;
#pragma unroll
            for (int kh = 0; kh < 3; kh++)
#pragma unroll
                for (int kw = 0; kw < 3; kw++) {
                    aB += sB[p0][hl + kh][w + kw] * wB[0 * 9 + kh * 3 + kw];
                    aD += sD[p0][hl + kh][w + kw] * wD[0 * 9 + kh * 3 + kw];
                    aB += sB[p1][hl + kh][w + kw] * wB[1 * 9 + kh * 3 + kw];
                    aD += sD[p1][hl + kh][w + kw] * wD[1 * 9 + kh * 3 + kw];
                    aB += sB[p2][hl + kh][w + kw] * wB[2 * 9 + kh * 3 + kw];
                    aD += sD[p2][hl + kh][w + kw] * wD[2 * 9 + kh * 3 + kw];
                }
            float e = fexp(aD);
            lsum += e;
            abp[(size_t)dz * (HH * WW) + (h0 + hl) * WW + w] = e * aB;
        }
        __syncthreads();
        if (dz < DD - 1) loadplane(dz + 2, p0);
        __syncthreads();
    }

    const int lane = tid & 31, warp = tid >> 5;
#pragma unroll
    for (int o = 16; o > 0; o >>= 1) lsum += __shfl_xor_sync(0xffffffffu, lsum, o);
    if (lane == 0) red[warp] = lsum;
    __syncthreads();
    if (tid == 0) {
        float v = red[0] + red[1] + red[2] + red[3] + red[4] + red[5] + red[6] + red[7];
        g_psum[(b * SS + s_) * 2 + hhalf] = v;
    }
}

// ============================================================================
// Kernel 2b: depthwise conv for C_ channels (64..127), rolling dz. Per-batch.
// ============================================================================
__global__ void __launch_bounds__(256) conv_c_kernel(
    const float* __restrict__ wdw, const float* __restrict__ bdw, int b)
{
    __shared__ float s[3][34][66];
    __shared__ float wt[27];

    const int hhalf = blockIdx.x;
    const int s_ = blockIdx.y;
    const int h0 = hhalf * 32;
    const int tid = threadIdx.x;
    const int ch = 64 + s_;

    const float* base = g_bcdt + ((size_t)(b * O3S + ch)) * NN;
    if (tid < 27) wt[tid] = wdw[ch * 27 + tid];
    const float bb = bdw[ch];

    auto loadplane = [&](int z, int slot) {
        for (int idx = tid; idx < 34 * 66; idx += 256) {
            int ih = idx / 66, iw = idx % 66;
            int h = h0 - 1 + ih, w = iw - 1;
            bool ok = ((unsigned)z < (unsigned)DD) && ((unsigned)h < (unsigned)HH)
                      && ((unsigned)w < (unsigned)WW);
            size_t g = (size_t)z * (HH * WW) + (size_t)h * WW + w;
            s[slot][ih][iw] = ok ? base[g] : 0.f;
        }
    };
    loadplane(-1, 0);
    loadplane(0, 1);
    loadplane(1, 2);
    __syncthreads();

    const int w = tid & 63;
    const int hl0 = tid >> 6;
    float* outp = g_c + ((size_t)(b * SS + s_)) * NN;

    for (int dz = 0; dz < DD; dz++) {
        const int p0 = dz % 3, p1 = (dz + 1) % 3, p2 = (dz + 2) % 3;
#pragma unroll
        for (int r = 0; r < 8; r++) {
            int hl = hl0 + r * 4;
            float a = bb;
#pragma unroll
            for (int kh = 0; kh < 3; kh++)
#pragma unroll
                for (int kw = 0; kw < 3; kw++) {
                    a += s[p0][hl + kh][w + kw] * wt[0 * 9 + kh * 3 + kw];
                    a += s[p1][hl + kh][w + kw] * wt[1 * 9 + kh * 3 + kw];
                    a += s[p2][hl + kh][w + kw] * wt[2 * 9 + kh * 3 + kw];
                }
            outp[(size_t)dz * (HH * WW) + (h0 + hl) * WW + w] = a;
        }
        __syncthreads();
        if (dz < DD - 1) loadplane(dz + 2, p0);
        __syncthreads();
    }
}

// ============================================================================
// Kernel 4 (HMMA): h_unnorm partials = sum_n x * AB_unnorm. Per-batch.
// BM=64(c), BN=64(s), BK=32. Register-prefetch double buffer.
// ============================================================================
__global__ void __launch_bounds__(256) hgemm_mma_kernel(const float* __restrict__ x, int b)
{
    __shared__ __align__(16) uint16_t As_hi[64 * A_STRIDE];
    __shared__ __align__(16) uint16_t As_lo[64 * A_STRIDE];
    __shared__ __align__(16) uint16_t Bs_hi[64 * HB_STRIDE];
    __shared__ __align__(16) uint16_t Bs_lo[64 * HB_STRIDE];

    const int c0 = blockIdx.x * 64;          // fastest -> L2 sharing of AB tile
    const int ks = blockIdx.y;               // 0..63
    const int nbase = ks * (NN / KSPLIT_H);  // 1024 chunk
    const int tid  = threadIdx.x;
    const int wid  = tid >> 5;
    const int lane = tid & 31;
    const int wm = wid >> 2;
    const int wn = wid & 3;

    const float* xb = x + ((size_t)(b * CC + c0)) * NN;
    const float* ab = g_ab + (size_t)b * SS * NN;
    const uint32_t as_hi = smem_u32(As_hi), as_lo = smem_u32(As_lo);
    const uint32_t bs_hi = smem_u32(Bs_hi), bs_lo = smem_u32(Bs_lo);

    const int lr = tid >> 3;            // 0..31
    const int lk = (tid & 7) << 2;      // 0..28

    float acc[2][2][4];
#pragma unroll
    for (int i = 0; i < 2; i++)
#pragma unroll
        for (int j = 0; j < 2; j++)
#pragma unroll
            for (int q = 0; q < 4; q++) acc[i][j][q] = 0.f;

    float4 rx[2], rab[2];
    rx[0]  = *(const float4*)(xb + (size_t)lr * NN + nbase + lk);
    rx[1]  = *(const float4*)(xb + (size_t)(lr + 32) * NN + nbase + lk);
    rab[0] = *(const float4*)(ab + (size_t)lr * NN + nbase + lk);
    rab[1] = *(const float4*)(ab + (size_t)(lr + 32) * NN + nbase + lk);

    for (int kc = 0; kc < NN / KSPLIT_H; kc += 32) {
#pragma unroll
        for (int r = 0; r < 2; r++) {
            float4 v = rx[r];
            uint32_t h01, l01, h23, l23;
            split2(v.x, v.y, h01, l01);
            split2(v.z, v.w, h23, l23);
            int off = (lr + r * 32) * A_STRIDE + lk;
            *(uint2*)(As_hi + off) = make_uint2(h01, h23);
            *(uint2*)(As_lo + off) = make_uint2(l01, l23);
        }
#pragma unroll
        for (int r = 0; r < 2; r++) {
            float4 v = rab[r];
            uint32_t h01, l01, h23, l23;
            split2(v.x, v.y, h01, l01);
            split2(v.z, v.w, h23, l23);
            int off = (lr + r * 32) * HB_STRIDE + lk;
            *(uint2*)(Bs_hi + off) = make_uint2(h01, h23);
            *(uint2*)(Bs_lo + off) = make_uint2(l01, l23);
        }
        __syncthreads();

        if (kc + 32 < NN / KSPLIT_H) {
            const int nb2 = nbase + kc + 32;
            rx[0]  = *(const float4*)(xb + (size_t)lr * NN + nb2 + lk);
            rx[1]  = *(const float4*)(xb + (size_t)(lr + 32) * NN + nb2 + lk);
            rab[0] = *(const float4*)(ab + (size_t)lr * NN + nb2 + lk);
            rab[1] = *(const float4*)(ab + (size_t)(lr + 32) * NN + nb2 + lk);
        }

#pragma unroll
        for (int kq = 0; kq < 2; kq++) {
            uint32_t a_hi[2][4], a_lo[2][4];
            const int arow = lane & 15;
            const int acol = (lane >> 4) << 3;
#pragma unroll
            for (int mi = 0; mi < 2; mi++) {
                uint32_t off = (uint32_t)((wm * 32 + mi * 16 + arow) * A_STRIDE
                                          + kq * 16 + acol) * 2;
                ldsm_x4(a_hi[mi], as_hi + off);
                ldsm_x4(a_lo[mi], as_lo + off);
            }
            uint32_t b_hi[2][2], b_lo[2][2];
            const int l = lane & 15;
            const int srow = l & 7;
            const int koff = (l >> 3) << 3;
#pragma unroll
            for (int ni = 0; ni < 2; ni++) {
                uint32_t off = (uint32_t)((wn * 16 + ni * 8 + srow) * HB_STRIDE
                                          + kq * 16 + koff) * 2;
                ldsm_x2(b_hi[ni], bs_hi + off);
                ldsm_x2(b_lo[ni], bs_lo + off);
            }
#pragma unroll
            for (int mi = 0; mi < 2; mi++)
#pragma unroll
                for (int ni = 0; ni < 2; ni++) {
                    mma_bf16(acc[mi][ni], a_hi[mi], b_hi[ni]);
                    mma_bf16(acc[mi][ni], a_hi[mi], b_lo[ni]);
                    mma_bf16(acc[mi][ni], a_lo[mi], b_hi[ni]);
                }
        }
        __syncthreads();
    }

    float* dst = g_hpart + (size_t)ks * (BB * CC * SS);
    const int qrow = lane >> 2;
    const int qcol = (lane & 3) << 1;
#pragma unroll
    for (int mi = 0; mi < 2; mi++) {
        int cA = c0 + wm * 32 + mi * 16 + qrow;
#pragma unroll
        for (int ni = 0; ni < 2; ni++) {
            int sA = wn * 16 + ni * 8 + qcol;
            float* pA = dst + ((size_t)(b * CC + cA)) * SS + sA;
            float* pB = dst + ((size_t)(b * CC + cA + 8)) * SS + sA;
            *(float2*)pA = make_float2(acc[mi][ni][0], acc[mi][ni][1]);
            *(float2*)pB = make_float2(acc[mi][ni][2], acc[mi][ni][3]);
        }
    }
}

// reduction of split-K partials + deferred softmax normalization
__global__ void __launch_bounds__(256) hreduce_kernel()
{
    int i = blockIdx.x * 256 + threadIdx.x;   // ((b*CC+c)*SS+s) < 65536
    int b = i >> 14;
    int s = i & 63;
    const float* ps = &g_psum[(b * SS + s) * 2];
    float inv = 1.f / (ps[0] + ps[1]);
    float sum = 0.f;
#pragma unroll
    for (int ks = 0; ks < KSPLIT_H; ks++)
        sum += g_hpart[(size_t)ks * (BB * CC * SS) + i];
    g_h[i] = sum * inv;
}

// ============================================================================
// Kernel 5: hz = W_hz @ h + b_hz ; h3 = h2*silu(z) + h2*Dp
// ============================================================================
__global__ void __launch_bounds__(256) e1_kernel(
    const float* __restrict__ Whz, const float* __restrict__ bhz,
    const float* __restrict__ Dp)
{
    const int b = blockIdx.y;
    const int o = blockIdx.x * 4 + (threadIdx.x >> 6);
    const int s_ = threadIdx.x & 63;
    const float* hb = g_h + (size_t)b * CC * SS;
    const float* w1 = Whz + (size_t)o * 256;
    const float* w2 = Whz + (size_t)(o + 256) * 256;
    float a1 = bhz[o], a2 = bhz[o + 256];
    for (int c = 0; c < 256; c++) {
        float hv = hb[c * 64 + s_];
        a1 += w1[c] * hv;
        a2 += w2[c] * hv;
    }
    float sig = 1.f / (1.f + __expf(-a2));
    g_h3[((size_t)b * CC + o) * SS + s_] = a1 * (a2 * sig) + a1 * Dp[0];
}

// Kernel 6: h4 = W_out @ h3 + b_out ; write to scratch + output tail
__global__ void __launch_bounds__(256) e2_kernel(
    const float* __restrict__ Wout, const float* __restrict__ bout,
    float* __restrict__ out)
{
    const int b = blockIdx.y;
    const int o = blockIdx.x * 4 + (threadIdx.x >> 6);
    const int s_ = threadIdx.x & 63;
    const float* hb = g_h3 + (size_t)b * CC * SS;
    const float* w1 = Wout + (size_t)o * 256;
    float acc = bout[o];
    for (int c = 0; c < 256; c++)
        acc += w1[c] * hb[c * 64 + s_];
    size_t idx = ((size_t)b * CC + o) * SS + s_;
    g_h4[idx] = acc;
    out[YSIZE + idx] = acc;
}

// ============================================================================
// Kernel 7 (HMMA): y[b,c,n] = sum_s h4[b,c,s] * C_[b,s,n]
// ============================================================================
__global__ void __launch_bounds__(256) ygemm_mma_kernel(float* __restrict__ y)
{
    __shared__ __align__(16) uint16_t As_hi[64 * A_STRIDE];
    __shared__ __align__(16) uint16_t As_lo[64 * A_STRIDE];
    __shared__ __align__(16) uint16_t Bs_hi[32 * B_STRIDE];
    __shared__ __align__(16) uint16_t Bs_lo[32 * B_STRIDE];

    const int m0 = blockIdx.x * 64;     // fastest -> L2 sharing of C_ tile
    const int n0 = blockIdx.y * 128;
    const int b  = blockIdx.z;
    const int tid  = threadIdx.x;
    const int wid  = tid >> 5;
    const int lane = tid & 31;
    const int wm = wid >> 2;
    const int wn = wid & 3;

    const float* h4b = g_h4 + (size_t)b * CC * SS;
    const float* cp  = g_c + (size_t)b * SS * NN;
    const uint32_t as_hi = smem_u32(As_hi), as_lo = smem_u32(As_lo);
    const uint32_t bs_hi = smem_u32(Bs_hi), bs_lo = smem_u32(Bs_lo);

    float acc[2][4][4];
#pragma unroll
    for (int i = 0; i < 2; i++)
#pragma unroll
        for (int j = 0; j < 4; j++)
#pragma unroll
            for (int q = 0; q < 4; q++) acc[i][j][q] = 0.f;

    for (int k0 = 0; k0 < 64; k0 += 32) {
#pragma unroll
        for (int r = 0; r < 2; r++) {
            int f = tid + r * 256;
            int m = f >> 3, k = (f & 7) << 2;
            float4 v = *(const float4*)(h4b + (size_t)(m0 + m) * SS + k0 + k);
            uint32_t h01, l01, h23, l23;
            split2(v.x, v.y, h01, l01);
            split2(v.z, v.w, h23, l23);
            int off = m * A_STRIDE + k;
            *(uint2*)(As_hi + off) = make_uint2(h01, h23);
            *(uint2*)(As_lo + off) = make_uint2(l01, l23);
        }
#pragma unroll
        for (int r = 0; r < 4; r++) {
            int f = tid + r * 256;
            int krow = f >> 5, n = (f & 31) << 2;
            float4 v = *(const float4*)(cp + (size_t)(k0 + krow) * NN + n0 + n);
            uint32_t h01, l01, h23, l23;
            split2(v.x, v.y, h01, l01);
            split2(v.z, v.w, h23, l23);
            int off = krow * B_STRIDE + n;
            *(uint2*)(Bs_hi + off) = make_uint2(h01, h23);
            *(uint2*)(Bs_lo + off) = make_uint2(l01, l23);
        }
        __syncthreads();

#pragma unroll
        for (int ks = 0; ks < 2; ks++) {
            uint32_t a_hi[2][4], a_lo[2][4];
            const int arow = lane & 15;
            const int acol = (lane >> 4) << 3;
#pragma unroll
            for (int mi = 0; mi < 2; mi++) {
                uint32_t off = (uint32_t)((wm * 32 + mi * 16 + arow) * A_STRIDE
                                          + ks * 16 + acol) * 2;
                ldsm_x4(a_hi[mi], as_hi + off);
                ldsm_x4(a_lo[mi], as_lo + off);
            }
            uint32_t b_hi[4][2], b_lo[4][2];
            const int brow = lane & 15;
#pragma unroll
            for (int ni = 0; ni < 4; ni++) {
                uint32_t off = (uint32_t)((ks * 16 + brow) * B_STRIDE
                                          + wn * 32 + ni * 8) * 2;
                ldsm_x2_t(b_hi[ni], bs_hi + off);
                ldsm_x2_t(b_lo[ni], bs_lo + off);
            }
#pragma unroll
            for (int mi = 0; mi < 2; mi++)
#pragma unroll
                for (int ni = 0; ni < 4; ni++) {
                    mma_bf16(acc[mi][ni], a_hi[mi], b_hi[ni]);
                    mma_bf16(acc[mi][ni], a_hi[mi], b_lo[ni]);
                    mma_bf16(acc[mi][ni], a_lo[mi], b_hi[ni]);
                }
        }
        __syncthreads();
    }

    const int qrow = lane >> 2;
    const int qcol = (lane & 3) << 1;
#pragma unroll
    for (int mi = 0; mi < 2; mi++) {
        int mA = m0 + wm * 32 + mi * 16 + qrow;
        float* rowA = y + ((size_t)(b * CC + mA)) * NN + n0;
        float* rowB = rowA + (size_t)8 * NN;
#pragma unroll
        for (int ni = 0; ni < 4; ni++) {
            int n = wn * 32 + ni * 8 + qcol;
            *(float2*)(rowA + n) = make_float2(acc[mi][ni][0], acc[mi][ni][1]);
            *(float2*)(rowB + n) = make_float2(acc[mi][ni][2], acc[mi][ni][3]);
        }
    }
}

// ============================================================================
extern "C" void kernel_launch(void* const* d_in, const int* in_sizes, int n_in,
                              void* d_out, int out_size)
{
    const float* x      = (const float*)d_in[0];
    const float* W_bcdt = (const float*)d_in[1];
    const float* b_bcdt = (const float*)d_in[2];
    const float* W_dw   = (const float*)d_in[3];
    const float* b_dw   = (const float*)d_in[4];
    const float* W_hz   = (const float*)d_in[5];
    const float* b_hz   = (const float*)d_in[6];
    const float* W_out  = (const float*)d_in[7];
    const float* b_out  = (const float*)d_in[8];
    // d_in[9] = A : unused (softmax shift invariance along the reduced axis)
    const float* Dp     = (const float*)d_in[10];
    float* out = (float*)d_out;

    // streams + per-batch fork/join events (created once; no device allocs)
    static cudaStream_t s1 = nullptr, s2 = nullptr, s3 = nullptr;
    static cudaEvent_t evG[BB], evA[BB], evC[BB], evH[BB];
    if (!s1) {
        cudaStreamCreateWithFlags(&s1, cudaStreamNonBlocking);
        cudaStreamCreateWithFlags(&s2, cudaStreamNonBlocking);
        cudaStreamCreateWithFlags(&s3, cudaStreamNonBlocking);
        for (int b = 0; b < BB; b++) {
            cudaEventCreateWithFlags(&evG[b], cudaEventDisableTiming);
            cudaEventCreateWithFlags(&evA[b], cudaEventDisableTiming);
            cudaEventCreateWithFlags(&evC[b], cudaEventDisableTiming);
            cudaEventCreateWithFlags(&evH[b], cudaEventDisableTiming);
        }
    }

    // Batch-pipelined front-end:
    //   stream0: gemm1(b)          -> evG[b]
    //   s1:  conv_ab(b) after evG  -> evA[b]
    //   s2:  conv_c(b)  after evG  -> evC[b]
    //   s3:  hgemm(b)   after evA  -> evH[b]
    for (int b = 0; b < BB; b++) {
        gemm1_mma_kernel<<<dim3(3, NN / 128, 1), 256>>>(x, W_bcdt, b_bcdt, b);
        cudaEventRecord(evG[b], 0);

        cudaStreamWaitEvent(s1, evG[b], 0);
        conv_ab_kernel<<<dim3(2, SS, 1), 256, 0, s1>>>(W_dw, b_dw, b);
        cudaEventRecord(evA[b], s1);

        cudaStreamWaitEvent(s2, evG[b], 0);
        conv_c_kernel<<<dim3(2, SS, 1), 256, 0, s2>>>(W_dw, b_dw, b);
        cudaEventRecord(evC[b], s2);

        cudaStreamWaitEvent(s3, evA[b], 0);
        hgemm_mma_kernel<<<dim3(4, KSPLIT_H, 1), 256, 0, s3>>>(x, b);
        cudaEventRecord(evH[b], s3);
    }

    // Tail on stream0: join all hgemm, then reduce + MLP, join conv_c, ygemm.
    for (int b = 0; b < BB; b++) cudaStreamWaitEvent(0, evH[b], 0);
    hreduce_kernel<<<256, 256>>>();
    e1_kernel<<<dim3(64, BB), 256>>>(W_hz, b_hz, Dp);
    e2_kernel<<<dim3(64, BB), 256>>>(W_out, b_out, out);
    for (int b = 0; b < BB; b++) cudaStreamWaitEvent(0, evC[b], 0);
    ygemm_mma_kernel<<<dim3(4, NN / 128, BB), 256>>>(out);
}

// round 11
// speedup vs baseline: 1.1326x; 1.1326x over previous
#include <cuda_runtime.h>
#include <cuda_bf16.h>
#include <cstdint>
#include <cstddef>

// Problem constants
#define BB   4
#define CC   256      // D_MODEL = D_INNER
#define SS   64
#define DD   16
#define HH   64
#define WW   64
#define NN   65536    // D*H*W
#define O3S  192      // 3*S
#define KSPLIT_H 64   // split-K factor for h-GEMM

static const size_t YSIZE = (size_t)BB * CC * NN;   // 67108864

// ---- static scratch (no runtime allocation allowed) ----
__device__ float g_bcdt[(size_t)BB * O3S * NN];   // GEMM1 output (pre-conv)
__device__ float g_ab[(size_t)BB * SS * NN];      // AB_unnorm = exp(conv dt)*conv B_
__device__ float g_c [(size_t)BB * SS * NN];      // conv C_ channels
__device__ float g_hpart[(size_t)KSPLIT_H * BB * CC * SS];
__device__ float g_psum[BB * SS * 2];             // per-h-half exp-sums
__device__ float g_h [BB * CC * SS];
__device__ float g_h3[BB * CC * SS];
__device__ float g_h4[BB * CC * SS];

// ============================================================================
// helpers
// ============================================================================
__device__ __forceinline__ uint32_t smem_u32(const void* p) {
    uint32_t a;
    asm("{ .reg .u64 t; cvta.to.shared.u64 t, %1; cvt.u32.u64 %0, t; }" : "=r"(a) : "l"(p));
    return a;
}
__device__ __forceinline__ void ldsm_x4(uint32_t* r, uint32_t addr) {
    asm volatile("ldmatrix.sync.aligned.m8n8.x4.shared.b16 {%0,%1,%2,%3}, [%4];"
        : "=r"(r[0]), "=r"(r[1]), "=r"(r[2]), "=r"(r[3]) : "r"(addr));
}
__device__ __forceinline__ void ldsm_x2(uint32_t* r, uint32_t addr) {
    asm volatile("ldmatrix.sync.aligned.m8n8.x2.shared.b16 {%0,%1}, [%2];"
        : "=r"(r[0]), "=r"(r[1]) : "r"(addr));
}
__device__ __forceinline__ void ldsm_x2_t(uint32_t* r, uint32_t addr) {
    asm volatile("ldmatrix.sync.aligned.m8n8.x2.trans.shared.b16 {%0,%1}, [%2];"
        : "=r"(r[0]), "=r"(r[1]) : "r"(addr));
}
__device__ __forceinline__ void mma_bf16(float* c, const uint32_t* a, const uint32_t* b) {
    asm volatile(
        "mma.sync.aligned.m16n8k16.row.col.f32.bf16.bf16.f32 "
        "{%0,%1,%2,%3}, {%4,%5,%6,%7}, {%8,%9}, {%0,%1,%2,%3};"
        : "+f"(c[0]), "+f"(c[1]), "+f"(c[2]), "+f"(c[3])
        : "r"(a[0]), "r"(a[1]), "r"(a[2]), "r"(a[3]), "r"(b[0]), "r"(b[1]));
}
__device__ __forceinline__ void split2(float v0, float v1, uint32_t& hi, uint32_t& lo) {
    __nv_bfloat16 h0 = __float2bfloat16(v0), h1 = __float2bfloat16(v1);
    float r0 = v0 - __bfloat162float(h0), r1 = v1 - __bfloat162float(h1);
    __nv_bfloat162 hh = __halves2bfloat162(h0, h1);
    __nv_bfloat162 ll = __floats2bfloat162_rn(r0, r1);
    hi = *(uint32_t*)&hh; lo = *(uint32_t*)&ll;
}
// FMA-pipe exp (poly 2^f on [-0.5,0.5], ~2e-9 rel err), clamped both sides
__device__ __forceinline__ float fexp(float x) {
    float t = fminf(fmaxf(x * 1.4426950408889634f, -125.0f), 125.0f);
    float n = rintf(t);
    float f = t - n;
    float p = 1.5403530393381609e-4f;
    p = fmaf(p, f, 1.3333558146428443e-3f);
    p = fmaf(p, f, 9.618129107628477e-3f);
    p = fmaf(p, f, 5.550410866482158e-2f);
    p = fmaf(p, f, 2.402265069591999e-1f);
    p = fmaf(p, f, 6.931471805599453e-1f);
    p = fmaf(p, f, 1.0f);
    return __int_as_float(((int)n + 127) << 23) * p;
}

#define A_STRIDE 40    // halves per 32-k row (32 + 8 pad)
#define B_STRIDE 136   // halves per 128-n row (128 + 8 pad)
#define HB_STRIDE 40

// ============================================================================
// Kernel 1 (HMMA): BCdt rows = W_bcdt @ x + b_bcdt for a SUBSET of m-tiles.
// m0 = m_base + blockIdx.x * m_step. Full batch in grid.z.
// Launch A: (2, 512, BB) base=0   step=128  -> B_ rows 0-63 + dt rows 128-191
// Launch B: (1, 512, BB) base=64  step=0    -> C_ rows 64-127
// ============================================================================
__global__ void __launch_bounds__(256) gemm1_mma_kernel(
    const float* __restrict__ x, const float* __restrict__ W,
    const float* __restrict__ bias, int m_base, int m_step)
{
    __shared__ __align__(16) uint16_t As_hi[64 * A_STRIDE];
    __shared__ __align__(16) uint16_t As_lo[64 * A_STRIDE];
    __shared__ __align__(16) uint16_t Bs_hi[32 * B_STRIDE];
    __shared__ __align__(16) uint16_t Bs_lo[32 * B_STRIDE];

    const int m0 = m_base + blockIdx.x * m_step;
    const int n0 = blockIdx.y * 128;
    const int b  = blockIdx.z;
    const int tid  = threadIdx.x;
    const int wid  = tid >> 5;
    const int lane = tid & 31;
    const int wm = wid >> 2;
    const int wn = wid & 3;

    const float* xb = x + (size_t)b * CC * NN;
    const uint32_t as_hi = smem_u32(As_hi), as_lo = smem_u32(As_lo);
    const uint32_t bs_hi = smem_u32(Bs_hi), bs_lo = smem_u32(Bs_lo);

    const int krow0 = tid >> 5;
    const int nloc  = (tid & 31) << 2;

    float acc[2][4][4];
#pragma unroll
    for (int i = 0; i < 2; i++)
#pragma unroll
        for (int j = 0; j < 4; j++)
#pragma unroll
            for (int q = 0; q < 4; q++) acc[i][j][q] = 0.f;

    float4 rbx[4];
#pragma unroll
    for (int r = 0; r < 4; r++)
        rbx[r] = *(const float4*)(xb + (size_t)(krow0 + r * 8) * NN + n0 + nloc);

    for (int k0 = 0; k0 < 256; k0 += 32) {
#pragma unroll
        for (int r = 0; r < 2; r++) {
            int f = tid + r * 256;
            int m = f >> 3, k = (f & 7) << 2;
            float4 v = *(const float4*)(W + (size_t)(m0 + m) * 256 + k0 + k);
            uint32_t h01, l01, h23, l23;
            split2(v.x, v.y, h01, l01);
            split2(v.z, v.w, h23, l23);
            int off = m * A_STRIDE + k;
            *(uint2*)(As_hi + off) = make_uint2(h01, h23);
            *(uint2*)(As_lo + off) = make_uint2(l01, l23);
        }
#pragma unroll
        for (int r = 0; r < 4; r++) {
            float4 v = rbx[r];
            uint32_t h01, l01, h23, l23;
            split2(v.x, v.y, h01, l01);
            split2(v.z, v.w, h23, l23);
            int off = (krow0 + r * 8) * B_STRIDE + nloc;
            *(uint2*)(Bs_hi + off) = make_uint2(h01, h23);
            *(uint2*)(Bs_lo + off) = make_uint2(l01, l23);
        }
        __syncthreads();

        if (k0 + 32 < 256) {
#pragma unroll
            for (int r = 0; r < 4; r++)
                rbx[r] = *(const float4*)(xb + (size_t)(k0 + 32 + krow0 + r * 8) * NN + n0 + nloc);
        }

#pragma unroll
        for (int ks = 0; ks < 2; ks++) {
            uint32_t a_hi[2][4], a_lo[2][4];
            const int arow = lane & 15;
            const int acol = (lane >> 4) << 3;
#pragma unroll
            for (int mi = 0; mi < 2; mi++) {
                uint32_t off = (uint32_t)((wm * 32 + mi * 16 + arow) * A_STRIDE
                                          + ks * 16 + acol) * 2;
                ldsm_x4(a_hi[mi], as_hi + off);
                ldsm_x4(a_lo[mi], as_lo + off);
            }
            uint32_t b_hi[4][2], b_lo[4][2];
            const int brow = lane & 15;
#pragma unroll
            for (int ni = 0; ni < 4; ni++) {
                uint32_t off = (uint32_t)((ks * 16 + brow) * B_STRIDE
                                          + wn * 32 + ni * 8) * 2;
                ldsm_x2_t(b_hi[ni], bs_hi + off);
                ldsm_x2_t(b_lo[ni], bs_lo + off);
            }
#pragma unroll
            for (int mi = 0; mi < 2; mi++)
#pragma unroll
                for (int ni = 0; ni < 4; ni++) {
                    mma_bf16(acc[mi][ni], a_hi[mi], b_hi[ni]);
                    mma_bf16(acc[mi][ni], a_hi[mi], b_lo[ni]);
                    mma_bf16(acc[mi][ni], a_lo[mi], b_hi[ni]);
                }
        }
        __syncthreads();
    }

    const int qrow = lane >> 2;
    const int qcol = (lane & 3) << 1;
#pragma unroll
    for (int mi = 0; mi < 2; mi++) {
        int mA = m0 + wm * 32 + mi * 16 + qrow;
        float bA = bias[mA], bB = bias[mA + 8];
        float* rowA = g_bcdt + ((size_t)(b * O3S + mA)) * NN + n0;
        float* rowB = rowA + (size_t)8 * NN;
#pragma unroll
        for (int ni = 0; ni < 4; ni++) {
            int n = wn * 32 + ni * 8 + qcol;
            *(float2*)(rowA + n) = make_float2(acc[mi][ni][0] + bA, acc[mi][ni][1] + bA);
            *(float2*)(rowB + n) = make_float2(acc[mi][ni][2] + bB, acc[mi][ni][3] + bB);
        }
    }
}

// ============================================================================
// Kernel 2a: FUSED depthwise conv (B_ ch s and dt ch 128+s) + exp + multiply.
// Rolling 3-plane smem buffers over all dz.
// ============================================================================
__global__ void __launch_bounds__(256) conv_ab_kernel(
    const float* __restrict__ wdw, const float* __restrict__ bdw)
{
    __shared__ float sB[3][34][66];
    __shared__ float sD[3][34][66];
    __shared__ float wB[27], wD[27];
    __shared__ float red[8];

    const int hhalf = blockIdx.x;
    const int s_ = blockIdx.y;
    const int b  = blockIdx.z;
    const int h0 = hhalf * 32;
    const int tid = threadIdx.x;
    const int chB = s_;
    const int chD = 128 + s_;

    const float* baseB = g_bcdt + ((size_t)(b * O3S + chB)) * NN;
    const float* baseD = g_bcdt + ((size_t)(b * O3S + chD)) * NN;

    if (tid < 27) wB[tid] = wdw[chB * 27 + tid];
    else if (tid >= 32 && tid < 59) wD[tid - 32] = wdw[chD * 27 + (tid - 32)];
    const float biasB = bdw[chB];
    const float biasD = bdw[chD];

    auto loadplane = [&](int z, int slot) {
        for (int idx = tid; idx < 34 * 66; idx += 256) {
            int ih = idx / 66, iw = idx % 66;
            int h = h0 - 1 + ih, w = iw - 1;
            bool ok = ((unsigned)z < (unsigned)DD) && ((unsigned)h < (unsigned)HH)
                      && ((unsigned)w < (unsigned)WW);
            size_t g = (size_t)z * (HH * WW) + (size_t)h * WW + w;
            sB[slot][ih][iw] = ok ? baseB[g] : 0.f;
            sD[slot][ih][iw] = ok ? baseD[g] : 0.f;
        }
    };
    loadplane(-1, 0);
    loadplane(0, 1);
    loadplane(1, 2);
    __syncthreads();

    const int w = tid & 63;
    const int hl0 = tid >> 6;
    float* abp = g_ab + ((size_t)(b * SS + s_)) * NN;
    float lsum = 0.f;

    for (int dz = 0; dz < DD; dz++) {
        const int p0 = dz % 3, p1 = (dz + 1) % 3, p2 = (dz + 2) % 3;
#pragma unroll
        for (int r = 0; r < 8; r++) {
            int hl = hl0 + r * 4;
            float aB = biasB, aD = biasD;
#pragma unroll
            for (int kh = 0; kh < 3; kh++)
#pragma unroll
                for (int kw = 0; kw < 3; kw++) {
                    aB += sB[p0][hl + kh][w + kw] * wB[0 * 9 + kh * 3 + kw];
                    aD += sD[p0][hl + kh][w + kw] * wD[0 * 9 + kh * 3 + kw];
                    aB += sB[p1][hl + kh][w + kw] * wB[1 * 9 + kh * 3 + kw];
                    aD += sD[p1][hl + kh][w + kw] * wD[1 * 9 + kh * 3 + kw];
                    aB += sB[p2][hl + kh][w + kw] * wB[2 * 9 + kh * 3 + kw];
                    aD += sD[p2][hl + kh][w + kw] * wD[2 * 9 + kh * 3 + kw];
                }
            float e = fexp(aD);
            lsum += e;
            abp[(size_t)dz * (HH * WW) + (h0 + hl) * WW + w] = e * aB;
        }
        __syncthreads();
        if (dz < DD - 1) loadplane(dz + 2, p0);
        __syncthreads();
    }

    const int lane = tid & 31, warp = tid >> 5;
#pragma unroll
    for (int o = 16; o > 0; o >>= 1) lsum += __shfl_xor_sync(0xffffffffu, lsum, o);
    if (lane == 0) red[warp] = lsum;
    __syncthreads();
    if (tid == 0) {
        float v = red[0] + red[1] + red[2] + red[3] + red[4] + red[5] + red[6] + red[7];
        g_psum[(b * SS + s_) * 2 + hhalf] = v;
    }
}

// ============================================================================
// Kernel 2b: depthwise conv for C_ channels (64..127), rolling dz.
// ============================================================================
__global__ void __launch_bounds__(256) conv_c_kernel(
    const float* __restrict__ wdw, const float* __restrict__ bdw)
{
    __shared__ float s[3][34][66];
    __shared__ float wt[27];

    const int hhalf = blockIdx.x;
    const int s_ = blockIdx.y;
    const int b  = blockIdx.z;
    const int h0 = hhalf * 32;
    const int tid = threadIdx.x;
    const int ch = 64 + s_;

    const float* base = g_bcdt + ((size_t)(b * O3S + ch)) * NN;
    if (tid < 27) wt[tid] = wdw[ch * 27 + tid];
    const float bb = bdw[ch];

    auto loadplane = [&](int z, int slot) {
        for (int idx = tid; idx < 34 * 66; idx += 256) {
            int ih = idx / 66, iw = idx % 66;
            int h = h0 - 1 + ih, w = iw - 1;
            bool ok = ((unsigned)z < (unsigned)DD) && ((unsigned)h < (unsigned)HH)
                      && ((unsigned)w < (unsigned)WW);
            size_t g = (size_t)z * (HH * WW) + (size_t)h * WW + w;
            s[slot][ih][iw] = ok ? base[g] : 0.f;
        }
    };
    loadplane(-1, 0);
    loadplane(0, 1);
    loadplane(1, 2);
    __syncthreads();

    const int w = tid & 63;
    const int hl0 = tid >> 6;
    float* outp = g_c + ((size_t)(b * SS + s_)) * NN;

    for (int dz = 0; dz < DD; dz++) {
        const int p0 = dz % 3, p1 = (dz + 1) % 3, p2 = (dz + 2) % 3;
#pragma unroll
        for (int r = 0; r < 8; r++) {
            int hl = hl0 + r * 4;
            float a = bb;
#pragma unroll
            for (int kh = 0; kh < 3; kh++)
#pragma unroll
                for (int kw = 0; kw < 3; kw++) {
                    a += s[p0][hl + kh][w + kw] * wt[0 * 9 + kh * 3 + kw];
                    a += s[p1][hl + kh][w + kw] * wt[1 * 9 + kh * 3 + kw];
                    a += s[p2][hl + kh][w + kw] * wt[2 * 9 + kh * 3 + kw];
                }
            outp[(size_t)dz * (HH * WW) + (h0 + hl) * WW + w] = a;
        }
        __syncthreads();
        if (dz < DD - 1) loadplane(dz + 2, p0);
        __syncthreads();
    }
}

// ============================================================================
// Kernel 4 (HMMA): h_unnorm partials = sum_n x * AB_unnorm
// BM=64(c), BN=64(s), BK=32. Register-prefetch double buffer. Full batch.
// ============================================================================
__global__ void __launch_bounds__(256) hgemm_mma_kernel(const float* __restrict__ x)
{
    __shared__ __align__(16) uint16_t As_hi[64 * A_STRIDE];
    __shared__ __align__(16) uint16_t As_lo[64 * A_STRIDE];
    __shared__ __align__(16) uint16_t Bs_hi[64 * HB_STRIDE];
    __shared__ __align__(16) uint16_t Bs_lo[64 * HB_STRIDE];

    const int c0 = blockIdx.x * 64;          // fastest -> L2 sharing of AB tile
    const int ks = blockIdx.y;               // 0..63
    const int b  = blockIdx.z;
    const int nbase = ks * (NN / KSPLIT_H);  // 1024 chunk
    const int tid  = threadIdx.x;
    const int wid  = tid >> 5;
    const int lane = tid & 31;
    const int wm = wid >> 2;
    const int wn = wid & 3;

    const float* xb = x + ((size_t)(b * CC + c0)) * NN;
    const float* ab = g_ab + (size_t)b * SS * NN;
    const uint32_t as_hi = smem_u32(As_hi), as_lo = smem_u32(As_lo);
    const uint32_t bs_hi = smem_u32(Bs_hi), bs_lo = smem_u32(Bs_lo);

    const int lr = tid >> 3;            // 0..31
    const int lk = (tid & 7) << 2;      // 0..28

    float acc[2][2][4];
#pragma unroll
    for (int i = 0; i < 2; i++)
#pragma unroll
        for (int j = 0; j < 2; j++)
#pragma unroll
            for (int q = 0; q < 4; q++) acc[i][j][q] = 0.f;

    float4 rx[2], rab[2];
    rx[0]  = *(const float4*)(xb + (size_t)lr * NN + nbase + lk);
    rx[1]  = *(const float4*)(xb + (size_t)(lr + 32) * NN + nbase + lk);
    rab[0] = *(const float4*)(ab + (size_t)lr * NN + nbase + lk);
    rab[1] = *(const float4*)(ab + (size_t)(lr + 32) * NN + nbase + lk);

    for (int kc = 0; kc < NN / KSPLIT_H; kc += 32) {
#pragma unroll
        for (int r = 0; r < 2; r++) {
            float4 v = rx[r];
            uint32_t h01, l01, h23, l23;
            split2(v.x, v.y, h01, l01);
            split2(v.z, v.w, h23, l23);
            int off = (lr + r * 32) * A_STRIDE + lk;
            *(uint2*)(As_hi + off) = make_uint2(h01, h23);
            *(uint2*)(As_lo + off) = make_uint2(l01, l23);
        }
#pragma unroll
        for (int r = 0; r < 2; r++) {
            float4 v = rab[r];
            uint32_t h01, l01, h23, l23;
            split2(v.x, v.y, h01, l01);
            split2(v.z, v.w, h23, l23);
            int off = (lr + r * 32) * HB_STRIDE + lk;
            *(uint2*)(Bs_hi + off) = make_uint2(h01, h23);
            *(uint2*)(Bs_lo + off) = make_uint2(l01, l23);
        }
        __syncthreads();

        if (kc + 32 < NN / KSPLIT_H) {
            const int nb2 = nbase + kc + 32;
            rx[0]  = *(const float4*)(xb + (size_t)lr * NN + nb2 + lk);
            rx[1]  = *(const float4*)(xb + (size_t)(lr + 32) * NN + nb2 + lk);
            rab[0] = *(const float4*)(ab + (size_t)lr * NN + nb2 + lk);
            rab[1] = *(const float4*)(ab + (size_t)(lr + 32) * NN + nb2 + lk);
        }

#pragma unroll
        for (int kq = 0; kq < 2; kq++) {
            uint32_t a_hi[2][4], a_lo[2][4];
            const int arow = lane & 15;
            const int acol = (lane >> 4) << 3;
#pragma unroll
            for (int mi = 0; mi < 2; mi++) {
                uint32_t off = (uint32_t)((wm * 32 + mi * 16 + arow) * A_STRIDE
                                          + kq * 16 + acol) * 2;
                ldsm_x4(a_hi[mi], as_hi + off);
                ldsm_x4(a_lo[mi], as_lo + off);
            }
            uint32_t b_hi[2][2], b_lo[2][2];
            const int l = lane & 15;
            const int srow = l & 7;
            const int koff = (l >> 3) << 3;
#pragma unroll
            for (int ni = 0; ni < 2; ni++) {
                uint32_t off = (uint32_t)((wn * 16 + ni * 8 + srow) * HB_STRIDE
                                          + kq * 16 + koff) * 2;
                ldsm_x2(b_hi[ni], bs_hi + off);
                ldsm_x2(b_lo[ni], bs_lo + off);
            }
#pragma unroll
            for (int mi = 0; mi < 2; mi++)
#pragma unroll
                for (int ni = 0; ni < 2; ni++) {
                    mma_bf16(acc[mi][ni], a_hi[mi], b_hi[ni]);
                    mma_bf16(acc[mi][ni], a_hi[mi], b_lo[ni]);
                    mma_bf16(acc[mi][ni], a_lo[mi], b_hi[ni]);
                }
        }
        __syncthreads();
    }

    float* dst = g_hpart + (size_t)ks * (BB * CC * SS);
    const int qrow = lane >> 2;
    const int qcol = (lane & 3) << 1;
#pragma unroll
    for (int mi = 0; mi < 2; mi++) {
        int cA = c0 + wm * 32 + mi * 16 + qrow;
#pragma unroll
        for (int ni = 0; ni < 2; ni++) {
            int sA = wn * 16 + ni * 8 + qcol;
            float* pA = dst + ((size_t)(b * CC + cA)) * SS + sA;
            float* pB = dst + ((size_t)(b * CC + cA + 8)) * SS + sA;
            *(float2*)pA = make_float2(acc[mi][ni][0], acc[mi][ni][1]);
            *(float2*)pB = make_float2(acc[mi][ni][2], acc[mi][ni][3]);
        }
    }
}

// reduction of split-K partials + deferred softmax normalization
__global__ void __launch_bounds__(256) hreduce_kernel()
{
    int i = blockIdx.x * 256 + threadIdx.x;   // ((b*CC+c)*SS+s) < 65536
    int b = i >> 14;
    int s = i & 63;
    const float* ps = &g_psum[(b * SS + s) * 2];
    float inv = 1.f / (ps[0] + ps[1]);
    float sum = 0.f;
#pragma unroll
    for (int ks = 0; ks < KSPLIT_H; ks++)
        sum += g_hpart[(size_t)ks * (BB * CC * SS) + i];
    g_h[i] = sum * inv;
}

// ============================================================================
// Kernel 5: hz = W_hz @ h + b_hz ; h3 = h2*silu(z) + h2*Dp
// ============================================================================
__global__ void __launch_bounds__(256) e1_kernel(
    const float* __restrict__ Whz, const float* __restrict__ bhz,
    const float* __restrict__ Dp)
{
    const int b = blockIdx.y;
    const int o = blockIdx.x * 4 + (threadIdx.x >> 6);
    const int s_ = threadIdx.x & 63;
    const float* hb = g_h + (size_t)b * CC * SS;
    const float* w1 = Whz + (size_t)o * 256;
    const float* w2 = Whz + (size_t)(o + 256) * 256;
    float a1 = bhz[o], a2 = bhz[o + 256];
    for (int c = 0; c < 256; c++) {
        float hv = hb[c * 64 + s_];
        a1 += w1[c] * hv;
        a2 += w2[c] * hv;
    }
    float sig = 1.f / (1.f + __expf(-a2));
    g_h3[((size_t)b * CC + o) * SS + s_] = a1 * (a2 * sig) + a1 * Dp[0];
}

// Kernel 6: h4 = W_out @ h3 + b_out ; write to scratch + output tail
__global__ void __launch_bounds__(256) e2_kernel(
    const float* __restrict__ Wout, const float* __restrict__ bout,
    float* __restrict__ out)
{
    const int b = blockIdx.y;
    const int o = blockIdx.x * 4 + (threadIdx.x >> 6);
    const int s_ = threadIdx.x & 63;
    const float* hb = g_h3 + (size_t)b * CC * SS;
    const float* w1 = Wout + (size_t)o * 256;
    float acc = bout[o];
    for (int c = 0; c < 256; c++)
        acc += w1[c] * hb[c * 64 + s_];
    size_t idx = ((size_t)b * CC + o) * SS + s_;
    g_h4[idx] = acc;
    out[YSIZE + idx] = acc;
}

// ============================================================================
// Kernel 7 (HMMA): y[b,c,n] = sum_s h4[b,c,s] * C_[b,s,n]
// ============================================================================
__global__ void __launch_bounds__(256) ygemm_mma_kernel(float* __restrict__ y)
{
    __shared__ __align__(16) uint16_t As_hi[64 * A_STRIDE];
    __shared__ __align__(16) uint16_t As_lo[64 * A_STRIDE];
    __shared__ __align__(16) uint16_t Bs_hi[32 * B_STRIDE];
    __shared__ __align__(16) uint16_t Bs_lo[32 * B_STRIDE];

    const int m0 = blockIdx.x * 64;     // fastest -> L2 sharing of C_ tile
    const int n0 = blockIdx.y * 128;
    const int b  = blockIdx.z;
    const int tid  = threadIdx.x;
    const int wid  = tid >> 5;
    const int lane = tid & 31;
    const int wm = wid >> 2;
    const int wn = wid & 3;

    const float* h4b = g_h4 + (size_t)b * CC * SS;
    const float* cp  = g_c + (size_t)b * SS * NN;
    const uint32_t as_hi = smem_u32(As_hi), as_lo = smem_u32(As_lo);
    const uint32_t bs_hi = smem_u32(Bs_hi), bs_lo = smem_u32(Bs_lo);

    float acc[2][4][4];
#pragma unroll
    for (int i = 0; i < 2; i++)
#pragma unroll
        for (int j = 0; j < 4; j++)
#pragma unroll
            for (int q = 0; q < 4; q++) acc[i][j][q] = 0.f;

    for (int k0 = 0; k0 < 64; k0 += 32) {
#pragma unroll
        for (int r = 0; r < 2; r++) {
            int f = tid + r * 256;
            int m = f >> 3, k = (f & 7) << 2;
            float4 v = *(const float4*)(h4b + (size_t)(m0 + m) * SS + k0 + k);
            uint32_t h01, l01, h23, l23;
            split2(v.x, v.y, h01, l01);
            split2(v.z, v.w, h23, l23);
            int off = m * A_STRIDE + k;
            *(uint2*)(As_hi + off) = make_uint2(h01, h23);
            *(uint2*)(As_lo + off) = make_uint2(l01, l23);
        }
#pragma unroll
        for (int r = 0; r < 4; r++) {
            int f = tid + r * 256;
            int krow = f >> 5, n = (f & 31) << 2;
            float4 v = *(const float4*)(cp + (size_t)(k0 + krow) * NN + n0 + n);
            uint32_t h01, l01, h23, l23;
            split2(v.x, v.y, h01, l01);
            split2(v.z, v.w, h23, l23);
            int off = krow * B_STRIDE + n;
            *(uint2*)(Bs_hi + off) = make_uint2(h01, h23);
            *(uint2*)(Bs_lo + off) = make_uint2(l01, l23);
        }
        __syncthreads();

#pragma unroll
        for (int ks = 0; ks < 2; ks++) {
            uint32_t a_hi[2][4], a_lo[2][4];
            const int arow = lane & 15;
            const int acol = (lane >> 4) << 3;
#pragma unroll
            for (int mi = 0; mi < 2; mi++) {
                uint32_t off = (uint32_t)((wm * 32 + mi * 16 + arow) * A_STRIDE
                                          + ks * 16 + acol) * 2;
                ldsm_x4(a_hi[mi], as_hi + off);
                ldsm_x4(a_lo[mi], as_lo + off);
            }
            uint32_t b_hi[4][2], b_lo[4][2];
            const int brow = lane & 15;
#pragma unroll
            for (int ni = 0; ni < 4; ni++) {
                uint32_t off = (uint32_t)((ks * 16 + brow) * B_STRIDE
                                          + wn * 32 + ni * 8) * 2;
                ldsm_x2_t(b_hi[ni], bs_hi + off);
                ldsm_x2_t(b_lo[ni], bs_lo + off);
            }
#pragma unroll
            for (int mi = 0; mi < 2; mi++)
#pragma unroll
                for (int ni = 0; ni < 4; ni++) {
                    mma_bf16(acc[mi][ni], a_hi[mi], b_hi[ni]);
                    mma_bf16(acc[mi][ni], a_hi[mi], b_lo[ni]);
                    mma_bf16(acc[mi][ni], a_lo[mi], b_hi[ni]);
                }
        }
        __syncthreads();
    }

    const int qrow = lane >> 2;
    const int qcol = (lane & 3) << 1;
#pragma unroll
    for (int mi = 0; mi < 2; mi++) {
        int mA = m0 + wm * 32 + mi * 16 + qrow;
        float* rowA = y + ((size_t)(b * CC + mA)) * NN + n0;
        float* rowB = rowA + (size_t)8 * NN;
#pragma unroll
        for (int ni = 0; ni < 4; ni++) {
            int n = wn * 32 + ni * 8 + qcol;
            *(float2*)(rowA + n) = make_float2(acc[mi][ni][0], acc[mi][ni][1]);
            *(float2*)(rowB + n) = make_float2(acc[mi][ni][2], acc[mi][ni][3]);
        }
    }
}

// ============================================================================
extern "C" void kernel_launch(void* const* d_in, const int* in_sizes, int n_in,
                              void* d_out, int out_size)
{
    const float* x      = (const float*)d_in[0];
    const float* W_bcdt = (const float*)d_in[1];
    const float* b_bcdt = (const float*)d_in[2];
    const float* W_dw   = (const float*)d_in[3];
    const float* b_dw   = (const float*)d_in[4];
    const float* W_hz   = (const float*)d_in[5];
    const float* b_hz   = (const float*)d_in[6];
    const float* W_out  = (const float*)d_in[7];
    const float* b_out  = (const float*)d_in[8];
    // d_in[9] = A : unused (softmax shift invariance along the reduced axis)
    const float* Dp     = (const float*)d_in[10];
    float* out = (float*)d_out;

    // side stream + fork/join events (created once; no device allocs)
    static cudaStream_t s1 = nullptr;
    static cudaEvent_t ev_ga = nullptr, ev_c = nullptr;
    if (!s1) {
        cudaStreamCreateWithFlags(&s1, cudaStreamNonBlocking);
        cudaEventCreateWithFlags(&ev_ga, cudaEventDisableTiming);
        cudaEventCreateWithFlags(&ev_c, cudaEventDisableTiming);
    }

    // Critical path (stream0): gemm1 for B_ + dt rows only (m-tiles 0 and 128),
    // then conv_ab -> hgemm -> hreduce -> e1 -> e2.
    gemm1_mma_kernel<<<dim3(2, NN / 128, BB), 256>>>(x, W_bcdt, b_bcdt, 0, 128);
    cudaEventRecord(ev_ga, 0);

    // Side chain (s1): gemm1 for C_ rows (m-tile 64) then conv_c — fully
    // overlapped with conv_ab + hgemm on stream0.
    cudaStreamWaitEvent(s1, ev_ga, 0);
    gemm1_mma_kernel<<<dim3(1, NN / 128, BB), 256, 0, s1>>>(x, W_bcdt, b_bcdt, 64, 0);
    conv_c_kernel<<<dim3(2, SS, BB), 256, 0, s1>>>(W_dw, b_dw);
    cudaEventRecord(ev_c, s1);

    conv_ab_kernel<<<dim3(2, SS, BB), 256>>>(W_dw, b_dw);
    hgemm_mma_kernel<<<dim3(4, KSPLIT_H, BB), 256>>>(x);
    hreduce_kernel<<<256, 256>>>();
    e1_kernel<<<dim3(64, BB), 256>>>(W_hz, b_hz, Dp);
    e2_kernel<<<dim3(64, BB), 256>>>(W_out, b_out, out);

    cudaStreamWaitEvent(0, ev_c, 0);
    ygemm_mma_kernel<<<dim3(4, NN / 128, BB), 256>>>(out);
}

// round 12
// speedup vs baseline: 1.1842x; 1.0455x over previous
#include <cuda_runtime.h>
#include <cuda_bf16.h>
#include <cstdint>
#include <cstddef>

// Problem constants
#define BB   4
#define CC   256      // D_MODEL = D_INNER
#define SS   64
#define DD   16
#define HH   64
#define WW   64
#define NN   65536    // D*H*W
#define O3S  192      // 3*S
#define KSPLIT_H 64   // split-K factor for h-GEMM

static const size_t YSIZE = (size_t)BB * CC * NN;   // 67108864

// ---- static scratch (no runtime allocation allowed) ----
__device__ float g_bcdt[(size_t)BB * O3S * NN];   // GEMM1 output (pre-conv)
__device__ float g_ab[(size_t)BB * SS * NN];      // AB_unnorm = exp(conv dt)*conv B_
__device__ float g_c [(size_t)BB * SS * NN];      // conv C_ channels
__device__ float g_hpart[(size_t)KSPLIT_H * BB * CC * SS];
__device__ float g_psum[BB * SS * 2];             // per-h-half exp-sums
__device__ float g_h [BB * CC * SS];
__device__ float g_h3[BB * CC * SS];
__device__ float g_h4[BB * CC * SS];

// ============================================================================
// helpers
// ============================================================================
__device__ __forceinline__ uint32_t smem_u32(const void* p) {
    uint32_t a;
    asm("{ .reg .u64 t; cvta.to.shared.u64 t, %1; cvt.u32.u64 %0, t; }" : "=r"(a) : "l"(p));
    return a;
}
__device__ __forceinline__ void ldsm_x4(uint32_t* r, uint32_t addr) {
    asm volatile("ldmatrix.sync.aligned.m8n8.x4.shared.b16 {%0,%1,%2,%3}, [%4];"
        : "=r"(r[0]), "=r"(r[1]), "=r"(r[2]), "=r"(r[3]) : "r"(addr));
}
__device__ __forceinline__ void ldsm_x2(uint32_t* r, uint32_t addr) {
    asm volatile("ldmatrix.sync.aligned.m8n8.x2.shared.b16 {%0,%1}, [%2];"
        : "=r"(r[0]), "=r"(r[1]) : "r"(addr));
}
__device__ __forceinline__ void ldsm_x2_t(uint32_t* r, uint32_t addr) {
    asm volatile("ldmatrix.sync.aligned.m8n8.x2.trans.shared.b16 {%0,%1}, [%2];"
        : "=r"(r[0]), "=r"(r[1]) : "r"(addr));
}
__device__ __forceinline__ void mma_bf16(float* c, const uint32_t* a, const uint32_t* b) {
    asm volatile(
        "mma.sync.aligned.m16n8k16.row.col.f32.bf16.bf16.f32 "
        "{%0,%1,%2,%3}, {%4,%5,%6,%7}, {%8,%9}, {%0,%1,%2,%3};"
        : "+f"(c[0]), "+f"(c[1]), "+f"(c[2]), "+f"(c[3])
        : "r"(a[0]), "r"(a[1]), "r"(a[2]), "r"(a[3]), "r"(b[0]), "r"(b[1]));
}
__device__ __forceinline__ void split2(float v0, float v1, uint32_t& hi, uint32_t& lo) {
    __nv_bfloat16 h0 = __float2bfloat16(v0), h1 = __float2bfloat16(v1);
    float r0 = v0 - __bfloat162float(h0), r1 = v1 - __bfloat162float(h1);
    __nv_bfloat162 hh = __halves2bfloat162(h0, h1);
    __nv_bfloat162 ll = __floats2bfloat162_rn(r0, r1);
    hi = *(uint32_t*)&hh; lo = *(uint32_t*)&ll;
}
// FMA-pipe exp (poly 2^f on [-0.5,0.5], ~2e-9 rel err), clamped both sides
__device__ __forceinline__ float fexp(float x) {
    float t = fminf(fmaxf(x * 1.4426950408889634f, -125.0f), 125.0f);
    float n = rintf(t);
    float f = t - n;
    float p = 1.5403530393381609e-4f;
    p = fmaf(p, f, 1.3333558146428443e-3f);
    p = fmaf(p, f, 9.618129107628477e-3f);
    p = fmaf(p, f, 5.550410866482158e-2f);
    p = fmaf(p, f, 2.402265069591999e-1f);
    p = fmaf(p, f, 6.931471805599453e-1f);
    p = fmaf(p, f, 1.0f);
    return __int_as_float(((int)n + 127) << 23) * p;
}

#define A_STRIDE 40    // halves per 32-k row (32 + 8 pad)
#define B_STRIDE 136   // halves per 128-n row (128 + 8 pad)
#define HB_STRIDE 40

// conv smem geometry: 34 rows x 68 floats (16B-aligned rows), 3 planes
#define CV_STRIDE 68
#define CV_PLANE  (34 * CV_STRIDE)
#define CVAB_SMEM (2 * 3 * CV_PLANE * 4)   // 55488 bytes (B + D arrays)

// ============================================================================
// Kernel 1 (HMMA): BCdt = W_bcdt(192x256) @ x(b,256,N) + b_bcdt
// BM=64, BN=128, BK=32. x tile register-prefetched.
// ============================================================================
__global__ void __launch_bounds__(256) gemm1_mma_kernel(
    const float* __restrict__ x, const float* __restrict__ W,
    const float* __restrict__ bias)
{
    __shared__ __align__(16) uint16_t As_hi[64 * A_STRIDE];
    __shared__ __align__(16) uint16_t As_lo[64 * A_STRIDE];
    __shared__ __align__(16) uint16_t Bs_hi[32 * B_STRIDE];
    __shared__ __align__(16) uint16_t Bs_lo[32 * B_STRIDE];

    const int m0 = blockIdx.x * 64;     // fastest -> L2 sharing of x tile
    const int n0 = blockIdx.y * 128;
    const int b  = blockIdx.z;
    const int tid  = threadIdx.x;
    const int wid  = tid >> 5;
    const int lane = tid & 31;
    const int wm = wid >> 2;
    const int wn = wid & 3;

    const float* xb = x + (size_t)b * CC * NN;
    const uint32_t as_hi = smem_u32(As_hi), as_lo = smem_u32(As_lo);
    const uint32_t bs_hi = smem_u32(Bs_hi), bs_lo = smem_u32(Bs_lo);

    const int krow0 = tid >> 5;
    const int nloc  = (tid & 31) << 2;

    float acc[2][4][4];
#pragma unroll
    for (int i = 0; i < 2; i++)
#pragma unroll
        for (int j = 0; j < 4; j++)
#pragma unroll
            for (int q = 0; q < 4; q++) acc[i][j][q] = 0.f;

    float4 rbx[4];
#pragma unroll
    for (int r = 0; r < 4; r++)
        rbx[r] = *(const float4*)(xb + (size_t)(krow0 + r * 8) * NN + n0 + nloc);

    for (int k0 = 0; k0 < 256; k0 += 32) {
#pragma unroll
        for (int r = 0; r < 2; r++) {
            int f = tid + r * 256;
            int m = f >> 3, k = (f & 7) << 2;
            float4 v = *(const float4*)(W + (size_t)(m0 + m) * 256 + k0 + k);
            uint32_t h01, l01, h23, l23;
            split2(v.x, v.y, h01, l01);
            split2(v.z, v.w, h23, l23);
            int off = m * A_STRIDE + k;
            *(uint2*)(As_hi + off) = make_uint2(h01, h23);
            *(uint2*)(As_lo + off) = make_uint2(l01, l23);
        }
#pragma unroll
        for (int r = 0; r < 4; r++) {
            float4 v = rbx[r];
            uint32_t h01, l01, h23, l23;
            split2(v.x, v.y, h01, l01);
            split2(v.z, v.w, h23, l23);
            int off = (krow0 + r * 8) * B_STRIDE + nloc;
            *(uint2*)(Bs_hi + off) = make_uint2(h01, h23);
            *(uint2*)(Bs_lo + off) = make_uint2(l01, l23);
        }
        __syncthreads();

        if (k0 + 32 < 256) {
#pragma unroll
            for (int r = 0; r < 4; r++)
                rbx[r] = *(const float4*)(xb + (size_t)(k0 + 32 + krow0 + r * 8) * NN + n0 + nloc);
        }

#pragma unroll
        for (int ks = 0; ks < 2; ks++) {
            uint32_t a_hi[2][4], a_lo[2][4];
            const int arow = lane & 15;
            const int acol = (lane >> 4) << 3;
#pragma unroll
            for (int mi = 0; mi < 2; mi++) {
                uint32_t off = (uint32_t)((wm * 32 + mi * 16 + arow) * A_STRIDE
                                          + ks * 16 + acol) * 2;
                ldsm_x4(a_hi[mi], as_hi + off);
                ldsm_x4(a_lo[mi], as_lo + off);
            }
            uint32_t b_hi[4][2], b_lo[4][2];
            const int brow = lane & 15;
#pragma unroll
            for (int ni = 0; ni < 4; ni++) {
                uint32_t off = (uint32_t)((ks * 16 + brow) * B_STRIDE
                                          + wn * 32 + ni * 8) * 2;
                ldsm_x2_t(b_hi[ni], bs_hi + off);
                ldsm_x2_t(b_lo[ni], bs_lo + off);
            }
#pragma unroll
            for (int mi = 0; mi < 2; mi++)
#pragma unroll
                for (int ni = 0; ni < 4; ni++) {
                    mma_bf16(acc[mi][ni], a_hi[mi], b_hi[ni]);
                    mma_bf16(acc[mi][ni], a_hi[mi], b_lo[ni]);
                    mma_bf16(acc[mi][ni], a_lo[mi], b_hi[ni]);
                }
        }
        __syncthreads();
    }

    const int qrow = lane >> 2;
    const int qcol = (lane & 3) << 1;
#pragma unroll
    for (int mi = 0; mi < 2; mi++) {
        int mA = m0 + wm * 32 + mi * 16 + qrow;
        float bA = bias[mA], bB = bias[mA + 8];
        float* rowA = g_bcdt + ((size_t)(b * O3S + mA)) * NN + n0;
        float* rowB = rowA + (size_t)8 * NN;
#pragma unroll
        for (int ni = 0; ni < 4; ni++) {
            int n = wn * 32 + ni * 8 + qcol;
            *(float2*)(rowA + n) = make_float2(acc[mi][ni][0] + bA, acc[mi][ni][1] + bA);
            *(float2*)(rowB + n) = make_float2(acc[mi][ni][2] + bB, acc[mi][ni][3] + bB);
        }
    }
}

// ============================================================================
// Kernel 2a: FUSED depthwise conv (B_ + dt) + exp + multiply, VECTORIZED.
// Thread = 4 w x 2 adjacent h rows. Per (plane,ch): 4 input rows x 2 LDS.128.
// Rolling 3-plane smem over dz. Writes AB_unnorm + per-(b,s,hhalf) exp-sums.
// ============================================================================
__global__ void __launch_bounds__(256) conv_ab_kernel(
    const float* __restrict__ wdw, const float* __restrict__ bdw)
{
    extern __shared__ __align__(16) float cvs[];
    float* sB = cvs;                    // [3][34][68]
    float* sD = cvs + 3 * CV_PLANE;     // [3][34][68]
    __shared__ float wB[27], wD[27];
    __shared__ float red[8];

    const int hhalf = blockIdx.x;
    const int s_ = blockIdx.y;
    const int b  = blockIdx.z;
    const int h0 = hhalf * 32;
    const int tid = threadIdx.x;
    const int chB = s_;
    const int chD = 128 + s_;

    const float* baseB = g_bcdt + ((size_t)(b * O3S + chB)) * NN;
    const float* baseD = g_bcdt + ((size_t)(b * O3S + chD)) * NN;

    if (tid < 27) wB[tid] = wdw[chB * 27 + tid];
    else if (tid >= 32 && tid < 59) wD[tid - 32] = wdw[chD * 27 + (tid - 32)];
    const float biasB = bdw[chB];
    const float biasD = bdw[chD];

    auto loadplane = [&](int z, int slot) {
        for (int idx = tid; idx < 34 * 66; idx += 256) {
            int ih = idx / 66, iw = idx % 66;
            int h = h0 - 1 + ih, w = iw - 1;
            bool ok = ((unsigned)z < (unsigned)DD) && ((unsigned)h < (unsigned)HH)
                      && ((unsigned)w < (unsigned)WW);
            size_t g = (size_t)z * (HH * WW) + (size_t)h * WW + w;
            sB[slot * CV_PLANE + ih * CV_STRIDE + iw] = ok ? baseB[g] : 0.f;
            sD[slot * CV_PLANE + ih * CV_STRIDE + iw] = ok ? baseD[g] : 0.f;
        }
    };
    loadplane(-1, 0);
    loadplane(0, 1);
    loadplane(1, 2);
    __syncthreads();

    const int w4 = (tid & 15) * 4;      // 0..60
    const int hl = (tid >> 4) * 2;      // 0,2,..,30 (output rows hl, hl+1)
    float* abp = g_ab + ((size_t)(b * SS + s_)) * NN;
    float lsum = 0.f;

    for (int dz = 0; dz < DD; dz++) {
        float aB0[4], aB1[4], aD0[4], aD1[4];
#pragma unroll
        for (int j = 0; j < 4; j++) {
            aB0[j] = biasB; aB1[j] = biasB;
            aD0[j] = biasD; aD1[j] = biasD;
        }
#pragma unroll
        for (int kd = 0; kd < 3; kd++) {
            const int pl = (dz + kd) % 3;
            const float* bb = sB + pl * CV_PLANE;
            const float* db = sD + pl * CV_PLANE;
#pragma unroll
            for (int q = 0; q < 4; q++) {      // input rows hl+q
                const float* rowb = bb + (hl + q) * CV_STRIDE + w4;
                const float* rowd = db + (hl + q) * CV_STRIDE + w4;
                float4 u0 = *(const float4*)(rowb);
                float4 u1 = *(const float4*)(rowb + 4);
                float4 t0 = *(const float4*)(rowd);
                float4 t1 = *(const float4*)(rowd + 4);
                float vB[8] = {u0.x, u0.y, u0.z, u0.w, u1.x, u1.y, u1.z, u1.w};
                float vD[8] = {t0.x, t0.y, t0.z, t0.w, t1.x, t1.y, t1.z, t1.w};
                if (q < 3) {
#pragma unroll
                    for (int kw = 0; kw < 3; kw++) {
                        float wtb = wB[kd * 9 + q * 3 + kw];
                        float wtd = wD[kd * 9 + q * 3 + kw];
#pragma unroll
                        for (int j = 0; j < 4; j++) {
                            aB0[j] = fmaf(vB[j + kw], wtb, aB0[j]);
                            aD0[j] = fmaf(vD[j + kw], wtd, aD0[j]);
                        }
                    }
                }
                if (q >= 1) {
#pragma unroll
                    for (int kw = 0; kw < 3; kw++) {
                        float wtb = wB[kd * 9 + (q - 1) * 3 + kw];
                        float wtd = wD[kd * 9 + (q - 1) * 3 + kw];
#pragma unroll
                        for (int j = 0; j < 4; j++) {
                            aB1[j] = fmaf(vB[j + kw], wtb, aB1[j]);
                            aD1[j] = fmaf(vD[j + kw], wtd, aD1[j]);
                        }
                    }
                }
            }
        }
        float e0[4], e1[4];
#pragma unroll
        for (int j = 0; j < 4; j++) {
            e0[j] = fexp(aD0[j]);
            e1[j] = fexp(aD1[j]);
            lsum += e0[j] + e1[j];
        }
        float* o0 = abp + (size_t)dz * (HH * WW) + (h0 + hl) * WW + w4;
        *(float4*)(o0)      = make_float4(e0[0] * aB0[0], e0[1] * aB0[1],
                                          e0[2] * aB0[2], e0[3] * aB0[3]);
        *(float4*)(o0 + WW) = make_float4(e1[0] * aB1[0], e1[1] * aB1[1],
                                          e1[2] * aB1[2], e1[3] * aB1[3]);
        __syncthreads();
        if (dz < DD - 1) loadplane(dz + 2, dz % 3);
        __syncthreads();
    }

    const int lane = tid & 31, warp = tid >> 5;
#pragma unroll
    for (int o = 16; o > 0; o >>= 1) lsum += __shfl_xor_sync(0xffffffffu, lsum, o);
    if (lane == 0) red[warp] = lsum;
    __syncthreads();
    if (tid == 0) {
        float v = red[0] + red[1] + red[2] + red[3] + red[4] + red[5] + red[6] + red[7];
        g_psum[(b * SS + s_) * 2 + hhalf] = v;
    }
}

// ============================================================================
// Kernel 2b: depthwise conv for C_ channels (64..127), VECTORIZED, rolling dz.
// ============================================================================
__global__ void __launch_bounds__(256) conv_c_kernel(
    const float* __restrict__ wdw, const float* __restrict__ bdw)
{
    __shared__ __align__(16) float s[3 * CV_PLANE];
    __shared__ float wt[27];

    const int hhalf = blockIdx.x;
    const int s_ = blockIdx.y;
    const int b  = blockIdx.z;
    const int h0 = hhalf * 32;
    const int tid = threadIdx.x;
    const int ch = 64 + s_;

    const float* base = g_bcdt + ((size_t)(b * O3S + ch)) * NN;
    if (tid < 27) wt[tid] = wdw[ch * 27 + tid];
    const float bbv = bdw[ch];

    auto loadplane = [&](int z, int slot) {
        for (int idx = tid; idx < 34 * 66; idx += 256) {
            int ih = idx / 66, iw = idx % 66;
            int h = h0 - 1 + ih, w = iw - 1;
            bool ok = ((unsigned)z < (unsigned)DD) && ((unsigned)h < (unsigned)HH)
                      && ((unsigned)w < (unsigned)WW);
            size_t g = (size_t)z * (HH * WW) + (size_t)h * WW + w;
            s[slot * CV_PLANE + ih * CV_STRIDE + iw] = ok ? base[g] : 0.f;
        }
    };
    loadplane(-1, 0);
    loadplane(0, 1);
    loadplane(1, 2);
    __syncthreads();

    const int w4 = (tid & 15) * 4;
    const int hl = (tid >> 4) * 2;
    float* outp = g_c + ((size_t)(b * SS + s_)) * NN;

    for (int dz = 0; dz < DD; dz++) {
        float a0[4], a1[4];
#pragma unroll
        for (int j = 0; j < 4; j++) { a0[j] = bbv; a1[j] = bbv; }
#pragma unroll
        for (int kd = 0; kd < 3; kd++) {
            const int pl = (dz + kd) % 3;
            const float* bb = s + pl * CV_PLANE;
#pragma unroll
            for (int q = 0; q < 4; q++) {
                const float* row = bb + (hl + q) * CV_STRIDE + w4;
                float4 u0 = *(const float4*)(row);
                float4 u1 = *(const float4*)(row + 4);
                float v[8] = {u0.x, u0.y, u0.z, u0.w, u1.x, u1.y, u1.z, u1.w};
                if (q < 3) {
#pragma unroll
                    for (int kw = 0; kw < 3; kw++) {
                        float wv = wt[kd * 9 + q * 3 + kw];
#pragma unroll
                        for (int j = 0; j < 4; j++)
                            a0[j] = fmaf(v[j + kw], wv, a0[j]);
                    }
                }
                if (q >= 1) {
#pragma unroll
                    for (int kw = 0; kw < 3; kw++) {
                        float wv = wt[kd * 9 + (q - 1) * 3 + kw];
#pragma unroll
                        for (int j = 0; j < 4; j++)
                            a1[j] = fmaf(v[j + kw], wv, a1[j]);
                    }
                }
            }
        }
        float* o0 = outp + (size_t)dz * (HH * WW) + (h0 + hl) * WW + w4;
        *(float4*)(o0)      = make_float4(a0[0], a0[1], a0[2], a0[3]);
        *(float4*)(o0 + WW) = make_float4(a1[0], a1[1], a1[2], a1[3]);
        __syncthreads();
        if (dz < DD - 1) loadplane(dz + 2, dz % 3);
        __syncthreads();
    }
}

// ============================================================================
// Kernel 4 (HMMA): h_unnorm partials = sum_n x * AB_unnorm
// BM=64(c), BN=64(s), BK=32. Register-prefetch double buffer.
// ============================================================================
__global__ void __launch_bounds__(256) hgemm_mma_kernel(const float* __restrict__ x)
{
    __shared__ __align__(16) uint16_t As_hi[64 * A_STRIDE];
    __shared__ __align__(16) uint16_t As_lo[64 * A_STRIDE];
    __shared__ __align__(16) uint16_t Bs_hi[64 * HB_STRIDE];
    __shared__ __align__(16) uint16_t Bs_lo[64 * HB_STRIDE];

    const int c0 = blockIdx.x * 64;          // fastest -> L2 sharing of AB tile
    const int ks = blockIdx.y;               // 0..63
    const int b  = blockIdx.z;
    const int nbase = ks * (NN / KSPLIT_H);  // 1024 chunk
    const int tid  = threadIdx.x;
    const int wid  = tid >> 5;
    const int lane = tid & 31;
    const int wm = wid >> 2;
    const int wn = wid & 3;

    const float* xb = x + ((size_t)(b * CC + c0)) * NN;
    const float* ab = g_ab + (size_t)b * SS * NN;
    const uint32_t as_hi = smem_u32(As_hi), as_lo = smem_u32(As_lo);
    const uint32_t bs_hi = smem_u32(Bs_hi), bs_lo = smem_u32(Bs_lo);

    const int lr = tid >> 3;            // 0..31
    const int lk = (tid & 7) << 2;      // 0..28

    float acc[2][2][4];
#pragma unroll
    for (int i = 0; i < 2; i++)
#pragma unroll
        for (int j = 0; j < 2; j++)
#pragma unroll
            for (int q = 0; q < 4; q++) acc[i][j][q] = 0.f;

    float4 rx[2], rab[2];
    rx[0]  = *(const float4*)(xb + (size_t)lr * NN + nbase + lk);
    rx[1]  = *(const float4*)(xb + (size_t)(lr + 32) * NN + nbase + lk);
    rab[0] = *(const float4*)(ab + (size_t)lr * NN + nbase + lk);
    rab[1] = *(const float4*)(ab + (size_t)(lr + 32) * NN + nbase + lk);

    for (int kc = 0; kc < NN / KSPLIT_H; kc += 32) {
#pragma unroll
        for (int r = 0; r < 2; r++) {
            float4 v = rx[r];
            uint32_t h01, l01, h23, l23;
            split2(v.x, v.y, h01, l01);
            split2(v.z, v.w, h23, l23);
            int off = (lr + r * 32) * A_STRIDE + lk;
            *(uint2*)(As_hi + off) = make_uint2(h01, h23);
            *(uint2*)(As_lo + off) = make_uint2(l01, l23);
        }
#pragma unroll
        for (int r = 0; r < 2; r++) {
            float4 v = rab[r];
            uint32_t h01, l01, h23, l23;
            split2(v.x, v.y, h01, l01);
            split2(v.z, v.w, h23, l23);
            int off = (lr + r * 32) * HB_STRIDE + lk;
            *(uint2*)(Bs_hi + off) = make_uint2(h01, h23);
            *(uint2*)(Bs_lo + off) = make_uint2(l01, l23);
        }
        __syncthreads();

        if (kc + 32 < NN / KSPLIT_H) {
            const int nb2 = nbase + kc + 32;
            rx[0]  = *(const float4*)(xb + (size_t)lr * NN + nb2 + lk);
            rx[1]  = *(const float4*)(xb + (size_t)(lr + 32) * NN + nb2 + lk);
            rab[0] = *(const float4*)(ab + (size_t)lr * NN + nb2 + lk);
            rab[1] = *(const float4*)(ab + (size_t)(lr + 32) * NN + nb2 + lk);
        }

#pragma unroll
        for (int kq = 0; kq < 2; kq++) {
            uint32_t a_hi[2][4], a_lo[2][4];
            const int arow = lane & 15;
            const int acol = (lane >> 4) << 3;
#pragma unroll
            for (int mi = 0; mi < 2; mi++) {
                uint32_t off = (uint32_t)((wm * 32 + mi * 16 + arow) * A_STRIDE
                                          + kq * 16 + acol) * 2;
                ldsm_x4(a_hi[mi], as_hi + off);
                ldsm_x4(a_lo[mi], as_lo + off);
            }
            uint32_t b_hi[2][2], b_lo[2][2];
            const int l = lane & 15;
            const int srow = l & 7;
            const int koff = (l >> 3) << 3;
#pragma unroll
            for (int ni = 0; ni < 2; ni++) {
                uint32_t off = (uint32_t)((wn * 16 + ni * 8 + srow) * HB_STRIDE
                                          + kq * 16 + koff) * 2;
                ldsm_x2(b_hi[ni], bs_hi + off);
                ldsm_x2(b_lo[ni], bs_lo + off);
            }
#pragma unroll
            for (int mi = 0; mi < 2; mi++)
#pragma unroll
                for (int ni = 0; ni < 2; ni++) {
                    mma_bf16(acc[mi][ni], a_hi[mi], b_hi[ni]);
                    mma_bf16(acc[mi][ni], a_hi[mi], b_lo[ni]);
                    mma_bf16(acc[mi][ni], a_lo[mi], b_hi[ni]);
                }
        }
        __syncthreads();
    }

    float* dst = g_hpart + (size_t)ks * (BB * CC * SS);
    const int qrow = lane >> 2;
    const int qcol = (lane & 3) << 1;
#pragma unroll
    for (int mi = 0; mi < 2; mi++) {
        int cA = c0 + wm * 32 + mi * 16 + qrow;
#pragma unroll
        for (int ni = 0; ni < 2; ni++) {
            int sA = wn * 16 + ni * 8 + qcol;
            float* pA = dst + ((size_t)(b * CC + cA)) * SS + sA;
            float* pB = dst + ((size_t)(b * CC + cA + 8)) * SS + sA;
            *(float2*)pA = make_float2(acc[mi][ni][0], acc[mi][ni][1]);
            *(float2*)pB = make_float2(acc[mi][ni][2], acc[mi][ni][3]);
        }
    }
}

// reduction of split-K partials + deferred softmax normalization
__global__ void __launch_bounds__(256) hreduce_kernel()
{
    int i = blockIdx.x * 256 + threadIdx.x;   // ((b*CC+c)*SS+s) < 65536
    int b = i >> 14;
    int s = i & 63;
    const float* ps = &g_psum[(b * SS + s) * 2];
    float inv = 1.f / (ps[0] + ps[1]);
    float sum = 0.f;
#pragma unroll
    for (int ks = 0; ks < KSPLIT_H; ks++)
        sum += g_hpart[(size_t)ks * (BB * CC * SS) + i];
    g_h[i] = sum * inv;
}

// ============================================================================
// Kernel 5: hz = W_hz @ h + b_hz ; h3 = h2*silu(z) + h2*Dp
// ============================================================================
__global__ void __launch_bounds__(256) e1_kernel(
    const float* __restrict__ Whz, const float* __restrict__ bhz,
    const float* __restrict__ Dp)
{
    const int b = blockIdx.y;
    const int o = blockIdx.x * 4 + (threadIdx.x >> 6);
    const int s_ = threadIdx.x & 63;
    const float* hb = g_h + (size_t)b * CC * SS;
    const float* w1 = Whz + (size_t)o * 256;
    const float* w2 = Whz + (size_t)(o + 256) * 256;
    float a1 = bhz[o], a2 = bhz[o + 256];
    for (int c = 0; c < 256; c++) {
        float hv = hb[c * 64 + s_];
        a1 += w1[c] * hv;
        a2 += w2[c] * hv;
    }
    float sig = 1.f / (1.f + __expf(-a2));
    g_h3[((size_t)b * CC + o) * SS + s_] = a1 * (a2 * sig) + a1 * Dp[0];
}

// Kernel 6: h4 = W_out @ h3 + b_out ; write to scratch + output tail
__global__ void __launch_bounds__(256) e2_kernel(
    const float* __restrict__ Wout, const float* __restrict__ bout,
    float* __restrict__ out)
{
    const int b = blockIdx.y;
    const int o = blockIdx.x * 4 + (threadIdx.x >> 6);
    const int s_ = threadIdx.x & 63;
    const float* hb = g_h3 + (size_t)b * CC * SS;
    const float* w1 = Wout + (size_t)o * 256;
    float acc = bout[o];
    for (int c = 0; c < 256; c++)
        acc += w1[c] * hb[c * 64 + s_];
    size_t idx = ((size_t)b * CC + o) * SS + s_;
    g_h4[idx] = acc;
    out[YSIZE + idx] = acc;
}

// ============================================================================
// Kernel 7 (HMMA): y[b,c,n] = sum_s h4[b,c,s] * C_[b,s,n]
// ============================================================================
__global__ void __launch_bounds__(256) ygemm_mma_kernel(float* __restrict__ y)
{
    __shared__ __align__(16) uint16_t As_hi[64 * A_STRIDE];
    __shared__ __align__(16) uint16_t As_lo[64 * A_STRIDE];
    __shared__ __align__(16) uint16_t Bs_hi[32 * B_STRIDE];
    __shared__ __align__(16) uint16_t Bs_lo[32 * B_STRIDE];

    const int m0 = blockIdx.x * 64;     // fastest -> L2 sharing of C_ tile
    const int n0 = blockIdx.y * 128;
    const int b  = blockIdx.z;
    const int tid  = threadIdx.x;
    const int wid  = tid >> 5;
    const int lane = tid & 31;
    const int wm = wid >> 2;
    const int wn = wid & 3;

    const float* h4b = g_h4 + (size_t)b * CC * SS;
    const float* cp  = g_c + (size_t)b * SS * NN;
    const uint32_t as_hi = smem_u32(As_hi), as_lo = smem_u32(As_lo);
    const uint32_t bs_hi = smem_u32(Bs_hi), bs_lo = smem_u32(Bs_lo);

    float acc[2][4][4];
#pragma unroll
    for (int i = 0; i < 2; i++)
#pragma unroll
        for (int j = 0; j < 4; j++)
#pragma unroll
            for (int q = 0; q < 4; q++) acc[i][j][q] = 0.f;

    for (int k0 = 0; k0 < 64; k0 += 32) {
#pragma unroll
        for (int r = 0; r < 2; r++) {
            int f = tid + r * 256;
            int m = f >> 3, k = (f & 7) << 2;
            float4 v = *(const float4*)(h4b + (size_t)(m0 + m) * SS + k0 + k);
            uint32_t h01, l01, h23, l23;
            split2(v.x, v.y, h01, l01);
            split2(v.z, v.w, h23, l23);
            int off = m * A_STRIDE + k;
            *(uint2*)(As_hi + off) = make_uint2(h01, h23);
            *(uint2*)(As_lo + off) = make_uint2(l01, l23);
        }
#pragma unroll
        for (int r = 0; r < 4; r++) {
            int f = tid + r * 256;
            int krow = f >> 5, n = (f & 31) << 2;
            float4 v = *(const float4*)(cp + (size_t)(k0 + krow) * NN + n0 + n);
            uint32_t h01, l01, h23, l23;
            split2(v.x, v.y, h01, l01);
            split2(v.z, v.w, h23, l23);
            int off = krow * B_STRIDE + n;
            *(uint2*)(Bs_hi + off) = make_uint2(h01, h23);
            *(uint2*)(Bs_lo + off) = make_uint2(l01, l23);
        }
        __syncthreads();

#pragma unroll
        for (int ks = 0; ks < 2; ks++) {
            uint32_t a_hi[2][4], a_lo[2][4];
            const int arow = lane & 15;
            const int acol = (lane >> 4) << 3;
#pragma unroll
            for (int mi = 0; mi < 2; mi++) {
                uint32_t off = (uint32_t)((wm * 32 + mi * 16 + arow) * A_STRIDE
                                          + ks * 16 + acol) * 2;
                ldsm_x4(a_hi[mi], as_hi + off);
                ldsm_x4(a_lo[mi], as_lo + off);
            }
            uint32_t b_hi[4][2], b_lo[4][2];
            const int brow = lane & 15;
#pragma unroll
            for (int ni = 0; ni < 4; ni++) {
                uint32_t off = (uint32_t)((ks * 16 + brow) * B_STRIDE
                                          + wn * 32 + ni * 8) * 2;
                ldsm_x2_t(b_hi[ni], bs_hi + off);
                ldsm_x2_t(b_lo[ni], bs_lo + off);
            }
#pragma unroll
            for (int mi = 0; mi < 2; mi++)
#pragma unroll
                for (int ni = 0; ni < 4; ni++) {
                    mma_bf16(acc[mi][ni], a_hi[mi], b_hi[ni]);
                    mma_bf16(acc[mi][ni], a_hi[mi], b_lo[ni]);
                    mma_bf16(acc[mi][ni], a_lo[mi], b_hi[ni]);
                }
        }
        __syncthreads();
    }

    const int qrow = lane >> 2;
    const int qcol = (lane & 3) << 1;
#pragma unroll
    for (int mi = 0; mi < 2; mi++) {
        int mA = m0 + wm * 32 + mi * 16 + qrow;
        float* rowA = y + ((size_t)(b * CC + mA)) * NN + n0;
        float* rowB = rowA + (size_t)8 * NN;
#pragma unroll
        for (int ni = 0; ni < 4; ni++) {
            int n = wn * 32 + ni * 8 + qcol;
            *(float2*)(rowA + n) = make_float2(acc[mi][ni][0], acc[mi][ni][1]);
            *(float2*)(rowB + n) = make_float2(acc[mi][ni][2], acc[mi][ni][3]);
        }
    }
}

// ============================================================================
extern "C" void kernel_launch(void* const* d_in, const int* in_sizes, int n_in,
                              void* d_out, int out_size)
{
    const float* x      = (const float*)d_in[0];
    const float* W_bcdt = (const float*)d_in[1];
    const float* b_bcdt = (const float*)d_in[2];
    const float* W_dw   = (const float*)d_in[3];
    const float* b_dw   = (const float*)d_in[4];
    const float* W_hz   = (const float*)d_in[5];
    const float* b_hz   = (const float*)d_in[6];
    const float* W_out  = (const float*)d_in[7];
    const float* b_out  = (const float*)d_in[8];
    // d_in[9] = A : unused (softmax shift invariance along the reduced axis)
    const float* Dp     = (const float*)d_in[10];
    float* out = (float*)d_out;

    // side stream + fork/join events (created once; no device allocs)
    static cudaStream_t s1 = nullptr;
    static cudaEvent_t ev_g1 = nullptr, ev_c = nullptr;
    if (!s1) {
        cudaStreamCreateWithFlags(&s1, cudaStreamNonBlocking);
        cudaEventCreateWithFlags(&ev_g1, cudaEventDisableTiming);
        cudaEventCreateWithFlags(&ev_c, cudaEventDisableTiming);
        cudaFuncSetAttribute(conv_ab_kernel,
                             cudaFuncAttributeMaxDynamicSharedMemorySize, CVAB_SMEM);
    }

    gemm1_mma_kernel<<<dim3(3, NN / 128, BB), 256>>>(x, W_bcdt, b_bcdt);
    cudaEventRecord(ev_g1, 0);

    // side stream: conv_c overlaps with conv_ab/hgemm/hreduce/e1/e2
    cudaStreamWaitEvent(s1, ev_g1, 0);
    conv_c_kernel<<<dim3(2, SS, BB), 256, 0, s1>>>(W_dw, b_dw);
    cudaEventRecord(ev_c, s1);

    conv_ab_kernel<<<dim3(2, SS, BB), 256, CVAB_SMEM>>>(W_dw, b_dw);
    hgemm_mma_kernel<<<dim3(4, KSPLIT_H, BB), 256>>>(x);
    hreduce_kernel<<<256, 256>>>();
    e1_kernel<<<dim3(64, BB), 256>>>(W_hz, b_hz, Dp);
    e2_kernel<<<dim3(64, BB), 256>>>(W_out, b_out, out);

    cudaStreamWaitEvent(0, ev_c, 0);
    ygemm_mma_kernel<<<dim3(4, NN / 128, BB), 256>>>(out);
}

// round 13
// speedup vs baseline: 1.2416x; 1.0484x over previous
#include <cuda_runtime.h>
#include <cuda_bf16.h>
#include <cstdint>
#include <cstddef>

// Problem constants
#define BB   4
#define CC   256      // D_MODEL = D_INNER
#define SS   64
#define DD   16
#define HH   64
#define WW   64
#define NN   65536    // D*H*W
#define O3S  192      // 3*S
#define KSPLIT_H 64   // split-K factor for h-GEMM

static const size_t YSIZE = (size_t)BB * CC * NN;   // 67108864

// ---- static scratch (no runtime allocation allowed) ----
__device__ float g_bcdt[(size_t)BB * O3S * NN];   // GEMM1 output (pre-conv)
__device__ float g_ab[(size_t)BB * SS * NN];      // AB_unnorm = exp(conv dt)*conv B_
__device__ float g_c [(size_t)BB * SS * NN];      // conv C_ channels
__device__ float g_hpart[(size_t)KSPLIT_H * BB * CC * SS];
__device__ float g_psum[BB * SS * 2];             // per-h-half exp-sums
__device__ float g_h [BB * CC * SS];
__device__ float g_h3[BB * CC * SS];
__device__ float g_h4[BB * CC * SS];

// ============================================================================
// helpers
// ============================================================================
__device__ __forceinline__ uint32_t smem_u32(const void* p) {
    uint32_t a;
    asm("{ .reg .u64 t; cvta.to.shared.u64 t, %1; cvt.u32.u64 %0, t; }" : "=r"(a) : "l"(p));
    return a;
}
__device__ __forceinline__ void ldsm_x4(uint32_t* r, uint32_t addr) {
    asm volatile("ldmatrix.sync.aligned.m8n8.x4.shared.b16 {%0,%1,%2,%3}, [%4];"
        : "=r"(r[0]), "=r"(r[1]), "=r"(r[2]), "=r"(r[3]) : "r"(addr));
}
__device__ __forceinline__ void ldsm_x2(uint32_t* r, uint32_t addr) {
    asm volatile("ldmatrix.sync.aligned.m8n8.x2.shared.b16 {%0,%1}, [%2];"
        : "=r"(r[0]), "=r"(r[1]) : "r"(addr));
}
__device__ __forceinline__ void ldsm_x2_t(uint32_t* r, uint32_t addr) {
    asm volatile("ldmatrix.sync.aligned.m8n8.x2.trans.shared.b16 {%0,%1}, [%2];"
        : "=r"(r[0]), "=r"(r[1]) : "r"(addr));
}
__device__ __forceinline__ void mma_bf16(float* c, const uint32_t* a, const uint32_t* b) {
    asm volatile(
        "mma.sync.aligned.m16n8k16.row.col.f32.bf16.bf16.f32 "
        "{%0,%1,%2,%3}, {%4,%5,%6,%7}, {%8,%9}, {%0,%1,%2,%3};"
        : "+f"(c[0]), "+f"(c[1]), "+f"(c[2]), "+f"(c[3])
        : "r"(a[0]), "r"(a[1]), "r"(a[2]), "r"(a[3]), "r"(b[0]), "r"(b[1]));
}
__device__ __forceinline__ void split2(float v0, float v1, uint32_t& hi, uint32_t& lo) {
    __nv_bfloat16 h0 = __float2bfloat16(v0), h1 = __float2bfloat16(v1);
    float r0 = v0 - __bfloat162float(h0), r1 = v1 - __bfloat162float(h1);
    __nv_bfloat162 hh = __halves2bfloat162(h0, h1);
    __nv_bfloat162 ll = __floats2bfloat162_rn(r0, r1);
    hi = *(uint32_t*)&hh; lo = *(uint32_t*)&ll;
}
// FMA-pipe exp (poly 2^f on [-0.5,0.5], ~2e-9 rel err), clamped both sides
__device__ __forceinline__ float fexp(float x) {
    float t = fminf(fmaxf(x * 1.4426950408889634f, -125.0f), 125.0f);
    float n = rintf(t);
    float f = t - n;
    float p = 1.5403530393381609e-4f;
    p = fmaf(p, f, 1.3333558146428443e-3f);
    p = fmaf(p, f, 9.618129107628477e-3f);
    p = fmaf(p, f, 5.550410866482158e-2f);
    p = fmaf(p, f, 2.402265069591999e-1f);
    p = fmaf(p, f, 6.931471805599453e-1f);
    p = fmaf(p, f, 1.0f);
    return __int_as_float(((int)n + 127) << 23) * p;
}

#define A_STRIDE 40    // halves per 32-k row (32 + 8 pad)
#define B_STRIDE 136   // halves per 128-n row (128 + 8 pad)
#define HB_STRIDE 40

// conv smem geometry: 34 rows x 68 floats (16B-aligned rows), 3 planes
#define CV_STRIDE 68
#define CV_PLANE  (34 * CV_STRIDE)
#define CVAB_SMEM (2 * 3 * CV_PLANE * 4)   // 55488 bytes (B + D arrays)

// double-buffer byte offsets
#define G1_ABUF (64 * A_STRIDE * 2)
#define G1_BBUF (32 * B_STRIDE * 2)
#define HG_ABUF (64 * A_STRIDE * 2)
#define HG_BBUF (64 * HB_STRIDE * 2)

// ============================================================================
// Kernel 1 (HMMA): BCdt = W_bcdt(192x256) @ x(b,256,N) + b_bcdt
// BM=64, BN=128, BK=32. Reg prefetch + smem DOUBLE BUFFER (1 sync/iter).
// ============================================================================
__global__ void __launch_bounds__(256) gemm1_mma_kernel(
    const float* __restrict__ x, const float* __restrict__ W,
    const float* __restrict__ bias)
{
    __shared__ __align__(16) uint16_t As_hi[2 * 64 * A_STRIDE];
    __shared__ __align__(16) uint16_t As_lo[2 * 64 * A_STRIDE];
    __shared__ __align__(16) uint16_t Bs_hi[2 * 32 * B_STRIDE];
    __shared__ __align__(16) uint16_t Bs_lo[2 * 32 * B_STRIDE];

    const int m0 = blockIdx.x * 64;     // fastest -> L2 sharing of x tile
    const int n0 = blockIdx.y * 128;
    const int b  = blockIdx.z;
    const int tid  = threadIdx.x;
    const int wid  = tid >> 5;
    const int lane = tid & 31;
    const int wm = wid >> 2;
    const int wn = wid & 3;

    const float* xb = x + (size_t)b * CC * NN;
    const uint32_t as_hi0 = smem_u32(As_hi), as_lo0 = smem_u32(As_lo);
    const uint32_t bs_hi0 = smem_u32(Bs_hi), bs_lo0 = smem_u32(Bs_lo);

    const int krow0 = tid >> 5;
    const int nloc  = (tid & 31) << 2;

    float acc[2][4][4];
#pragma unroll
    for (int i = 0; i < 2; i++)
#pragma unroll
        for (int j = 0; j < 4; j++)
#pragma unroll
            for (int q = 0; q < 4; q++) acc[i][j][q] = 0.f;

    float4 rbx[4];
#pragma unroll
    for (int r = 0; r < 4; r++)
        rbx[r] = *(const float4*)(xb + (size_t)(krow0 + r * 8) * NN + n0 + nloc);

    for (int it = 0; it < 8; it++) {
        const int k0 = it * 32;
        const int buf = it & 1;
        uint16_t* Ah = As_hi + buf * (64 * A_STRIDE);
        uint16_t* Al = As_lo + buf * (64 * A_STRIDE);
        uint16_t* Bh = Bs_hi + buf * (32 * B_STRIDE);
        uint16_t* Bl = Bs_lo + buf * (32 * B_STRIDE);

#pragma unroll
        for (int r = 0; r < 2; r++) {
            int f = tid + r * 256;
            int m = f >> 3, k = (f & 7) << 2;
            float4 v = *(const float4*)(W + (size_t)(m0 + m) * 256 + k0 + k);
            uint32_t h01, l01, h23, l23;
            split2(v.x, v.y, h01, l01);
            split2(v.z, v.w, h23, l23);
            int off = m * A_STRIDE + k;
            *(uint2*)(Ah + off) = make_uint2(h01, h23);
            *(uint2*)(Al + off) = make_uint2(l01, l23);
        }
#pragma unroll
        for (int r = 0; r < 4; r++) {
            float4 v = rbx[r];
            uint32_t h01, l01, h23, l23;
            split2(v.x, v.y, h01, l01);
            split2(v.z, v.w, h23, l23);
            int off = (krow0 + r * 8) * B_STRIDE + nloc;
            *(uint2*)(Bh + off) = make_uint2(h01, h23);
            *(uint2*)(Bl + off) = make_uint2(l01, l23);
        }
        __syncthreads();     // single barrier per iteration (double buffer)

        if (it < 7) {
#pragma unroll
            for (int r = 0; r < 4; r++)
                rbx[r] = *(const float4*)(xb + (size_t)(k0 + 32 + krow0 + r * 8) * NN + n0 + nloc);
        }

        const uint32_t ah = as_hi0 + buf * G1_ABUF, al = as_lo0 + buf * G1_ABUF;
        const uint32_t bh = bs_hi0 + buf * G1_BBUF, bl = bs_lo0 + buf * G1_BBUF;
#pragma unroll
        for (int ks = 0; ks < 2; ks++) {
            uint32_t a_hi[2][4], a_lo[2][4];
            const int arow = lane & 15;
            const int acol = (lane >> 4) << 3;
#pragma unroll
            for (int mi = 0; mi < 2; mi++) {
                uint32_t off = (uint32_t)((wm * 32 + mi * 16 + arow) * A_STRIDE
                                          + ks * 16 + acol) * 2;
                ldsm_x4(a_hi[mi], ah + off);
                ldsm_x4(a_lo[mi], al + off);
            }
            uint32_t b_hi[4][2], b_lo[4][2];
            const int brow = lane & 15;
#pragma unroll
            for (int ni = 0; ni < 4; ni++) {
                uint32_t off = (uint32_t)((ks * 16 + brow) * B_STRIDE
                                          + wn * 32 + ni * 8) * 2;
                ldsm_x2_t(b_hi[ni], bh + off);
                ldsm_x2_t(b_lo[ni], bl + off);
            }
#pragma unroll
            for (int mi = 0; mi < 2; mi++)
#pragma unroll
                for (int ni = 0; ni < 4; ni++) {
                    mma_bf16(acc[mi][ni], a_hi[mi], b_hi[ni]);
                    mma_bf16(acc[mi][ni], a_hi[mi], b_lo[ni]);
                    mma_bf16(acc[mi][ni], a_lo[mi], b_hi[ni]);
                }
        }
    }

    const int qrow = lane >> 2;
    const int qcol = (lane & 3) << 1;
#pragma unroll
    for (int mi = 0; mi < 2; mi++) {
        int mA = m0 + wm * 32 + mi * 16 + qrow;
        float bA = bias[mA], bB = bias[mA + 8];
        float* rowA = g_bcdt + ((size_t)(b * O3S + mA)) * NN + n0;
        float* rowB = rowA + (size_t)8 * NN;
#pragma unroll
        for (int ni = 0; ni < 4; ni++) {
            int n = wn * 32 + ni * 8 + qcol;
            *(float2*)(rowA + n) = make_float2(acc[mi][ni][0] + bA, acc[mi][ni][1] + bA);
            *(float2*)(rowB + n) = make_float2(acc[mi][ni][2] + bB, acc[mi][ni][3] + bB);
        }
    }
}

// ============================================================================
// Kernel 2a: FUSED depthwise conv (B_ + dt) + exp + multiply, VECTORIZED.
// ============================================================================
__global__ void __launch_bounds__(256) conv_ab_kernel(
    const float* __restrict__ wdw, const float* __restrict__ bdw)
{
    extern __shared__ __align__(16) float cvs[];
    float* sB = cvs;                    // [3][34][68]
    float* sD = cvs + 3 * CV_PLANE;     // [3][34][68]
    __shared__ float wB[27], wD[27];
    __shared__ float red[8];

    const int hhalf = blockIdx.x;
    const int s_ = blockIdx.y;
    const int b  = blockIdx.z;
    const int h0 = hhalf * 32;
    const int tid = threadIdx.x;
    const int chB = s_;
    const int chD = 128 + s_;

    const float* baseB = g_bcdt + ((size_t)(b * O3S + chB)) * NN;
    const float* baseD = g_bcdt + ((size_t)(b * O3S + chD)) * NN;

    if (tid < 27) wB[tid] = wdw[chB * 27 + tid];
    else if (tid >= 32 && tid < 59) wD[tid - 32] = wdw[chD * 27 + (tid - 32)];
    const float biasB = bdw[chB];
    const float biasD = bdw[chD];

    auto loadplane = [&](int z, int slot) {
        for (int idx = tid; idx < 34 * 66; idx += 256) {
            int ih = idx / 66, iw = idx % 66;
            int h = h0 - 1 + ih, w = iw - 1;
            bool ok = ((unsigned)z < (unsigned)DD) && ((unsigned)h < (unsigned)HH)
                      && ((unsigned)w < (unsigned)WW);
            size_t g = (size_t)z * (HH * WW) + (size_t)h * WW + w;
            sB[slot * CV_PLANE + ih * CV_STRIDE + iw] = ok ? baseB[g] : 0.f;
            sD[slot * CV_PLANE + ih * CV_STRIDE + iw] = ok ? baseD[g] : 0.f;
        }
    };
    loadplane(-1, 0);
    loadplane(0, 1);
    loadplane(1, 2);
    __syncthreads();

    const int w4 = (tid & 15) * 4;      // 0..60
    const int hl = (tid >> 4) * 2;      // 0,2,..,30
    float* abp = g_ab + ((size_t)(b * SS + s_)) * NN;
    float lsum = 0.f;

    for (int dz = 0; dz < DD; dz++) {
        float aB0[4], aB1[4], aD0[4], aD1[4];
#pragma unroll
        for (int j = 0; j < 4; j++) {
            aB0[j] = biasB; aB1[j] = biasB;
            aD0[j] = biasD; aD1[j] = biasD;
        }
#pragma unroll
        for (int kd = 0; kd < 3; kd++) {
            const int pl = (dz + kd) % 3;
            const float* bb = sB + pl * CV_PLANE;
            const float* db = sD + pl * CV_PLANE;
#pragma unroll
            for (int q = 0; q < 4; q++) {
                const float* rowb = bb + (hl + q) * CV_STRIDE + w4;
                const float* rowd = db + (hl + q) * CV_STRIDE + w4;
                float4 u0 = *(const float4*)(rowb);
                float4 u1 = *(const float4*)(rowb + 4);
                float4 t0 = *(const float4*)(rowd);
                float4 t1 = *(const float4*)(rowd + 4);
                float vB[8] = {u0.x, u0.y, u0.z, u0.w, u1.x, u1.y, u1.z, u1.w};
                float vD[8] = {t0.x, t0.y, t0.z, t0.w, t1.x, t1.y, t1.z, t1.w};
                if (q < 3) {
#pragma unroll
                    for (int kw = 0; kw < 3; kw++) {
                        float wtb = wB[kd * 9 + q * 3 + kw];
                        float wtd = wD[kd * 9 + q * 3 + kw];
#pragma unroll
                        for (int j = 0; j < 4; j++) {
                            aB0[j] = fmaf(vB[j + kw], wtb, aB0[j]);
                            aD0[j] = fmaf(vD[j + kw], wtd, aD0[j]);
                        }
                    }
                }
                if (q >= 1) {
#pragma unroll
                    for (int kw = 0; kw < 3; kw++) {
                        float wtb = wB[kd * 9 + (q - 1) * 3 + kw];
                        float wtd = wD[kd * 9 + (q - 1) * 3 + kw];
#pragma unroll
                        for (int j = 0; j < 4; j++) {
                            aB1[j] = fmaf(vB[j + kw], wtb, aB1[j]);
                            aD1[j] = fmaf(vD[j + kw], wtd, aD1[j]);
                        }
                    }
                }
            }
        }
        float e0[4], e1[4];
#pragma unroll
        for (int j = 0; j < 4; j++) {
            e0[j] = fexp(aD0[j]);
            e1[j] = fexp(aD1[j]);
            lsum += e0[j] + e1[j];
        }
        float* o0 = abp + (size_t)dz * (HH * WW) + (h0 + hl) * WW + w4;
        *(float4*)(o0)      = make_float4(e0[0] * aB0[0], e0[1] * aB0[1],
                                          e0[2] * aB0[2], e0[3] * aB0[3]);
        *(float4*)(o0 + WW) = make_float4(e1[0] * aB1[0], e1[1] * aB1[1],
                                          e1[2] * aB1[2], e1[3] * aB1[3]);
        __syncthreads();
        if (dz < DD - 1) loadplane(dz + 2, dz % 3);
        __syncthreads();
    }

    const int lane = tid & 31, warp = tid >> 5;
#pragma unroll
    for (int o = 16; o > 0; o >>= 1) lsum += __shfl_xor_sync(0xffffffffu, lsum, o);
    if (lane == 0) red[warp] = lsum;
    __syncthreads();
    if (tid == 0) {
        float v = red[0] + red[1] + red[2] + red[3] + red[4] + red[5] + red[6] + red[7];
        g_psum[(b * SS + s_) * 2 + hhalf] = v;
    }
}

// ============================================================================
// Kernel 2b: depthwise conv for C_ channels (64..127), VECTORIZED, rolling dz.
// ============================================================================
__global__ void __launch_bounds__(256) conv_c_kernel(
    const float* __restrict__ wdw, const float* __restrict__ bdw)
{
    __shared__ __align__(16) float s[3 * CV_PLANE];
    __shared__ float wt[27];

    const int hhalf = blockIdx.x;
    const int s_ = blockIdx.y;
    const int b  = blockIdx.z;
    const int h0 = hhalf * 32;
    const int tid = threadIdx.x;
    const int ch = 64 + s_;

    const float* base = g_bcdt + ((size_t)(b * O3S + ch)) * NN;
    if (tid < 27) wt[tid] = wdw[ch * 27 + tid];
    const float bbv = bdw[ch];

    auto loadplane = [&](int z, int slot) {
        for (int idx = tid; idx < 34 * 66; idx += 256) {
            int ih = idx / 66, iw = idx % 66;
            int h = h0 - 1 + ih, w = iw - 1;
            bool ok = ((unsigned)z < (unsigned)DD) && ((unsigned)h < (unsigned)HH)
                      && ((unsigned)w < (unsigned)WW);
            size_t g = (size_t)z * (HH * WW) + (size_t)h * WW + w;
            s[slot * CV_PLANE + ih * CV_STRIDE + iw] = ok ? base[g] : 0.f;
        }
    };
    loadplane(-1, 0);
    loadplane(0, 1);
    loadplane(1, 2);
    __syncthreads();

    const int w4 = (tid & 15) * 4;
    const int hl = (tid >> 4) * 2;
    float* outp = g_c + ((size_t)(b * SS + s_)) * NN;

    for (int dz = 0; dz < DD; dz++) {
        float a0[4], a1[4];
#pragma unroll
        for (int j = 0; j < 4; j++) { a0[j] = bbv; a1[j] = bbv; }
#pragma unroll
        for (int kd = 0; kd < 3; kd++) {
            const int pl = (dz + kd) % 3;
            const float* bb = s + pl * CV_PLANE;
#pragma unroll
            for (int q = 0; q < 4; q++) {
                const float* row = bb + (hl + q) * CV_STRIDE + w4;
                float4 u0 = *(const float4*)(row);
                float4 u1 = *(const float4*)(row + 4);
                float v[8] = {u0.x, u0.y, u0.z, u0.w, u1.x, u1.y, u1.z, u1.w};
                if (q < 3) {
#pragma unroll
                    for (int kw = 0; kw < 3; kw++) {
                        float wv = wt[kd * 9 + q * 3 + kw];
#pragma unroll
                        for (int j = 0; j < 4; j++)
                            a0[j] = fmaf(v[j + kw], wv, a0[j]);
                    }
                }
                if (q >= 1) {
#pragma unroll
                    for (int kw = 0; kw < 3; kw++) {
                        float wv = wt[kd * 9 + (q - 1) * 3 + kw];
#pragma unroll
                        for (int j = 0; j < 4; j++)
                            a1[j] = fmaf(v[j + kw], wv, a1[j]);
                    }
                }
            }
        }
        float* o0 = outp + (size_t)dz * (HH * WW) + (h0 + hl) * WW + w4;
        *(float4*)(o0)      = make_float4(a0[0], a0[1], a0[2], a0[3]);
        *(float4*)(o0 + WW) = make_float4(a1[0], a1[1], a1[2], a1[3]);
        __syncthreads();
        if (dz < DD - 1) loadplane(dz + 2, dz % 3);
        __syncthreads();
    }
}

// ============================================================================
// Kernel 4 (HMMA): h_unnorm partials = sum_n x * AB_unnorm
// BM=64(c), BN=64(s), BK=32. Reg prefetch + smem DOUBLE BUFFER (1 sync/iter).
// ============================================================================
__global__ void __launch_bounds__(256) hgemm_mma_kernel(const float* __restrict__ x)
{
    __shared__ __align__(16) uint16_t As_hi[2 * 64 * A_STRIDE];
    __shared__ __align__(16) uint16_t As_lo[2 * 64 * A_STRIDE];
    __shared__ __align__(16) uint16_t Bs_hi[2 * 64 * HB_STRIDE];
    __shared__ __align__(16) uint16_t Bs_lo[2 * 64 * HB_STRIDE];

    const int c0 = blockIdx.x * 64;          // fastest -> L2 sharing of AB tile
    const int ks = blockIdx.y;               // 0..63
    const int b  = blockIdx.z;
    const int nbase = ks * (NN / KSPLIT_H);  // 1024 chunk
    const int tid  = threadIdx.x;
    const int wid  = tid >> 5;
    const int lane = tid & 31;
    const int wm = wid >> 2;
    const int wn = wid & 3;

    const float* xb = x + ((size_t)(b * CC + c0)) * NN;
    const float* ab = g_ab + (size_t)b * SS * NN;
    const uint32_t as_hi0 = smem_u32(As_hi), as_lo0 = smem_u32(As_lo);
    const uint32_t bs_hi0 = smem_u32(Bs_hi), bs_lo0 = smem_u32(Bs_lo);

    const int lr = tid >> 3;            // 0..31
    const int lk = (tid & 7) << 2;      // 0..28

    float acc[2][2][4];
#pragma unroll
    for (int i = 0; i < 2; i++)
#pragma unroll
        for (int j = 0; j < 2; j++)
#pragma unroll
            for (int q = 0; q < 4; q++) acc[i][j][q] = 0.f;

    float4 rx[2], rab[2];
    rx[0]  = *(const float4*)(xb + (size_t)lr * NN + nbase + lk);
    rx[1]  = *(const float4*)(xb + (size_t)(lr + 32) * NN + nbase + lk);
    rab[0] = *(const float4*)(ab + (size_t)lr * NN + nbase + lk);
    rab[1] = *(const float4*)(ab + (size_t)(lr + 32) * NN + nbase + lk);

    const int ITERS = (NN / KSPLIT_H) / 32;   // 32
    for (int it = 0; it < ITERS; it++) {
        const int buf = it & 1;
        uint16_t* Ah = As_hi + buf * (64 * A_STRIDE);
        uint16_t* Al = As_lo + buf * (64 * A_STRIDE);
        uint16_t* Bh = Bs_hi + buf * (64 * HB_STRIDE);
        uint16_t* Bl = Bs_lo + buf * (64 * HB_STRIDE);

#pragma unroll
        for (int r = 0; r < 2; r++) {
            float4 v = rx[r];
            uint32_t h01, l01, h23, l23;
            split2(v.x, v.y, h01, l01);
            split2(v.z, v.w, h23, l23);
            int off = (lr + r * 32) * A_STRIDE + lk;
            *(uint2*)(Ah + off) = make_uint2(h01, h23);
            *(uint2*)(Al + off) = make_uint2(l01, l23);
        }
#pragma unroll
        for (int r = 0; r < 2; r++) {
            float4 v = rab[r];
            uint32_t h01, l01, h23, l23;
            split2(v.x, v.y, h01, l01);
            split2(v.z, v.w, h23, l23);
            int off = (lr + r * 32) * HB_STRIDE + lk;
            *(uint2*)(Bh + off) = make_uint2(h01, h23);
            *(uint2*)(Bl + off) = make_uint2(l01, l23);
        }
        __syncthreads();     // single barrier per iteration (double buffer)

        if (it + 1 < ITERS) {
            const int nb2 = nbase + (it + 1) * 32;
            rx[0]  = *(const float4*)(xb + (size_t)lr * NN + nb2 + lk);
            rx[1]  = *(const float4*)(xb + (size_t)(lr + 32) * NN + nb2 + lk);
            rab[0] = *(const float4*)(ab + (size_t)lr * NN + nb2 + lk);
            rab[1] = *(const float4*)(ab + (size_t)(lr + 32) * NN + nb2 + lk);
        }

        const uint32_t ah = as_hi0 + buf * HG_ABUF, al = as_lo0 + buf * HG_ABUF;
        const uint32_t bh = bs_hi0 + buf * HG_BBUF, bl = bs_lo0 + buf * HG_BBUF;
#pragma unroll
        for (int kq = 0; kq < 2; kq++) {
            uint32_t a_hi[2][4], a_lo[2][4];
            const int arow = lane & 15;
            const int acol = (lane >> 4) << 3;
#pragma unroll
            for (int mi = 0; mi < 2; mi++) {
                uint32_t off = (uint32_t)((wm * 32 + mi * 16 + arow) * A_STRIDE
                                          + kq * 16 + acol) * 2;
                ldsm_x4(a_hi[mi], ah + off);
                ldsm_x4(a_lo[mi], al + off);
            }
            uint32_t b_hi[2][2], b_lo[2][2];
            const int l = lane & 15;
            const int srow = l & 7;
            const int koff = (l >> 3) << 3;
#pragma unroll
            for (int ni = 0; ni < 2; ni++) {
                uint32_t off = (uint32_t)((wn * 16 + ni * 8 + srow) * HB_STRIDE
                                          + kq * 16 + koff) * 2;
                ldsm_x2(b_hi[ni], bh + off);
                ldsm_x2(b_lo[ni], bl + off);
            }
#pragma unroll
            for (int mi = 0; mi < 2; mi++)
#pragma unroll
                for (int ni = 0; ni < 2; ni++) {
                    mma_bf16(acc[mi][ni], a_hi[mi], b_hi[ni]);
                    mma_bf16(acc[mi][ni], a_hi[mi], b_lo[ni]);
                    mma_bf16(acc[mi][ni], a_lo[mi], b_hi[ni]);
                }
        }
    }

    float* dst = g_hpart + (size_t)ks * (BB * CC * SS);
    const int qrow = lane >> 2;
    const int qcol = (lane & 3) << 1;
#pragma unroll
    for (int mi = 0; mi < 2; mi++) {
        int cA = c0 + wm * 32 + mi * 16 + qrow;
#pragma unroll
        for (int ni = 0; ni < 2; ni++) {
            int sA = wn * 16 + ni * 8 + qcol;
            float* pA = dst + ((size_t)(b * CC + cA)) * SS + sA;
            float* pB = dst + ((size_t)(b * CC + cA + 8)) * SS + sA;
            *(float2*)pA = make_float2(acc[mi][ni][0], acc[mi][ni][1]);
            *(float2*)pB = make_float2(acc[mi][ni][2], acc[mi][ni][3]);
        }
    }
}

// reduction of split-K partials + deferred softmax normalization
__global__ void __launch_bounds__(256) hreduce_kernel()
{
    int i = blockIdx.x * 256 + threadIdx.x;   // ((b*CC+c)*SS+s) < 65536
    int b = i >> 14;
    int s = i & 63;
    const float* ps = &g_psum[(b * SS + s) * 2];
    float inv = 1.f / (ps[0] + ps[1]);
    float sum = 0.f;
#pragma unroll
    for (int ks = 0; ks < KSPLIT_H; ks++)
        sum += g_hpart[(size_t)ks * (BB * CC * SS) + i];
    g_h[i] = sum * inv;
}

// ============================================================================
// Kernel 5: hz = W_hz @ h + b_hz ; h3 = h2*silu(z) + h2*Dp
// ============================================================================
__global__ void __launch_bounds__(256) e1_kernel(
    const float* __restrict__ Whz, const float* __restrict__ bhz,
    const float* __restrict__ Dp)
{
    const int b = blockIdx.y;
    const int o = blockIdx.x * 4 + (threadIdx.x >> 6);
    const int s_ = threadIdx.x & 63;
    const float* hb = g_h + (size_t)b * CC * SS;
    const float* w1 = Whz + (size_t)o * 256;
    const float* w2 = Whz + (size_t)(o + 256) * 256;
    float a1 = bhz[o], a2 = bhz[o + 256];
    for (int c = 0; c < 256; c++) {
        float hv = hb[c * 64 + s_];
        a1 += w1[c] * hv;
        a2 += w2[c] * hv;
    }
    float sig = 1.f / (1.f + __expf(-a2));
    g_h3[((size_t)b * CC + o) * SS + s_] = a1 * (a2 * sig) + a1 * Dp[0];
}

// Kernel 6: h4 = W_out @ h3 + b_out ; write to scratch + output tail
__global__ void __launch_bounds__(256) e2_kernel(
    const float* __restrict__ Wout, const float* __restrict__ bout,
    float* __restrict__ out)
{
    const int b = blockIdx.y;
    const int o = blockIdx.x * 4 + (threadIdx.x >> 6);
    const int s_ = threadIdx.x & 63;
    const float* hb = g_h3 + (size_t)b * CC * SS;
    const float* w1 = Wout + (size_t)o * 256;
    float acc = bout[o];
    for (int c = 0; c < 256; c++)
        acc += w1[c] * hb[c * 64 + s_];
    size_t idx = ((size_t)b * CC + o) * SS + s_;
    g_h4[idx] = acc;
    out[YSIZE + idx] = acc;
}

// ============================================================================
// Kernel 7 (HMMA): y[b,c,n] = sum_s h4[b,c,s] * C_[b,s,n]
// ============================================================================
__global__ void __launch_bounds__(256) ygemm_mma_kernel(float* __restrict__ y)
{
    __shared__ __align__(16) uint16_t As_hi[64 * A_STRIDE];
    __shared__ __align__(16) uint16_t As_lo[64 * A_STRIDE];
    __shared__ __align__(16) uint16_t Bs_hi[32 * B_STRIDE];
    __shared__ __align__(16) uint16_t Bs_lo[32 * B_STRIDE];

    const int m0 = blockIdx.x * 64;     // fastest -> L2 sharing of C_ tile
    const int n0 = blockIdx.y * 128;
    const int b  = blockIdx.z;
    const int tid  = threadIdx.x;
    const int wid  = tid >> 5;
    const int lane = tid & 31;
    const int wm = wid >> 2;
    const int wn = wid & 3;

    const float* h4b = g_h4 + (size_t)b * CC * SS;
    const float* cp  = g_c + (size_t)b * SS * NN;
    const uint32_t as_hi = smem_u32(As_hi), as_lo = smem_u32(As_lo);
    const uint32_t bs_hi = smem_u32(Bs_hi), bs_lo = smem_u32(Bs_lo);

    float acc[2][4][4];
#pragma unroll
    for (int i = 0; i < 2; i++)
#pragma unroll
        for (int j = 0; j < 4; j++)
#pragma unroll
            for (int q = 0; q < 4; q++) acc[i][j][q] = 0.f;

    for (int k0 = 0; k0 < 64; k0 += 32) {
#pragma unroll
        for (int r = 0; r < 2; r++) {
            int f = tid + r * 256;
            int m = f >> 3, k = (f & 7) << 2;
            float4 v = *(const float4*)(h4b + (size_t)(m0 + m) * SS + k0 + k);
            uint32_t h01, l01, h23, l23;
            split2(v.x, v.y, h01, l01);
            split2(v.z, v.w, h23, l23);
            int off = m * A_STRIDE + k;
            *(uint2*)(As_hi + off) = make_uint2(h01, h23);
            *(uint2*)(As_lo + off) = make_uint2(l01, l23);
        }
#pragma unroll
        for (int r = 0; r < 4; r++) {
            int f = tid + r * 256;
            int krow = f >> 5, n = (f & 31) << 2;
            float4 v = *(const float4*)(cp + (size_t)(k0 + krow) * NN + n0 + n);
            uint32_t h01, l01, h23, l23;
            split2(v.x, v.y, h01, l01);
            split2(v.z, v.w, h23, l23);
            int off = krow * B_STRIDE + n;
            *(uint2*)(Bs_hi + off) = make_uint2(h01, h23);
            *(uint2*)(Bs_lo + off) = make_uint2(l01, l23);
        }
        __syncthreads();

#pragma unroll
        for (int ks = 0; ks < 2; ks++) {
            uint32_t a_hi[2][4], a_lo[2][4];
            const int arow = lane & 15;
            const int acol = (lane >> 4) << 3;
#pragma unroll
            for (int mi = 0; mi < 2; mi++) {
                uint32_t off = (uint32_t)((wm * 32 + mi * 16 + arow) * A_STRIDE
                                          + ks * 16 + acol) * 2;
                ldsm_x4(a_hi[mi], as_hi + off);
                ldsm_x4(a_lo[mi], as_lo + off);
            }
            uint32_t b_hi[4][2], b_lo[4][2];
            const int brow = lane & 15;
#pragma unroll
            for (int ni = 0; ni < 4; ni++) {
                uint32_t off = (uint32_t)((ks * 16 + brow) * B_STRIDE
                                          + wn * 32 + ni * 8) * 2;
                ldsm_x2_t(b_hi[ni], bs_hi + off);
                ldsm_x2_t(b_lo[ni], bs_lo + off);
            }
#pragma unroll
            for (int mi = 0; mi < 2; mi++)
#pragma unroll
                for (int ni = 0; ni < 4; ni++) {
                    mma_bf16(acc[mi][ni], a_hi[mi], b_hi[ni]);
                    mma_bf16(acc[mi][ni], a_hi[mi], b_lo[ni]);
                    mma_bf16(acc[mi][ni], a_lo[mi], b_hi[ni]);
                }
        }
        __syncthreads();
    }

    const int qrow = lane >> 2;
    const int qcol = (lane & 3) << 1;
#pragma unroll
    for (int mi = 0; mi < 2; mi++) {
        int mA = m0 + wm * 32 + mi * 16 + qrow;
        float* rowA = y + ((size_t)(b * CC + mA)) * NN + n0;
        float* rowB = rowA + (size_t)8 * NN;
#pragma unroll
        for (int ni = 0; ni < 4; ni++) {
            int n = wn * 32 + ni * 8 + qcol;
            *(float2*)(rowA + n) = make_float2(acc[mi][ni][0], acc[mi][ni][1]);
            *(float2*)(rowB + n) = make_float2(acc[mi][ni][2], acc[mi][ni][3]);
        }
    }
}

// ============================================================================
extern "C" void kernel_launch(void* const* d_in, const int* in_sizes, int n_in,
                              void* d_out, int out_size)
{
    const float* x      = (const float*)d_in[0];
    const float* W_bcdt = (const float*)d_in[1];
    const float* b_bcdt = (const float*)d_in[2];
    const float* W_dw   = (const float*)d_in[3];
    const float* b_dw   = (const float*)d_in[4];
    const float* W_hz   = (const float*)d_in[5];
    const float* b_hz   = (const float*)d_in[6];
    const float* W_out  = (const float*)d_in[7];
    const float* b_out  = (const float*)d_in[8];
    // d_in[9] = A : unused (softmax shift invariance along the reduced axis)
    const float* Dp     = (const float*)d_in[10];
    float* out = (float*)d_out;

    // side stream + fork/join events (created once; no device allocs)
    static cudaStream_t s1 = nullptr;
    static cudaEvent_t ev_g1 = nullptr, ev_c = nullptr;
    if (!s1) {
        cudaStreamCreateWithFlags(&s1, cudaStreamNonBlocking);
        cudaEventCreateWithFlags(&ev_g1, cudaEventDisableTiming);
        cudaEventCreateWithFlags(&ev_c, cudaEventDisableTiming);
        cudaFuncSetAttribute(conv_ab_kernel,
                             cudaFuncAttributeMaxDynamicSharedMemorySize, CVAB_SMEM);
    }

    gemm1_mma_kernel<<<dim3(3, NN / 128, BB), 256>>>(x, W_bcdt, b_bcdt);
    cudaEventRecord(ev_g1, 0);

    // side stream: conv_c overlaps with conv_ab/hgemm/hreduce/e1/e2
    cudaStreamWaitEvent(s1, ev_g1, 0);
    conv_c_kernel<<<dim3(2, SS, BB), 256, 0, s1>>>(W_dw, b_dw);
    cudaEventRecord(ev_c, s1);

    conv_ab_kernel<<<dim3(2, SS, BB), 256, CVAB_SMEM>>>(W_dw, b_dw);
    hgemm_mma_kernel<<<dim3(4, KSPLIT_H, BB), 256>>>(x);
    hreduce_kernel<<<256, 256>>>();
    e1_kernel<<<dim3(64, BB), 256>>>(W_hz, b_hz, Dp);
    e2_kernel<<<dim3(64, BB), 256>>>(W_out, b_out, out);

    cudaStreamWaitEvent(0, ev_c, 0);
    ygemm_mma_kernel<<<dim3(4, NN / 128, BB), 256>>>(out);
}

// round 15
// speedup vs baseline: 1.3004x; 1.0474x over previous
#include <cuda_runtime.h>
#include <cuda_bf16.h>
#include <cstdint>
#include <cstddef>

// Problem constants
#define BB   4
#define CC   256      // D_MODEL = D_INNER
#define SS   64
#define DD   16
#define HH   64
#define WW   64
#define NN   65536    // D*H*W
#define O3S  192      // 3*S
#define KSPLIT_H 64   // split-K factor for h-GEMM

static const size_t YSIZE = (size_t)BB * CC * NN;   // 67108864

// ---- static scratch (no runtime allocation allowed) ----
__device__ float g_bcdt[(size_t)BB * O3S * NN];   // GEMM1 output (pre-conv)
__device__ float g_ab[(size_t)BB * SS * NN];      // AB_unnorm = exp(conv dt)*conv B_
__device__ float g_c [(size_t)BB * SS * NN];      // conv C_ channels
__device__ float g_hpart[(size_t)KSPLIT_H * BB * CC * SS];
__device__ float g_psum[BB * SS * 2];             // per-h-half exp-sums
__device__ float g_h [BB * CC * SS];
__device__ float g_h3[BB * CC * SS];
__device__ float g_h4[BB * CC * SS];

// ============================================================================
// helpers
// ============================================================================
__device__ __forceinline__ uint32_t smem_u32(const void* p) {
    uint32_t a;
    asm("{ .reg .u64 t; cvta.to.shared.u64 t, %1; cvt.u32.u64 %0, t; }" : "=r"(a) : "l"(p));
    return a;
}
__device__ __forceinline__ void ldsm_x4(uint32_t* r, uint32_t addr) {
    asm volatile("ldmatrix.sync.aligned.m8n8.x4.shared.b16 {%0,%1,%2,%3}, [%4];"
        : "=r"(r[0]), "=r"(r[1]), "=r"(r[2]), "=r"(r[3]) : "r"(addr));
}
__device__ __forceinline__ void ldsm_x2(uint32_t* r, uint32_t addr) {
    asm volatile("ldmatrix.sync.aligned.m8n8.x2.shared.b16 {%0,%1}, [%2];"
        : "=r"(r[0]), "=r"(r[1]) : "r"(addr));
}
__device__ __forceinline__ void ldsm_x2_t(uint32_t* r, uint32_t addr) {
    asm volatile("ldmatrix.sync.aligned.m8n8.x2.trans.shared.b16 {%0,%1}, [%2];"
        : "=r"(r[0]), "=r"(r[1]) : "r"(addr));
}
__device__ __forceinline__ void mma_bf16(float* c, const uint32_t* a, const uint32_t* b) {
    asm volatile(
        "mma.sync.aligned.m16n8k16.row.col.f32.bf16.bf16.f32 "
        "{%0,%1,%2,%3}, {%4,%5,%6,%7}, {%8,%9}, {%0,%1,%2,%3};"
        : "+f"(c[0]), "+f"(c[1]), "+f"(c[2]), "+f"(c[3])
        : "r"(a[0]), "r"(a[1]), "r"(a[2]), "r"(a[3]), "r"(b[0]), "r"(b[1]));
}
__device__ __forceinline__ void split2(float v0, float v1, uint32_t& hi, uint32_t& lo) {
    __nv_bfloat16 h0 = __float2bfloat16(v0), h1 = __float2bfloat16(v1);
    float r0 = v0 - __bfloat162float(h0), r1 = v1 - __bfloat162float(h1);
    __nv_bfloat162 hh = __halves2bfloat162(h0, h1);
    __nv_bfloat162 ll = __floats2bfloat162_rn(r0, r1);
    hi = *(uint32_t*)&hh; lo = *(uint32_t*)&ll;
}
// FMA-pipe exp (poly 2^f on [-0.5,0.5], ~2e-9 rel err), clamped both sides
__device__ __forceinline__ float fexp(float x) {
    float t = fminf(fmaxf(x * 1.4426950408889634f, -125.0f), 125.0f);
    float n = rintf(t);
    float f = t - n;
    float p = 1.5403530393381609e-4f;
    p = fmaf(p, f, 1.3333558146428443e-3f);
    p = fmaf(p, f, 9.618129107628477e-3f);
    p = fmaf(p, f, 5.550410866482158e-2f);
    p = fmaf(p, f, 2.402265069591999e-1f);
    p = fmaf(p, f, 6.931471805599453e-1f);
    p = fmaf(p, f, 1.0f);
    return __int_as_float(((int)n + 127) << 23) * p;
}

#define A_STRIDE 40    // halves per 32-k row (32 + 8 pad)
#define B_STRIDE 136   // halves per 128-n row (128 + 8 pad)
#define HB_STRIDE 40

// conv smem geometry: 34 rows x 68 floats (16B-aligned rows), 4-plane ring
#define CV_STRIDE 68
#define CV_PLANE  (34 * CV_STRIDE)
#define CVAB_SMEM (2 * 4 * CV_PLANE * 4)   // 73984 bytes (B + D arrays)

// double-buffer byte offsets
#define G1_ABUF (64 * A_STRIDE * 2)
#define G1_BBUF (32 * B_STRIDE * 2)
#define HG_ABUF (64 * A_STRIDE * 2)
#define HG_BBUF (64 * HB_STRIDE * 2)
#define YG_ABUF (64 * A_STRIDE * 2)
#define YG_BBUF (32 * B_STRIDE * 2)

// ============================================================================
// Kernel 1 (HMMA): BCdt = W_bcdt(192x256) @ x(b,256,N) + b_bcdt
// BM=64, BN=128, BK=32. Reg prefetch + smem double buffer (1 sync/iter).
// ============================================================================
__global__ void __launch_bounds__(256) gemm1_mma_kernel(
    const float* __restrict__ x, const float* __restrict__ W,
    const float* __restrict__ bias)
{
    __shared__ __align__(16) uint16_t As_hi[2 * 64 * A_STRIDE];
    __shared__ __align__(16) uint16_t As_lo[2 * 64 * A_STRIDE];
    __shared__ __align__(16) uint16_t Bs_hi[2 * 32 * B_STRIDE];
    __shared__ __align__(16) uint16_t Bs_lo[2 * 32 * B_STRIDE];

    const int m0 = blockIdx.x * 64;     // fastest -> L2 sharing of x tile
    const int n0 = blockIdx.y * 128;
    const int b  = blockIdx.z;
    const int tid  = threadIdx.x;
    const int wid  = tid >> 5;
    const int lane = tid & 31;
    const int wm = wid >> 2;
    const int wn = wid & 3;

    const float* xb = x + (size_t)b * CC * NN;
    const uint32_t as_hi0 = smem_u32(As_hi), as_lo0 = smem_u32(As_lo);
    const uint32_t bs_hi0 = smem_u32(Bs_hi), bs_lo0 = smem_u32(Bs_lo);

    const int krow0 = tid >> 5;
    const int nloc  = (tid & 31) << 2;

    float acc[2][4][4];
#pragma unroll
    for (int i = 0; i < 2; i++)
#pragma unroll
        for (int j = 0; j < 4; j++)
#pragma unroll
            for (int q = 0; q < 4; q++) acc[i][j][q] = 0.f;

    float4 rbx[4];
#pragma unroll
    for (int r = 0; r < 4; r++)
        rbx[r] = *(const float4*)(xb + (size_t)(krow0 + r * 8) * NN + n0 + nloc);

    for (int it = 0; it < 8; it++) {
        const int k0 = it * 32;
        const int buf = it & 1;
        uint16_t* Ah = As_hi + buf * (64 * A_STRIDE);
        uint16_t* Al = As_lo + buf * (64 * A_STRIDE);
        uint16_t* Bh = Bs_hi + buf * (32 * B_STRIDE);
        uint16_t* Bl = Bs_lo + buf * (32 * B_STRIDE);

#pragma unroll
        for (int r = 0; r < 2; r++) {
            int f = tid + r * 256;
            int m = f >> 3, k = (f & 7) << 2;
            float4 v = *(const float4*)(W + (size_t)(m0 + m) * 256 + k0 + k);
            uint32_t h01, l01, h23, l23;
            split2(v.x, v.y, h01, l01);
            split2(v.z, v.w, h23, l23);
            int off = m * A_STRIDE + k;
            *(uint2*)(Ah + off) = make_uint2(h01, h23);
            *(uint2*)(Al + off) = make_uint2(l01, l23);
        }
#pragma unroll
        for (int r = 0; r < 4; r++) {
            float4 v = rbx[r];
            uint32_t h01, l01, h23, l23;
            split2(v.x, v.y, h01, l01);
            split2(v.z, v.w, h23, l23);
            int off = (krow0 + r * 8) * B_STRIDE + nloc;
            *(uint2*)(Bh + off) = make_uint2(h01, h23);
            *(uint2*)(Bl + off) = make_uint2(l01, l23);
        }
        __syncthreads();     // single barrier per iteration (double buffer)

        if (it < 7) {
#pragma unroll
            for (int r = 0; r < 4; r++)
                rbx[r] = *(const float4*)(xb + (size_t)(k0 + 32 + krow0 + r * 8) * NN + n0 + nloc);
        }

        const uint32_t ah = as_hi0 + buf * G1_ABUF, al = as_lo0 + buf * G1_ABUF;
        const uint32_t bh = bs_hi0 + buf * G1_BBUF, bl = bs_lo0 + buf * G1_BBUF;
#pragma unroll
        for (int ks = 0; ks < 2; ks++) {
            uint32_t a_hi[2][4], a_lo[2][4];
            const int arow = lane & 15;
            const int acol = (lane >> 4) << 3;
#pragma unroll
            for (int mi = 0; mi < 2; mi++) {
                uint32_t off = (uint32_t)((wm * 32 + mi * 16 + arow) * A_STRIDE
                                          + ks * 16 + acol) * 2;
                ldsm_x4(a_hi[mi], ah + off);
                ldsm_x4(a_lo[mi], al + off);
            }
            uint32_t b_hi[4][2], b_lo[4][2];
            const int brow = lane & 15;
#pragma unroll
            for (int ni = 0; ni < 4; ni++) {
                uint32_t off = (uint32_t)((ks * 16 + brow) * B_STRIDE
                                          + wn * 32 + ni * 8) * 2;
                ldsm_x2_t(b_hi[ni], bh + off);
                ldsm_x2_t(b_lo[ni], bl + off);
            }
#pragma unroll
            for (int mi = 0; mi < 2; mi++)
#pragma unroll
                for (int ni = 0; ni < 4; ni++) {
                    mma_bf16(acc[mi][ni], a_hi[mi], b_hi[ni]);
                    mma_bf16(acc[mi][ni], a_hi[mi], b_lo[ni]);
                    mma_bf16(acc[mi][ni], a_lo[mi], b_hi[ni]);
                }
        }
    }

    const int qrow = lane >> 2;
    const int qcol = (lane & 3) << 1;
#pragma unroll
    for (int mi = 0; mi < 2; mi++) {
        int mA = m0 + wm * 32 + mi * 16 + qrow;
        float bA = bias[mA], bB = bias[mA + 8];
        float* rowA = g_bcdt + ((size_t)(b * O3S + mA)) * NN + n0;
        float* rowB = rowA + (size_t)8 * NN;
#pragma unroll
        for (int ni = 0; ni < 4; ni++) {
            int n = wn * 32 + ni * 8 + qcol;
            *(float2*)(rowA + n) = make_float2(acc[mi][ni][0] + bA, acc[mi][ni][1] + bA);
            *(float2*)(rowB + n) = make_float2(acc[mi][ni][2] + bB, acc[mi][ni][3] + bB);
        }
    }
}

// ============================================================================
// Kernel 2a: FUSED depthwise conv (B_ + dt) + exp + multiply, VECTORIZED.
// 4-plane ring buffer: ONE sync per dz, load issued before compute.
// NOTE: guard is dz < DD-1 (NOT dz+2 < DD): the out-of-range z=DD call
// zero-fills the top halo plane that dz=DD-1's kd=2 tap reads.
// ============================================================================
__global__ void __launch_bounds__(256) conv_ab_kernel(
    const float* __restrict__ wdw, const float* __restrict__ bdw)
{
    extern __shared__ __align__(16) float cvs[];
    float* sB = cvs;                    // [4][34][68]
    float* sD = cvs + 4 * CV_PLANE;     // [4][34][68]
    __shared__ float wB[27], wD[27];
    __shared__ float red[8];

    const int hhalf = blockIdx.x;
    const int s_ = blockIdx.y;
    const int b  = blockIdx.z;
    const int h0 = hhalf * 32;
    const int tid = threadIdx.x;
    const int chB = s_;
    const int chD = 128 + s_;

    const float* baseB = g_bcdt + ((size_t)(b * O3S + chB)) * NN;
    const float* baseD = g_bcdt + ((size_t)(b * O3S + chD)) * NN;

    if (tid < 27) wB[tid] = wdw[chB * 27 + tid];
    else if (tid >= 32 && tid < 59) wD[tid - 32] = wdw[chD * 27 + (tid - 32)];
    const float biasB = bdw[chB];
    const float biasD = bdw[chD];

    // slot(z) = (z+1) & 3 ; out-of-range z writes zeros (halo)
    auto loadplane = [&](int z, int slot) {
        for (int idx = tid; idx < 34 * 66; idx += 256) {
            int ih = idx / 66, iw = idx % 66;
            int h = h0 - 1 + ih, w = iw - 1;
            bool ok = ((unsigned)z < (unsigned)DD) && ((unsigned)h < (unsigned)HH)
                      && ((unsigned)w < (unsigned)WW);
            size_t g = (size_t)z * (HH * WW) + (size_t)h * WW + w;
            sB[slot * CV_PLANE + ih * CV_STRIDE + iw] = ok ? baseB[g] : 0.f;
            sD[slot * CV_PLANE + ih * CV_STRIDE + iw] = ok ? baseD[g] : 0.f;
        }
    };
    loadplane(-1, 0);
    loadplane(0, 1);
    loadplane(1, 2);
    __syncthreads();

    const int w4 = (tid & 15) * 4;      // 0..60
    const int hl = (tid >> 4) * 2;      // 0,2,..,30
    float* abp = g_ab + ((size_t)(b * SS + s_)) * NN;
    float lsum = 0.f;

    for (int dz = 0; dz < DD; dz++) {
        // issue next plane load FIRST (ring slot (dz+3)&3 is unused by compute);
        // z=DD at dz=DD-2 zero-fills the top halo plane.
        if (dz < DD - 1) loadplane(dz + 2, (dz + 3) & 3);

        float aB0[4], aB1[4], aD0[4], aD1[4];
#pragma unroll
        for (int j = 0; j < 4; j++) {
            aB0[j] = biasB; aB1[j] = biasB;
            aD0[j] = biasD; aD1[j] = biasD;
        }
#pragma unroll
        for (int kd = 0; kd < 3; kd++) {
            const int pl = (dz + kd) & 3;       // slot(dz-1+kd) = (dz+kd)&3
            const float* bb = sB + pl * CV_PLANE;
            const float* db = sD + pl * CV_PLANE;
#pragma unroll
            for (int q = 0; q < 4; q++) {
                const float* rowb = bb + (hl + q) * CV_STRIDE + w4;
                const float* rowd = db + (hl + q) * CV_STRIDE + w4;
                float4 u0 = *(const float4*)(rowb);
                float4 u1 = *(const float4*)(rowb + 4);
                float4 t0 = *(const float4*)(rowd);
                float4 t1 = *(const float4*)(rowd + 4);
                float vB[8] = {u0.x, u0.y, u0.z, u0.w, u1.x, u1.y, u1.z, u1.w};
                float vD[8] = {t0.x, t0.y, t0.z, t0.w, t1.x, t1.y, t1.z, t1.w};
                if (q < 3) {
#pragma unroll
                    for (int kw = 0; kw < 3; kw++) {
                        float wtb = wB[kd * 9 + q * 3 + kw];
                        float wtd = wD[kd * 9 + q * 3 + kw];
#pragma unroll
                        for (int j = 0; j < 4; j++) {
                            aB0[j] = fmaf(vB[j + kw], wtb, aB0[j]);
                            aD0[j] = fmaf(vD[j + kw], wtd, aD0[j]);
                        }
                    }
                }
                if (q >= 1) {
#pragma unroll
                    for (int kw = 0; kw < 3; kw++) {
                        float wtb = wB[kd * 9 + (q - 1) * 3 + kw];
                        float wtd = wD[kd * 9 + (q - 1) * 3 + kw];
#pragma unroll
                        for (int j = 0; j < 4; j++) {
                            aB1[j] = fmaf(vB[j + kw], wtb, aB1[j]);
                            aD1[j] = fmaf(vD[j + kw], wtd, aD1[j]);
                        }
                    }
                }
            }
        }
        float e0[4], e1[4];
#pragma unroll
        for (int j = 0; j < 4; j++) {
            e0[j] = fexp(aD0[j]);
            e1[j] = fexp(aD1[j]);
            lsum += e0[j] + e1[j];
        }
        float* o0 = abp + (size_t)dz * (HH * WW) + (h0 + hl) * WW + w4;
        *(float4*)(o0)      = make_float4(e0[0] * aB0[0], e0[1] * aB0[1],
                                          e0[2] * aB0[2], e0[3] * aB0[3]);
        *(float4*)(o0 + WW) = make_float4(e1[0] * aB1[0], e1[1] * aB1[1],
                                          e1[2] * aB1[2], e1[3] * aB1[3]);
        __syncthreads();    // one barrier per dz
    }

    const int lane = tid & 31, warp = tid >> 5;
#pragma unroll
    for (int o = 16; o > 0; o >>= 1) lsum += __shfl_xor_sync(0xffffffffu, lsum, o);
    if (lane == 0) red[warp] = lsum;
    __syncthreads();
    if (tid == 0) {
        float v = red[0] + red[1] + red[2] + red[3] + red[4] + red[5] + red[6] + red[7];
        g_psum[(b * SS + s_) * 2 + hhalf] = v;
    }
}

// ============================================================================
// Kernel 2b: depthwise conv for C_ channels, VECTORIZED, 4-plane ring.
// Same dz < DD-1 guard (zero-fill top halo).
// ============================================================================
__global__ void __launch_bounds__(256) conv_c_kernel(
    const float* __restrict__ wdw, const float* __restrict__ bdw)
{
    __shared__ __align__(16) float s[4 * CV_PLANE];
    __shared__ float wt[27];

    const int hhalf = blockIdx.x;
    const int s_ = blockIdx.y;
    const int b  = blockIdx.z;
    const int h0 = hhalf * 32;
    const int tid = threadIdx.x;
    const int ch = 64 + s_;

    const float* base = g_bcdt + ((size_t)(b * O3S + ch)) * NN;
    if (tid < 27) wt[tid] = wdw[ch * 27 + tid];
    const float bbv = bdw[ch];

    auto loadplane = [&](int z, int slot) {
        for (int idx = tid; idx < 34 * 66; idx += 256) {
            int ih = idx / 66, iw = idx % 66;
            int h = h0 - 1 + ih, w = iw - 1;
            bool ok = ((unsigned)z < (unsigned)DD) && ((unsigned)h < (unsigned)HH)
                      && ((unsigned)w < (unsigned)WW);
            size_t g = (size_t)z * (HH * WW) + (size_t)h * WW + w;
            s[slot * CV_PLANE + ih * CV_STRIDE + iw] = ok ? base[g] : 0.f;
        }
    };
    loadplane(-1, 0);
    loadplane(0, 1);
    loadplane(1, 2);
    __syncthreads();

    const int w4 = (tid & 15) * 4;
    const int hl = (tid >> 4) * 2;
    float* outp = g_c + ((size_t)(b * SS + s_)) * NN;

    for (int dz = 0; dz < DD; dz++) {
        if (dz < DD - 1) loadplane(dz + 2, (dz + 3) & 3);

        float a0[4], a1[4];
#pragma unroll
        for (int j = 0; j < 4; j++) { a0[j] = bbv; a1[j] = bbv; }
#pragma unroll
        for (int kd = 0; kd < 3; kd++) {
            const int pl = (dz + kd) & 3;
            const float* bb = s + pl * CV_PLANE;
#pragma unroll
            for (int q = 0; q < 4; q++) {
                const float* row = bb + (hl + q) * CV_STRIDE + w4;
                float4 u0 = *(const float4*)(row);
                float4 u1 = *(const float4*)(row + 4);
                float v[8] = {u0.x, u0.y, u0.z, u0.w, u1.x, u1.y, u1.z, u1.w};
                if (q < 3) {
#pragma unroll
                    for (int kw = 0; kw < 3; kw++) {
                        float wv = wt[kd * 9 + q * 3 + kw];
#pragma unroll
                        for (int j = 0; j < 4; j++)
                            a0[j] = fmaf(v[j + kw], wv, a0[j]);
                    }
                }
                if (q >= 1) {
#pragma unroll
                    for (int kw = 0; kw < 3; kw++) {
                        float wv = wt[kd * 9 + (q - 1) * 3 + kw];
#pragma unroll
                        for (int j = 0; j < 4; j++)
                            a1[j] = fmaf(v[j + kw], wv, a1[j]);
                    }
                }
            }
        }
        float* o0 = outp + (size_t)dz * (HH * WW) + (h0 + hl) * WW + w4;
        *(float4*)(o0)      = make_float4(a0[0], a0[1], a0[2], a0[3]);
        *(float4*)(o0 + WW) = make_float4(a1[0], a1[1], a1[2], a1[3]);
        __syncthreads();
    }
}

// ============================================================================
// Kernel 4 (HMMA): h_unnorm partials = sum_n x * AB_unnorm
// BM=64(c), BN=64(s), BK=32. Double buffer + 8-wide STS.128 repack.
// ============================================================================
__global__ void __launch_bounds__(256) hgemm_mma_kernel(const float* __restrict__ x)
{
    __shared__ __align__(16) uint16_t As_hi[2 * 64 * A_STRIDE];
    __shared__ __align__(16) uint16_t As_lo[2 * 64 * A_STRIDE];
    __shared__ __align__(16) uint16_t Bs_hi[2 * 64 * HB_STRIDE];
    __shared__ __align__(16) uint16_t Bs_lo[2 * 64 * HB_STRIDE];

    const int c0 = blockIdx.x * 64;          // fastest -> L2 sharing of AB tile
    const int ks = blockIdx.y;               // 0..63
    const int b  = blockIdx.z;
    const int nbase = ks * (NN / KSPLIT_H);  // 1024 chunk
    const int tid  = threadIdx.x;
    const int wid  = tid >> 5;
    const int lane = tid & 31;
    const int wm = wid >> 2;
    const int wn = wid & 3;

    const float* xb = x + ((size_t)(b * CC + c0)) * NN;
    const float* ab = g_ab + (size_t)b * SS * NN;
    const uint32_t as_hi0 = smem_u32(As_hi), as_lo0 = smem_u32(As_lo);
    const uint32_t bs_hi0 = smem_u32(Bs_hi), bs_lo0 = smem_u32(Bs_lo);

    // 8-wide k per thread: row lr2 (0..63), k offset lk8 (0,8,16,24)
    const int lr2 = tid >> 2;
    const int lk8 = (tid & 3) << 3;

    float acc[2][2][4];
#pragma unroll
    for (int i = 0; i < 2; i++)
#pragma unroll
        for (int j = 0; j < 2; j++)
#pragma unroll
            for (int q = 0; q < 4; q++) acc[i][j][q] = 0.f;

    float4 rx[2], rab[2];
    rx[0]  = *(const float4*)(xb + (size_t)lr2 * NN + nbase + lk8);
    rx[1]  = *(const float4*)(xb + (size_t)lr2 * NN + nbase + lk8 + 4);
    rab[0] = *(const float4*)(ab + (size_t)lr2 * NN + nbase + lk8);
    rab[1] = *(const float4*)(ab + (size_t)lr2 * NN + nbase + lk8 + 4);

    const int ITERS = (NN / KSPLIT_H) / 32;   // 32
    for (int it = 0; it < ITERS; it++) {
        const int buf = it & 1;
        uint16_t* Ah = As_hi + buf * (64 * A_STRIDE);
        uint16_t* Al = As_lo + buf * (64 * A_STRIDE);
        uint16_t* Bh = Bs_hi + buf * (64 * HB_STRIDE);
        uint16_t* Bl = Bs_lo + buf * (64 * HB_STRIDE);

        {
            uint32_t h0, l0, h1, l1, h2, l2, h3, l3;
            split2(rx[0].x, rx[0].y, h0, l0);
            split2(rx[0].z, rx[0].w, h1, l1);
            split2(rx[1].x, rx[1].y, h2, l2);
            split2(rx[1].z, rx[1].w, h3, l3);
            int off = lr2 * A_STRIDE + lk8;
            *(uint4*)(Ah + off) = make_uint4(h0, h1, h2, h3);
            *(uint4*)(Al + off) = make_uint4(l0, l1, l2, l3);
            split2(rab[0].x, rab[0].y, h0, l0);
            split2(rab[0].z, rab[0].w, h1, l1);
            split2(rab[1].x, rab[1].y, h2, l2);
            split2(rab[1].z, rab[1].w, h3, l3);
            off = lr2 * HB_STRIDE + lk8;
            *(uint4*)(Bh + off) = make_uint4(h0, h1, h2, h3);
            *(uint4*)(Bl + off) = make_uint4(l0, l1, l2, l3);
        }
        __syncthreads();     // single barrier per iteration (double buffer)

        if (it + 1 < ITERS) {
            const int nb2 = nbase + (it + 1) * 32;
            rx[0]  = *(const float4*)(xb + (size_t)lr2 * NN + nb2 + lk8);
            rx[1]  = *(const float4*)(xb + (size_t)lr2 * NN + nb2 + lk8 + 4);
            rab[0] = *(const float4*)(ab + (size_t)lr2 * NN + nb2 + lk8);
            rab[1] = *(const float4*)(ab + (size_t)lr2 * NN + nb2 + lk8 + 4);
        }

        const uint32_t ah = as_hi0 + buf * HG_ABUF, al = as_lo0 + buf * HG_ABUF;
        const uint32_t bh = bs_hi0 + buf * HG_BBUF, bl = bs_lo0 + buf * HG_BBUF;
#pragma unroll
        for (int kq = 0; kq < 2; kq++) {
            uint32_t a_hi[2][4], a_lo[2][4];
            const int arow = lane & 15;
            const int acol = (lane >> 4) << 3;
#pragma unroll
            for (int mi = 0; mi < 2; mi++) {
                uint32_t off = (uint32_t)((wm * 32 + mi * 16 + arow) * A_STRIDE
                                          + kq * 16 + acol) * 2;
                ldsm_x4(a_hi[mi], ah + off);
                ldsm_x4(a_lo[mi], al + off);
            }
            uint32_t b_hi[2][2], b_lo[2][2];
            const int l = lane & 15;
            const int srow = l & 7;
            const int koff = (l >> 3) << 3;
#pragma unroll
            for (int ni = 0; ni < 2; ni++) {
                uint32_t off = (uint32_t)((wn * 16 + ni * 8 + srow) * HB_STRIDE
                                          + kq * 16 + koff) * 2;
                ldsm_x2(b_hi[ni], bh + off);
                ldsm_x2(b_lo[ni], bl + off);
            }
#pragma unroll
            for (int mi = 0; mi < 2; mi++)
#pragma unroll
                for (int ni = 0; ni < 2; ni++) {
                    mma_bf16(acc[mi][ni], a_hi[mi], b_hi[ni]);
                    mma_bf16(acc[mi][ni], a_hi[mi], b_lo[ni]);
                    mma_bf16(acc[mi][ni], a_lo[mi], b_hi[ni]);
                }
        }
    }

    float* dst = g_hpart + (size_t)ks * (BB * CC * SS);
    const int qrow = lane >> 2;
    const int qcol = (lane & 3) << 1;
#pragma unroll
    for (int mi = 0; mi < 2; mi++) {
        int cA = c0 + wm * 32 + mi * 16 + qrow;
#pragma unroll
        for (int ni = 0; ni < 2; ni++) {
            int sA = wn * 16 + ni * 8 + qcol;
            float* pA = dst + ((size_t)(b * CC + cA)) * SS + sA;
            float* pB = dst + ((size_t)(b * CC + cA + 8)) * SS + sA;
            *(float2*)pA = make_float2(acc[mi][ni][0], acc[mi][ni][1]);
            *(float2*)pB = make_float2(acc[mi][ni][2], acc[mi][ni][3]);
        }
    }
}

// reduction of split-K partials + deferred softmax normalization
__global__ void __launch_bounds__(256) hreduce_kernel()
{
    int i = blockIdx.x * 256 + threadIdx.x;   // ((b*CC+c)*SS+s) < 65536
    int b = i >> 14;
    int s = i & 63;
    const float* ps = &g_psum[(b * SS + s) * 2];
    float inv = 1.f / (ps[0] + ps[1]);
    float sum = 0.f;
#pragma unroll
    for (int ks = 0; ks < KSPLIT_H; ks++)
        sum += g_hpart[(size_t)ks * (BB * CC * SS) + i];
    g_h[i] = sum * inv;
}

// ============================================================================
// Kernel 5: hz = W_hz @ h + b_hz ; h3 = h2*silu(z) + h2*Dp
// ============================================================================
__global__ void __launch_bounds__(256) e1_kernel(
    const float* __restrict__ Whz, const float* __restrict__ bhz,
    const float* __restrict__ Dp)
{
    const int b = blockIdx.y;
    const int o = blockIdx.x * 4 + (threadIdx.x >> 6);
    const int s_ = threadIdx.x & 63;
    const float* hb = g_h + (size_t)b * CC * SS;
    const float* w1 = Whz + (size_t)o * 256;
    const float* w2 = Whz + (size_t)(o + 256) * 256;
    float a1 = bhz[o], a2 = bhz[o + 256];
    for (int c = 0; c < 256; c++) {
        float hv = hb[c * 64 + s_];
        a1 += w1[c] * hv;
        a2 += w2[c] * hv;
    }
    float sig = 1.f / (1.f + __expf(-a2));
    g_h3[((size_t)b * CC + o) * SS + s_] = a1 * (a2 * sig) + a1 * Dp[0];
}

// Kernel 6: h4 = W_out @ h3 + b_out ; write to scratch + output tail
__global__ void __launch_bounds__(256) e2_kernel(
    const float* __restrict__ Wout, const float* __restrict__ bout,
    float* __restrict__ out)
{
    const int b = blockIdx.y;
    const int o = blockIdx.x * 4 + (threadIdx.x >> 6);
    const int s_ = threadIdx.x & 63;
    const float* hb = g_h3 + (size_t)b * CC * SS;
    const float* w1 = Wout + (size_t)o * 256;
    float acc = bout[o];
    for (int c = 0; c < 256; c++)
        acc += w1[c] * hb[c * 64 + s_];
    size_t idx = ((size_t)b * CC + o) * SS + s_;
    g_h4[idx] = acc;
    out[YSIZE + idx] = acc;
}

// ============================================================================
// Kernel 7 (HMMA): y[b,c,n] = sum_s h4[b,c,s] * C_[b,s,n]
// BM=64, BN=128, K=64 (2 x BK=32). Double buffer + reg prefetch (1 sync/iter).
// ============================================================================
__global__ void __launch_bounds__(256) ygemm_mma_kernel(float* __restrict__ y)
{
    __shared__ __align__(16) uint16_t As_hi[2 * 64 * A_STRIDE];
    __shared__ __align__(16) uint16_t As_lo[2 * 64 * A_STRIDE];
    __shared__ __align__(16) uint16_t Bs_hi[2 * 32 * B_STRIDE];
    __shared__ __align__(16) uint16_t Bs_lo[2 * 32 * B_STRIDE];

    const int m0 = blockIdx.x * 64;     // fastest -> L2 sharing of C_ tile
    const int n0 = blockIdx.y * 128;
    const int b  = blockIdx.z;
    const int tid  = threadIdx.x;
    const int wid  = tid >> 5;
    const int lane = tid & 31;
    const int wm = wid >> 2;
    const int wn = wid & 3;

    const float* h4b = g_h4 + (size_t)b * CC * SS;
    const float* cp  = g_c + (size_t)b * SS * NN;
    const uint32_t as_hi0 = smem_u32(As_hi), as_lo0 = smem_u32(As_lo);
    const uint32_t bs_hi0 = smem_u32(Bs_hi), bs_lo0 = smem_u32(Bs_lo);

    const int am = tid >> 3, ak = (tid & 7) << 2;
    const int krow0 = tid >> 5;
    const int nloc  = (tid & 31) << 2;

    float acc[2][4][4];
#pragma unroll
    for (int i = 0; i < 2; i++)
#pragma unroll
        for (int j = 0; j < 4; j++)
#pragma unroll
            for (int q = 0; q < 4; q++) acc[i][j][q] = 0.f;

    // prefetch tile 0
    float4 ra[2], rb[4];
#pragma unroll
    for (int r = 0; r < 2; r++)
        ra[r] = *(const float4*)(h4b + (size_t)(m0 + am + r * 32) * SS + ak);
#pragma unroll
    for (int r = 0; r < 4; r++)
        rb[r] = *(const float4*)(cp + (size_t)(krow0 + r * 8) * NN + n0 + nloc);

    for (int it = 0; it < 2; it++) {
        const int buf = it;
        uint16_t* Ah = As_hi + buf * (64 * A_STRIDE);
        uint16_t* Al = As_lo + buf * (64 * A_STRIDE);
        uint16_t* Bh = Bs_hi + buf * (32 * B_STRIDE);
        uint16_t* Bl = Bs_lo + buf * (32 * B_STRIDE);

#pragma unroll
        for (int r = 0; r < 2; r++) {
            float4 v = ra[r];
            uint32_t h01, l01, h23, l23;
            split2(v.x, v.y, h01, l01);
            split2(v.z, v.w, h23, l23);
            int off = (am + r * 32) * A_STRIDE + ak;
            *(uint2*)(Ah + off) = make_uint2(h01, h23);
            *(uint2*)(Al + off) = make_uint2(l01, l23);
        }
#pragma unroll
        for (int r = 0; r < 4; r++) {
            float4 v = rb[r];
            uint32_t h01, l01, h23, l23;
            split2(v.x, v.y, h01, l01);
            split2(v.z, v.w, h23, l23);
            int off = (krow0 + r * 8) * B_STRIDE + nloc;
            *(uint2*)(Bh + off) = make_uint2(h01, h23);
            *(uint2*)(Bl + off) = make_uint2(l01, l23);
        }
        __syncthreads();

        if (it == 0) {
#pragma unroll
            for (int r = 0; r < 2; r++)
                ra[r] = *(const float4*)(h4b + (size_t)(m0 + am + r * 32) * SS + 32 + ak);
#pragma unroll
            for (int r = 0; r < 4; r++)
                rb[r] = *(const float4*)(cp + (size_t)(32 + krow0 + r * 8) * NN + n0 + nloc);
        }

        const uint32_t ah = as_hi0 + buf * YG_ABUF, al = as_lo0 + buf * YG_ABUF;
        const uint32_t bh = bs_hi0 + buf * YG_BBUF, bl = bs_lo0 + buf * YG_BBUF;
#pragma unroll
        for (int ks = 0; ks < 2; ks++) {
            uint32_t a_hi[2][4], a_lo[2][4];
            const int arow = lane & 15;
            const int acol = (lane >> 4) << 3;
#pragma unroll
            for (int mi = 0; mi < 2; mi++) {
                uint32_t off = (uint32_t)((wm * 32 + mi * 16 + arow) * A_STRIDE
                                          + ks * 16 + acol) * 2;
                ldsm_x4(a_hi[mi], ah + off);
                ldsm_x4(a_lo[mi], al + off);
            }
            uint32_t b_hi[4][2], b_lo[4][2];
            const int brow = lane & 15;
#pragma unroll
            for (int ni = 0; ni < 4; ni++) {
                uint32_t off = (uint32_t)((ks * 16 + brow) * B_STRIDE
                                          + wn * 32 + ni * 8) * 2;
                ldsm_x2_t(b_hi[ni], bh + off);
                ldsm_x2_t(b_lo[ni], bl + off);
            }
#pragma unroll
            for (int mi = 0; mi < 2; mi++)
#pragma unroll
                for (int ni = 0; ni < 4; ni++) {
                    mma_bf16(acc[mi][ni], a_hi[mi], b_hi[ni]);
                    mma_bf16(acc[mi][ni], a_hi[mi], b_lo[ni]);
                    mma_bf16(acc[mi][ni], a_lo[mi], b_hi[ni]);
                }
        }
    }

    const int qrow = lane >> 2;
    const int qcol = (lane & 3) << 1;
#pragma unroll
    for (int mi = 0; mi < 2; mi++) {
        int mA = m0 + wm * 32 + mi * 16 + qrow;
        float* rowA = y + ((size_t)(b * CC + mA)) * NN + n0;
        float* rowB = rowA + (size_t)8 * NN;
#pragma unroll
        for (int ni = 0; ni < 4; ni++) {
            int n = wn * 32 + ni * 8 + qcol;
            *(float2*)(rowA + n) = make_float2(acc[mi][ni][0], acc[mi][ni][1]);
            *(float2*)(rowB + n) = make_float2(acc[mi][ni][2], acc[mi][ni][3]);
        }
    }
}

// ============================================================================
extern "C" void kernel_launch(void* const* d_in, const int* in_sizes, int n_in,
                              void* d_out, int out_size)
{
    const float* x      = (const float*)d_in[0];
    const float* W_bcdt = (const float*)d_in[1];
    const float* b_bcdt = (const float*)d_in[2];
    const float* W_dw   = (const float*)d_in[3];
    const float* b_dw   = (const float*)d_in[4];
    const float* W_hz   = (const float*)d_in[5];
    const float* b_hz   = (const float*)d_in[6];
    const float* W_out  = (const float*)d_in[7];
    const float* b_out  = (const float*)d_in[8];
    // d_in[9] = A : unused (softmax shift invariance along the reduced axis)
    const float* Dp     = (const float*)d_in[10];
    float* out = (float*)d_out;

    // side stream + fork/join events (created once; no device allocs)
    static cudaStream_t s1 = nullptr;
    static cudaEvent_t ev_g1 = nullptr, ev_c = nullptr;
    if (!s1) {
        cudaStreamCreateWithFlags(&s1, cudaStreamNonBlocking);
        cudaEventCreateWithFlags(&ev_g1, cudaEventDisableTiming);
        cudaEventCreateWithFlags(&ev_c, cudaEventDisableTiming);
        cudaFuncSetAttribute(conv_ab_kernel,
                             cudaFuncAttributeMaxDynamicSharedMemorySize, CVAB_SMEM);
    }

    gemm1_mma_kernel<<<dim3(3, NN / 128, BB), 256>>>(x, W_bcdt, b_bcdt);
    cudaEventRecord(ev_g1, 0);

    // side stream: conv_c overlaps with conv_ab/hgemm/hreduce/e1/e2
    cudaStreamWaitEvent(s1, ev_g1, 0);
    conv_c_kernel<<<dim3(2, SS, BB), 256, 0, s1>>>(W_dw, b_dw);
    cudaEventRecord(ev_c, s1);

    conv_ab_kernel<<<dim3(2, SS, BB), 256, CVAB_SMEM>>>(W_dw, b_dw);
    hgemm_mma_kernel<<<dim3(4, KSPLIT_H, BB), 256>>>(x);
    hreduce_kernel<<<256, 256>>>();
    e1_kernel<<<dim3(64, BB), 256>>>(W_hz, b_hz, Dp);
    e2_kernel<<<dim3(64, BB), 256>>>(W_out, b_out, out);

    cudaStreamWaitEvent(0, ev_c, 0);
    ygemm_mma_kernel<<<dim3(4, NN / 128, BB), 256>>>(out);
}

// round 16
// speedup vs baseline: 1.3202x; 1.0152x over previous
#include <cuda_runtime.h>
#include <cuda_bf16.h>
#include <cstdint>
#include <cstddef>

// Problem constants
#define BB   4
#define CC   256      // D_MODEL = D_INNER
#define SS   64
#define DD   16
#define HH   64
#define WW   64
#define NN   65536    // D*H*W
#define O3S  192      // 3*S
#define KSPLIT_H 64   // split-K factor for h-GEMM

static const size_t YSIZE = (size_t)BB * CC * NN;   // 67108864

// ---- static scratch (no runtime allocation allowed) ----
__device__ float g_bcdt[(size_t)BB * O3S * NN];   // GEMM1 output (pre-conv)
__device__ float g_ab[(size_t)BB * SS * NN];      // AB_unnorm = exp(conv dt)*conv B_
__device__ float g_c [(size_t)BB * SS * NN];      // conv C_ channels
__device__ float g_hpart[(size_t)KSPLIT_H * BB * CC * SS];
__device__ float g_psum[BB * SS * 2];             // per-h-half exp-sums
__device__ float g_h [BB * CC * SS];
__device__ float g_h3[BB * CC * SS];
__device__ float g_h4[BB * CC * SS];

// ============================================================================
// helpers
// ============================================================================
__device__ __forceinline__ uint32_t smem_u32(const void* p) {
    uint32_t a;
    asm("{ .reg .u64 t; cvta.to.shared.u64 t, %1; cvt.u32.u64 %0, t; }" : "=r"(a) : "l"(p));
    return a;
}
__device__ __forceinline__ void ldsm_x4(uint32_t* r, uint32_t addr) {
    asm volatile("ldmatrix.sync.aligned.m8n8.x4.shared.b16 {%0,%1,%2,%3}, [%4];"
        : "=r"(r[0]), "=r"(r[1]), "=r"(r[2]), "=r"(r[3]) : "r"(addr));
}
__device__ __forceinline__ void ldsm_x2(uint32_t* r, uint32_t addr) {
    asm volatile("ldmatrix.sync.aligned.m8n8.x2.shared.b16 {%0,%1}, [%2];"
        : "=r"(r[0]), "=r"(r[1]) : "r"(addr));
}
__device__ __forceinline__ void ldsm_x2_t(uint32_t* r, uint32_t addr) {
    asm volatile("ldmatrix.sync.aligned.m8n8.x2.trans.shared.b16 {%0,%1}, [%2];"
        : "=r"(r[0]), "=r"(r[1]) : "r"(addr));
}
__device__ __forceinline__ void mma_bf16(float* c, const uint32_t* a, const uint32_t* b) {
    asm volatile(
        "mma.sync.aligned.m16n8k16.row.col.f32.bf16.bf16.f32 "
        "{%0,%1,%2,%3}, {%4,%5,%6,%7}, {%8,%9}, {%0,%1,%2,%3};"
        : "+f"(c[0]), "+f"(c[1]), "+f"(c[2]), "+f"(c[3])
        : "r"(a[0]), "r"(a[1]), "r"(a[2]), "r"(a[3]), "r"(b[0]), "r"(b[1]));
}
__device__ __forceinline__ void split2(float v0, float v1, uint32_t& hi, uint32_t& lo) {
    __nv_bfloat16 h0 = __float2bfloat16(v0), h1 = __float2bfloat16(v1);
    float r0 = v0 - __bfloat162float(h0), r1 = v1 - __bfloat162float(h1);
    __nv_bfloat162 hh = __halves2bfloat162(h0, h1);
    __nv_bfloat162 ll = __floats2bfloat162_rn(r0, r1);
    hi = *(uint32_t*)&hh; lo = *(uint32_t*)&ll;
}
// FMA-pipe exp (poly 2^f on [-0.5,0.5], ~2e-9 rel err), clamped both sides
__device__ __forceinline__ float fexp(float x) {
    float t = fminf(fmaxf(x * 1.4426950408889634f, -125.0f), 125.0f);
    float n = rintf(t);
    float f = t - n;
    float p = 1.5403530393381609e-4f;
    p = fmaf(p, f, 1.3333558146428443e-3f);
    p = fmaf(p, f, 9.618129107628477e-3f);
    p = fmaf(p, f, 5.550410866482158e-2f);
    p = fmaf(p, f, 2.402265069591999e-1f);
    p = fmaf(p, f, 6.931471805599453e-1f);
    p = fmaf(p, f, 1.0f);
    return __int_as_float(((int)n + 127) << 23) * p;
}

#define A_STRIDE 40    // halves per 32-k row (32 + 8 pad)
#define B_STRIDE 136   // halves per 128-n row (128 + 8 pad)
#define HB_STRIDE 40

// conv smem geometry: 34 rows x 68 floats (16B-aligned rows), 4-plane ring
#define CV_STRIDE 68
#define CV_PLANE  (34 * CV_STRIDE)
#define CVAB_SMEM (2 * 4 * CV_PLANE * 4)   // 73984 bytes (B + D arrays)

// double-buffer byte offsets
#define G1_ABUF (64 * A_STRIDE * 2)
#define G1_BBUF (32 * B_STRIDE * 2)
#define HG_ABUF (64 * A_STRIDE * 2)
#define HG_BBUF (64 * HB_STRIDE * 2)
#define YG_ABUF (64 * A_STRIDE * 2)
#define YG_BBUF (32 * B_STRIDE * 2)

// ============================================================================
// Kernel 1 (HMMA): BCdt = W_bcdt(192x256) @ x(b,256,N) + b_bcdt
// BM=64, BN=128, BK=32. Reg prefetch + smem double buffer (1 sync/iter).
// ============================================================================
__global__ void __launch_bounds__(256) gemm1_mma_kernel(
    const float* __restrict__ x, const float* __restrict__ W,
    const float* __restrict__ bias)
{
    __shared__ __align__(16) uint16_t As_hi[2 * 64 * A_STRIDE];
    __shared__ __align__(16) uint16_t As_lo[2 * 64 * A_STRIDE];
    __shared__ __align__(16) uint16_t Bs_hi[2 * 32 * B_STRIDE];
    __shared__ __align__(16) uint16_t Bs_lo[2 * 32 * B_STRIDE];

    const int m0 = blockIdx.x * 64;     // fastest -> L2 sharing of x tile
    const int n0 = blockIdx.y * 128;
    const int b  = blockIdx.z;
    const int tid  = threadIdx.x;
    const int wid  = tid >> 5;
    const int lane = tid & 31;
    const int wm = wid >> 2;
    const int wn = wid & 3;

    const float* xb = x + (size_t)b * CC * NN;
    const uint32_t as_hi0 = smem_u32(As_hi), as_lo0 = smem_u32(As_lo);
    const uint32_t bs_hi0 = smem_u32(Bs_hi), bs_lo0 = smem_u32(Bs_lo);

    const int krow0 = tid >> 5;
    const int nloc  = (tid & 31) << 2;

    float acc[2][4][4];
#pragma unroll
    for (int i = 0; i < 2; i++)
#pragma unroll
        for (int j = 0; j < 4; j++)
#pragma unroll
            for (int q = 0; q < 4; q++) acc[i][j][q] = 0.f;

    float4 rbx[4];
#pragma unroll
    for (int r = 0; r < 4; r++)
        rbx[r] = *(const float4*)(xb + (size_t)(krow0 + r * 8) * NN + n0 + nloc);

    for (int it = 0; it < 8; it++) {
        const int k0 = it * 32;
        const int buf = it & 1;
        uint16_t* Ah = As_hi + buf * (64 * A_STRIDE);
        uint16_t* Al = As_lo + buf * (64 * A_STRIDE);
        uint16_t* Bh = Bs_hi + buf * (32 * B_STRIDE);
        uint16_t* Bl = Bs_lo + buf * (32 * B_STRIDE);

#pragma unroll
        for (int r = 0; r < 2; r++) {
            int f = tid + r * 256;
            int m = f >> 3, k = (f & 7) << 2;
            float4 v = *(const float4*)(W + (size_t)(m0 + m) * 256 + k0 + k);
            uint32_t h01, l01, h23, l23;
            split2(v.x, v.y, h01, l01);
            split2(v.z, v.w, h23, l23);
            int off = m * A_STRIDE + k;
            *(uint2*)(Ah + off) = make_uint2(h01, h23);
            *(uint2*)(Al + off) = make_uint2(l01, l23);
        }
#pragma unroll
        for (int r = 0; r < 4; r++) {
            float4 v = rbx[r];
            uint32_t h01, l01, h23, l23;
            split2(v.x, v.y, h01, l01);
            split2(v.z, v.w, h23, l23);
            int off = (krow0 + r * 8) * B_STRIDE + nloc;
            *(uint2*)(Bh + off) = make_uint2(h01, h23);
            *(uint2*)(Bl + off) = make_uint2(l01, l23);
        }
        __syncthreads();     // single barrier per iteration (double buffer)

        if (it < 7) {
#pragma unroll
            for (int r = 0; r < 4; r++)
                rbx[r] = *(const float4*)(xb + (size_t)(k0 + 32 + krow0 + r * 8) * NN + n0 + nloc);
        }

        const uint32_t ah = as_hi0 + buf * G1_ABUF, al = as_lo0 + buf * G1_ABUF;
        const uint32_t bh = bs_hi0 + buf * G1_BBUF, bl = bs_lo0 + buf * G1_BBUF;
#pragma unroll
        for (int ks = 0; ks < 2; ks++) {
            uint32_t a_hi[2][4], a_lo[2][4];
            const int arow = lane & 15;
            const int acol = (lane >> 4) << 3;
#pragma unroll
            for (int mi = 0; mi < 2; mi++) {
                uint32_t off = (uint32_t)((wm * 32 + mi * 16 + arow) * A_STRIDE
                                          + ks * 16 + acol) * 2;
                ldsm_x4(a_hi[mi], ah + off);
                ldsm_x4(a_lo[mi], al + off);
            }
            uint32_t b_hi[4][2], b_lo[4][2];
            const int brow = lane & 15;
#pragma unroll
            for (int ni = 0; ni < 4; ni++) {
                uint32_t off = (uint32_t)((ks * 16 + brow) * B_STRIDE
                                          + wn * 32 + ni * 8) * 2;
                ldsm_x2_t(b_hi[ni], bh + off);
                ldsm_x2_t(b_lo[ni], bl + off);
            }
#pragma unroll
            for (int mi = 0; mi < 2; mi++)
#pragma unroll
                for (int ni = 0; ni < 4; ni++) {
                    mma_bf16(acc[mi][ni], a_hi[mi], b_hi[ni]);
                    mma_bf16(acc[mi][ni], a_hi[mi], b_lo[ni]);
                    mma_bf16(acc[mi][ni], a_lo[mi], b_hi[ni]);
                }
        }
    }

    const int qrow = lane >> 2;
    const int qcol = (lane & 3) << 1;
#pragma unroll
    for (int mi = 0; mi < 2; mi++) {
        int mA = m0 + wm * 32 + mi * 16 + qrow;
        float bA = bias[mA], bB = bias[mA + 8];
        float* rowA = g_bcdt + ((size_t)(b * O3S + mA)) * NN + n0;
        float* rowB = rowA + (size_t)8 * NN;
#pragma unroll
        for (int ni = 0; ni < 4; ni++) {
            int n = wn * 32 + ni * 8 + qcol;
            *(float2*)(rowA + n) = make_float2(acc[mi][ni][0] + bA, acc[mi][ni][1] + bA);
            *(float2*)(rowB + n) = make_float2(acc[mi][ni][2] + bB, acc[mi][ni][3] + bB);
        }
    }
}

// ============================================================================
// Kernel 2a: FUSED depthwise conv (B_ + dt) + exp + multiply, VECTORIZED.
// 4-plane ring buffer: ONE sync per dz, load issued before compute.
// NOTE: guard is dz < DD-1: the out-of-range z=DD call zero-fills the top
// halo plane that dz=DD-1's kd=2 tap reads.
// ============================================================================
__global__ void __launch_bounds__(256) conv_ab_kernel(
    const float* __restrict__ wdw, const float* __restrict__ bdw)
{
    extern __shared__ __align__(16) float cvs[];
    float* sB = cvs;                    // [4][34][68]
    float* sD = cvs + 4 * CV_PLANE;     // [4][34][68]
    __shared__ float wB[27], wD[27];
    __shared__ float red[8];

    const int hhalf = blockIdx.x;
    const int s_ = blockIdx.y;
    const int b  = blockIdx.z;
    const int h0 = hhalf * 32;
    const int tid = threadIdx.x;
    const int chB = s_;
    const int chD = 128 + s_;

    const float* baseB = g_bcdt + ((size_t)(b * O3S + chB)) * NN;
    const float* baseD = g_bcdt + ((size_t)(b * O3S + chD)) * NN;

    if (tid < 27) wB[tid] = wdw[chB * 27 + tid];
    else if (tid >= 32 && tid < 59) wD[tid - 32] = wdw[chD * 27 + (tid - 32)];
    const float biasB = bdw[chB];
    const float biasD = bdw[chD];

    // slot(z) = (z+1) & 3 ; out-of-range z writes zeros (halo)
    auto loadplane = [&](int z, int slot) {
        for (int idx = tid; idx < 34 * 66; idx += 256) {
            int ih = idx / 66, iw = idx % 66;
            int h = h0 - 1 + ih, w = iw - 1;
            bool ok = ((unsigned)z < (unsigned)DD) && ((unsigned)h < (unsigned)HH)
                      && ((unsigned)w < (unsigned)WW);
            size_t g = (size_t)z * (HH * WW) + (size_t)h * WW + w;
            sB[slot * CV_PLANE + ih * CV_STRIDE + iw] = ok ? baseB[g] : 0.f;
            sD[slot * CV_PLANE + ih * CV_STRIDE + iw] = ok ? baseD[g] : 0.f;
        }
    };
    loadplane(-1, 0);
    loadplane(0, 1);
    loadplane(1, 2);
    __syncthreads();

    const int w4 = (tid & 15) * 4;      // 0..60
    const int hl = (tid >> 4) * 2;      // 0,2,..,30
    float* abp = g_ab + ((size_t)(b * SS + s_)) * NN;
    float lsum = 0.f;

    for (int dz = 0; dz < DD; dz++) {
        // issue next plane load FIRST; z=DD at dz=DD-2 zero-fills top halo.
        if (dz < DD - 1) loadplane(dz + 2, (dz + 3) & 3);

        float aB0[4], aB1[4], aD0[4], aD1[4];
#pragma unroll
        for (int j = 0; j < 4; j++) {
            aB0[j] = biasB; aB1[j] = biasB;
            aD0[j] = biasD; aD1[j] = biasD;
        }
#pragma unroll
        for (int kd = 0; kd < 3; kd++) {
            const int pl = (dz + kd) & 3;       // slot(dz-1+kd) = (dz+kd)&3
            const float* bb = sB + pl * CV_PLANE;
            const float* db = sD + pl * CV_PLANE;
#pragma unroll
            for (int q = 0; q < 4; q++) {
                const float* rowb = bb + (hl + q) * CV_STRIDE + w4;
                const float* rowd = db + (hl + q) * CV_STRIDE + w4;
                float4 u0 = *(const float4*)(rowb);
                float4 u1 = *(const float4*)(rowb + 4);
                float4 t0 = *(const float4*)(rowd);
                float4 t1 = *(const float4*)(rowd + 4);
                float vB[8] = {u0.x, u0.y, u0.z, u0.w, u1.x, u1.y, u1.z, u1.w};
                float vD[8] = {t0.x, t0.y, t0.z, t0.w, t1.x, t1.y, t1.z, t1.w};
                if (q < 3) {
#pragma unroll
                    for (int kw = 0; kw < 3; kw++) {
                        float wtb = wB[kd * 9 + q * 3 + kw];
                        float wtd = wD[kd * 9 + q * 3 + kw];
#pragma unroll
                        for (int j = 0; j < 4; j++) {
                            aB0[j] = fmaf(vB[j + kw], wtb, aB0[j]);
                            aD0[j] = fmaf(vD[j + kw], wtd, aD0[j]);
                        }
                    }
                }
                if (q >= 1) {
#pragma unroll
                    for (int kw = 0; kw < 3; kw++) {
                        float wtb = wB[kd * 9 + (q - 1) * 3 + kw];
                        float wtd = wD[kd * 9 + (q - 1) * 3 + kw];
#pragma unroll
                        for (int j = 0; j < 4; j++) {
                            aB1[j] = fmaf(vB[j + kw], wtb, aB1[j]);
                            aD1[j] = fmaf(vD[j + kw], wtd, aD1[j]);
                        }
                    }
                }
            }
        }
        float e0[4], e1[4];
#pragma unroll
        for (int j = 0; j < 4; j++) {
            e0[j] = fexp(aD0[j]);
            e1[j] = fexp(aD1[j]);
            lsum += e0[j] + e1[j];
        }
        float* o0 = abp + (size_t)dz * (HH * WW) + (h0 + hl) * WW + w4;
        *(float4*)(o0)      = make_float4(e0[0] * aB0[0], e0[1] * aB0[1],
                                          e0[2] * aB0[2], e0[3] * aB0[3]);
        *(float4*)(o0 + WW) = make_float4(e1[0] * aB1[0], e1[1] * aB1[1],
                                          e1[2] * aB1[2], e1[3] * aB1[3]);
        __syncthreads();    // one barrier per dz
    }

    const int lane = tid & 31, warp = tid >> 5;
#pragma unroll
    for (int o = 16; o > 0; o >>= 1) lsum += __shfl_xor_sync(0xffffffffu, lsum, o);
    if (lane == 0) red[warp] = lsum;
    __syncthreads();
    if (tid == 0) {
        float v = red[0] + red[1] + red[2] + red[3] + red[4] + red[5] + red[6] + red[7];
        g_psum[(b * SS + s_) * 2 + hhalf] = v;
    }
}

// ============================================================================
// Kernel 2b: depthwise conv for C_ channels, VECTORIZED, 4-plane ring.
// Same dz < DD-1 guard (zero-fill top halo).
// ============================================================================
__global__ void __launch_bounds__(256) conv_c_kernel(
    const float* __restrict__ wdw, const float* __restrict__ bdw)
{
    __shared__ __align__(16) float s[4 * CV_PLANE];
    __shared__ float wt[27];

    const int hhalf = blockIdx.x;
    const int s_ = blockIdx.y;
    const int b  = blockIdx.z;
    const int h0 = hhalf * 32;
    const int tid = threadIdx.x;
    const int ch = 64 + s_;

    const float* base = g_bcdt + ((size_t)(b * O3S + ch)) * NN;
    if (tid < 27) wt[tid] = wdw[ch * 27 + tid];
    const float bbv = bdw[ch];

    auto loadplane = [&](int z, int slot) {
        for (int idx = tid; idx < 34 * 66; idx += 256) {
            int ih = idx / 66, iw = idx % 66;
            int h = h0 - 1 + ih, w = iw - 1;
            bool ok = ((unsigned)z < (unsigned)DD) && ((unsigned)h < (unsigned)HH)
                      && ((unsigned)w < (unsigned)WW);
            size_t g = (size_t)z * (HH * WW) + (size_t)h * WW + w;
            s[slot * CV_PLANE + ih * CV_STRIDE + iw] = ok ? base[g] : 0.f;
        }
    };
    loadplane(-1, 0);
    loadplane(0, 1);
    loadplane(1, 2);
    __syncthreads();

    const int w4 = (tid & 15) * 4;
    const int hl = (tid >> 4) * 2;
    float* outp = g_c + ((size_t)(b * SS + s_)) * NN;

    for (int dz = 0; dz < DD; dz++) {
        if (dz < DD - 1) loadplane(dz + 2, (dz + 3) & 3);

        float a0[4], a1[4];
#pragma unroll
        for (int j = 0; j < 4; j++) { a0[j] = bbv; a1[j] = bbv; }
#pragma unroll
        for (int kd = 0; kd < 3; kd++) {
            const int pl = (dz + kd) & 3;
            const float* bb = s + pl * CV_PLANE;
#pragma unroll
            for (int q = 0; q < 4; q++) {
                const float* row = bb + (hl + q) * CV_STRIDE + w4;
                float4 u0 = *(const float4*)(row);
                float4 u1 = *(const float4*)(row + 4);
                float v[8] = {u0.x, u0.y, u0.z, u0.w, u1.x, u1.y, u1.z, u1.w};
                if (q < 3) {
#pragma unroll
                    for (int kw = 0; kw < 3; kw++) {
                        float wv = wt[kd * 9 + q * 3 + kw];
#pragma unroll
                        for (int j = 0; j < 4; j++)
                            a0[j] = fmaf(v[j + kw], wv, a0[j]);
                    }
                }
                if (q >= 1) {
#pragma unroll
                    for (int kw = 0; kw < 3; kw++) {
                        float wv = wt[kd * 9 + (q - 1) * 3 + kw];
#pragma unroll
                        for (int j = 0; j < 4; j++)
                            a1[j] = fmaf(v[j + kw], wv, a1[j]);
                    }
                }
            }
        }
        float* o0 = outp + (size_t)dz * (HH * WW) + (h0 + hl) * WW + w4;
        *(float4*)(o0)      = make_float4(a0[0], a0[1], a0[2], a0[3]);
        *(float4*)(o0 + WW) = make_float4(a1[0], a1[1], a1[2], a1[3]);
        __syncthreads();
    }
}

// ============================================================================
// Kernel 4 (HMMA): h_unnorm partials = sum_n x * AB_unnorm
// BM=64(c), BN=64(s), BK=32. Double buffer, R13 4-wide uint2 store layout.
// ============================================================================
__global__ void __launch_bounds__(256) hgemm_mma_kernel(const float* __restrict__ x)
{
    __shared__ __align__(16) uint16_t As_hi[2 * 64 * A_STRIDE];
    __shared__ __align__(16) uint16_t As_lo[2 * 64 * A_STRIDE];
    __shared__ __align__(16) uint16_t Bs_hi[2 * 64 * HB_STRIDE];
    __shared__ __align__(16) uint16_t Bs_lo[2 * 64 * HB_STRIDE];

    const int c0 = blockIdx.x * 64;          // fastest -> L2 sharing of AB tile
    const int ks = blockIdx.y;               // 0..63
    const int b  = blockIdx.z;
    const int nbase = ks * (NN / KSPLIT_H);  // 1024 chunk
    const int tid  = threadIdx.x;
    const int wid  = tid >> 5;
    const int lane = tid & 31;
    const int wm = wid >> 2;
    const int wn = wid & 3;

    const float* xb = x + ((size_t)(b * CC + c0)) * NN;
    const float* ab = g_ab + (size_t)b * SS * NN;
    const uint32_t as_hi0 = smem_u32(As_hi), as_lo0 = smem_u32(As_lo);
    const uint32_t bs_hi0 = smem_u32(Bs_hi), bs_lo0 = smem_u32(Bs_lo);

    const int lr = tid >> 3;            // 0..31
    const int lk = (tid & 7) << 2;      // 0..28

    float acc[2][2][4];
#pragma unroll
    for (int i = 0; i < 2; i++)
#pragma unroll
        for (int j = 0; j < 2; j++)
#pragma unroll
            for (int q = 0; q < 4; q++) acc[i][j][q] = 0.f;

    float4 rx[2], rab[2];
    rx[0]  = *(const float4*)(xb + (size_t)lr * NN + nbase + lk);
    rx[1]  = *(const float4*)(xb + (size_t)(lr + 32) * NN + nbase + lk);
    rab[0] = *(const float4*)(ab + (size_t)lr * NN + nbase + lk);
    rab[1] = *(const float4*)(ab + (size_t)(lr + 32) * NN + nbase + lk);

    const int ITERS = (NN / KSPLIT_H) / 32;   // 32
    for (int it = 0; it < ITERS; it++) {
        const int buf = it & 1;
        uint16_t* Ah = As_hi + buf * (64 * A_STRIDE);
        uint16_t* Al = As_lo + buf * (64 * A_STRIDE);
        uint16_t* Bh = Bs_hi + buf * (64 * HB_STRIDE);
        uint16_t* Bl = Bs_lo + buf * (64 * HB_STRIDE);

#pragma unroll
        for (int r = 0; r < 2; r++) {
            float4 v = rx[r];
            uint32_t h01, l01, h23, l23;
            split2(v.x, v.y, h01, l01);
            split2(v.z, v.w, h23, l23);
            int off = (lr + r * 32) * A_STRIDE + lk;
            *(uint2*)(Ah + off) = make_uint2(h01, h23);
            *(uint2*)(Al + off) = make_uint2(l01, l23);
        }
#pragma unroll
        for (int r = 0; r < 2; r++) {
            float4 v = rab[r];
            uint32_t h01, l01, h23, l23;
            split2(v.x, v.y, h01, l01);
            split2(v.z, v.w, h23, l23);
            int off = (lr + r * 32) * HB_STRIDE + lk;
            *(uint2*)(Bh + off) = make_uint2(h01, h23);
            *(uint2*)(Bl + off) = make_uint2(l01, l23);
        }
        __syncthreads();     // single barrier per iteration (double buffer)

        if (it + 1 < ITERS) {
            const int nb2 = nbase + (it + 1) * 32;
            rx[0]  = *(const float4*)(xb + (size_t)lr * NN + nb2 + lk);
            rx[1]  = *(const float4*)(xb + (size_t)(lr + 32) * NN + nb2 + lk);
            rab[0] = *(const float4*)(ab + (size_t)lr * NN + nb2 + lk);
            rab[1] = *(const float4*)(ab + (size_t)(lr + 32) * NN + nb2 + lk);
        }

        const uint32_t ah = as_hi0 + buf * HG_ABUF, al = as_lo0 + buf * HG_ABUF;
        const uint32_t bh = bs_hi0 + buf * HG_BBUF, bl = bs_lo0 + buf * HG_BBUF;
#pragma unroll
        for (int kq = 0; kq < 2; kq++) {
            uint32_t a_hi[2][4], a_lo[2][4];
            const int arow = lane & 15;
            const int acol = (lane >> 4) << 3;
#pragma unroll
            for (int mi = 0; mi < 2; mi++) {
                uint32_t off = (uint32_t)((wm * 32 + mi * 16 + arow) * A_STRIDE
                                          + kq * 16 + acol) * 2;
                ldsm_x4(a_hi[mi], ah + off);
                ldsm_x4(a_lo[mi], al + off);
            }
            uint32_t b_hi[2][2], b_lo[2][2];
            const int l = lane & 15;
            const int srow = l & 7;
            const int koff = (l >> 3) << 3;
#pragma unroll
            for (int ni = 0; ni < 2; ni++) {
                uint32_t off = (uint32_t)((wn * 16 + ni * 8 + srow) * HB_STRIDE
                                          + kq * 16 + koff) * 2;
                ldsm_x2(b_hi[ni], bh + off);
                ldsm_x2(b_lo[ni], bl + off);
            }
#pragma unroll
            for (int mi = 0; mi < 2; mi++)
#pragma unroll
                for (int ni = 0; ni < 2; ni++) {
                    mma_bf16(acc[mi][ni], a_hi[mi], b_hi[ni]);
                    mma_bf16(acc[mi][ni], a_hi[mi], b_lo[ni]);
                    mma_bf16(acc[mi][ni], a_lo[mi], b_hi[ni]);
                }
        }
    }

    float* dst = g_hpart + (size_t)ks * (BB * CC * SS);
    const int qrow = lane >> 2;
    const int qcol = (lane & 3) << 1;
#pragma unroll
    for (int mi = 0; mi < 2; mi++) {
        int cA = c0 + wm * 32 + mi * 16 + qrow;
#pragma unroll
        for (int ni = 0; ni < 2; ni++) {
            int sA = wn * 16 + ni * 8 + qcol;
            float* pA = dst + ((size_t)(b * CC + cA)) * SS + sA;
            float* pB = dst + ((size_t)(b * CC + cA + 8)) * SS + sA;
            *(float2*)pA = make_float2(acc[mi][ni][0], acc[mi][ni][1]);
            *(float2*)pB = make_float2(acc[mi][ni][2], acc[mi][ni][3]);
        }
    }
}

// reduction of split-K partials + deferred softmax normalization
__global__ void __launch_bounds__(256) hreduce_kernel()
{
    int i = blockIdx.x * 256 + threadIdx.x;   // ((b*CC+c)*SS+s) < 65536
    int b = i >> 14;
    int s = i & 63;
    const float* ps = &g_psum[(b * SS + s) * 2];
    float inv = 1.f / (ps[0] + ps[1]);
    float sum = 0.f;
#pragma unroll
    for (int ks = 0; ks < KSPLIT_H; ks++)
        sum += g_hpart[(size_t)ks * (BB * CC * SS) + i];
    g_h[i] = sum * inv;
}

// ============================================================================
// Kernel 5: hz = W_hz @ h + b_hz ; h3 = h2*silu(z) + h2*Dp
// ============================================================================
__global__ void __launch_bounds__(256) e1_kernel(
    const float* __restrict__ Whz, const float* __restrict__ bhz,
    const float* __restrict__ Dp)
{
    const int b = blockIdx.y;
    const int o = blockIdx.x * 4 + (threadIdx.x >> 6);
    const int s_ = threadIdx.x & 63;
    const float* hb = g_h + (size_t)b * CC * SS;
    const float* w1 = Whz + (size_t)o * 256;
    const float* w2 = Whz + (size_t)(o + 256) * 256;
    float a1 = bhz[o], a2 = bhz[o + 256];
    for (int c = 0; c < 256; c++) {
        float hv = hb[c * 64 + s_];
        a1 += w1[c] * hv;
        a2 += w2[c] * hv;
    }
    float sig = 1.f / (1.f + __expf(-a2));
    g_h3[((size_t)b * CC + o) * SS + s_] = a1 * (a2 * sig) + a1 * Dp[0];
}

// Kernel 6: h4 = W_out @ h3 + b_out ; write to scratch + output tail
__global__ void __launch_bounds__(256) e2_kernel(
    const float* __restrict__ Wout, const float* __restrict__ bout,
    float* __restrict__ out)
{
    const int b = blockIdx.y;
    const int o = blockIdx.x * 4 + (threadIdx.x >> 6);
    const int s_ = threadIdx.x & 63;
    const float* hb = g_h3 + (size_t)b * CC * SS;
    const float* w1 = Wout + (size_t)o * 256;
    float acc = bout[o];
    for (int c = 0; c < 256; c++)
        acc += w1[c] * hb[c * 64 + s_];
    size_t idx = ((size_t)b * CC + o) * SS + s_;
    g_h4[idx] = acc;
    out[YSIZE + idx] = acc;
}

// ============================================================================
// Kernel 7 (HMMA): y[b,c,n] = sum_s h4[b,c,s] * C_[b,s,n]
// BM=64, BN=128, K=64 (2 x BK=32). Double buffer + reg prefetch (1 sync/iter).
// ============================================================================
__global__ void __launch_bounds__(256) ygemm_mma_kernel(float* __restrict__ y)
{
    __shared__ __align__(16) uint16_t As_hi[2 * 64 * A_STRIDE];
    __shared__ __align__(16) uint16_t As_lo[2 * 64 * A_STRIDE];
    __shared__ __align__(16) uint16_t Bs_hi[2 * 32 * B_STRIDE];
    __shared__ __align__(16) uint16_t Bs_lo[2 * 32 * B_STRIDE];

    const int m0 = blockIdx.x * 64;     // fastest -> L2 sharing of C_ tile
    const int n0 = blockIdx.y * 128;
    const int b  = blockIdx.z;
    const int tid  = threadIdx.x;
    const int wid  = tid >> 5;
    const int lane = tid & 31;
    const int wm = wid >> 2;
    const int wn = wid & 3;

    const float* h4b = g_h4 + (size_t)b * CC * SS;
    const float* cp  = g_c + (size_t)b * SS * NN;
    const uint32_t as_hi0 = smem_u32(As_hi), as_lo0 = smem_u32(As_lo);
    const uint32_t bs_hi0 = smem_u32(Bs_hi), bs_lo0 = smem_u32(Bs_lo);

    const int am = tid >> 3, ak = (tid & 7) << 2;
    const int krow0 = tid >> 5;
    const int nloc  = (tid & 31) << 2;

    float acc[2][4][4];
#pragma unroll
    for (int i = 0; i < 2; i++)
#pragma unroll
        for (int j = 0; j < 4; j++)
#pragma unroll
            for (int q = 0; q < 4; q++) acc[i][j][q] = 0.f;

    // prefetch tile 0
    float4 ra[2], rb[4];
#pragma unroll
    for (int r = 0; r < 2; r++)
        ra[r] = *(const float4*)(h4b + (size_t)(m0 + am + r * 32) * SS + ak);
#pragma unroll
    for (int r = 0; r < 4; r++)
        rb[r] = *(const float4*)(cp + (size_t)(krow0 + r * 8) * NN + n0 + nloc);

    for (int it = 0; it < 2; it++) {
        const int buf = it;
        uint16_t* Ah = As_hi + buf * (64 * A_STRIDE);
        uint16_t* Al = As_lo + buf * (64 * A_STRIDE);
        uint16_t* Bh = Bs_hi + buf * (32 * B_STRIDE);
        uint16_t* Bl = Bs_lo + buf * (32 * B_STRIDE);

#pragma unroll
        for (int r = 0; r < 2; r++) {
            float4 v = ra[r];
            uint32_t h01, l01, h23, l23;
            split2(v.x, v.y, h01, l01);
            split2(v.z, v.w, h23, l23);
            int off = (am + r * 32) * A_STRIDE + ak;
            *(uint2*)(Ah + off) = make_uint2(h01, h23);
            *(uint2*)(Al + off) = make_uint2(l01, l23);
        }
#pragma unroll
        for (int r = 0; r < 4; r++) {
            float4 v = rb[r];
            uint32_t h01, l01, h23, l23;
            split2(v.x, v.y, h01, l01);
            split2(v.z, v.w, h23, l23);
            int off = (krow0 + r * 8) * B_STRIDE + nloc;
            *(uint2*)(Bh + off) = make_uint2(h01, h23);
            *(uint2*)(Bl + off) = make_uint2(l01, l23);
        }
        __syncthreads();

        if (it == 0) {
#pragma unroll
            for (int r = 0; r < 2; r++)
                ra[r] = *(const float4*)(h4b + (size_t)(m0 + am + r * 32) * SS + 32 + ak);
#pragma unroll
            for (int r = 0; r < 4; r++)
                rb[r] = *(const float4*)(cp + (size_t)(32 + krow0 + r * 8) * NN + n0 + nloc);
        }

        const uint32_t ah = as_hi0 + buf * YG_ABUF, al = as_lo0 + buf * YG_ABUF;
        const uint32_t bh = bs_hi0 + buf * YG_BBUF, bl = bs_lo0 + buf * YG_BBUF;
#pragma unroll
        for (int ks = 0; ks < 2; ks++) {
            uint32_t a_hi[2][4], a_lo[2][4];
            const int arow = lane & 15;
            const int acol = (lane >> 4) << 3;
#pragma unroll
            for (int mi = 0; mi < 2; mi++) {
                uint32_t off = (uint32_t)((wm * 32 + mi * 16 + arow) * A_STRIDE
                                          + ks * 16 + acol) * 2;
                ldsm_x4(a_hi[mi], ah + off);
                ldsm_x4(a_lo[mi], al + off);
            }
            uint32_t b_hi[4][2], b_lo[4][2];
            const int brow = lane & 15;
#pragma unroll
            for (int ni = 0; ni < 4; ni++) {
                uint32_t off = (uint32_t)((ks * 16 + brow) * B_STRIDE
                                          + wn * 32 + ni * 8) * 2;
                ldsm_x2_t(b_hi[ni], bh + off);
                ldsm_x2_t(b_lo[ni], bl + off);
            }
#pragma unroll
            for (int mi = 0; mi < 2; mi++)
#pragma unroll
                for (int ni = 0; ni < 4; ni++) {
                    mma_bf16(acc[mi][ni], a_hi[mi], b_hi[ni]);
                    mma_bf16(acc[mi][ni], a_hi[mi], b_lo[ni]);
                    mma_bf16(acc[mi][ni], a_lo[mi], b_hi[ni]);
                }
        }
    }

    const int qrow = lane >> 2;
    const int qcol = (lane & 3) << 1;
#pragma unroll
    for (int mi = 0; mi < 2; mi++) {
        int mA = m0 + wm * 32 + mi * 16 + qrow;
        float* rowA = y + ((size_t)(b * CC + mA)) * NN + n0;
        float* rowB = rowA + (size_t)8 * NN;
#pragma unroll
        for (int ni = 0; ni < 4; ni++) {
            int n = wn * 32 + ni * 8 + qcol;
            *(float2*)(rowA + n) = make_float2(acc[mi][ni][0], acc[mi][ni][1]);
            *(float2*)(rowB + n) = make_float2(acc[mi][ni][2], acc[mi][ni][3]);
        }
    }
}

// ============================================================================
extern "C" void kernel_launch(void* const* d_in, const int* in_sizes, int n_in,
                              void* d_out, int out_size)
{
    const float* x      = (const float*)d_in[0];
    const float* W_bcdt = (const float*)d_in[1];
    const float* b_bcdt = (const float*)d_in[2];
    const float* W_dw   = (const float*)d_in[3];
    const float* b_dw   = (const float*)d_in[4];
    const float* W_hz   = (const float*)d_in[5];
    const float* b_hz   = (const float*)d_in[6];
    const float* W_out  = (const float*)d_in[7];
    const float* b_out  = (const float*)d_in[8];
    // d_in[9] = A : unused (softmax shift invariance along the reduced axis)
    const float* Dp     = (const float*)d_in[10];
    float* out = (float*)d_out;

    // side stream + fork/join events (created once; no device allocs)
    static cudaStream_t s1 = nullptr;
    static cudaEvent_t ev_g1 = nullptr, ev_c = nullptr;
    if (!s1) {
        cudaStreamCreateWithFlags(&s1, cudaStreamNonBlocking);
        cudaEventCreateWithFlags(&ev_g1, cudaEventDisableTiming);
        cudaEventCreateWithFlags(&ev_c, cudaEventDisableTiming);
        cudaFuncSetAttribute(conv_ab_kernel,
                             cudaFuncAttributeMaxDynamicSharedMemorySize, CVAB_SMEM);
    }

    gemm1_mma_kernel<<<dim3(3, NN / 128, BB), 256>>>(x, W_bcdt, b_bcdt);
    cudaEventRecord(ev_g1, 0);

    // side stream: conv_c overlaps with conv_ab/hgemm/hreduce/e1/e2
    cudaStreamWaitEvent(s1, ev_g1, 0);
    conv_c_kernel<<<dim3(2, SS, BB), 256, 0, s1>>>(W_dw, b_dw);
    cudaEventRecord(ev_c, s1);

    conv_ab_kernel<<<dim3(2, SS, BB), 256, CVAB_SMEM>>>(W_dw, b_dw);
    hgemm_mma_kernel<<<dim3(4, KSPLIT_H, BB), 256>>>(x);
    hreduce_kernel<<<256, 256>>>();
    e1_kernel<<<dim3(64, BB), 256>>>(W_hz, b_hz, Dp);
    e2_kernel<<<dim3(64, BB), 256>>>(W_out, b_out, out);

    cudaStreamWaitEvent(0, ev_c, 0);
    ygemm_mma_kernel<<<dim3(4, NN / 128, BB), 256>>>(out);
}